// round 8
// baseline (speedup 1.0000x reference)
#include <cuda_runtime.h>
#include <cuda_fp16.h>
#include <math.h>
#include <stdint.h>

#define B_DIM   4
#define L_DIM   2048
#define D_MODEL 1024
#define N_HEADS 16
#define D_HEAD  64
#define ML      (B_DIM * L_DIM)
#define N_PAIR  (B_DIM * N_HEADS)
#define N_CHUNK (L_DIM / 64)
#define DD      (D_MODEL * D_MODEL)
#define FS      65                       /* full-array smem stride */
#define HS2     34                       /* half-array smem stride (8B-aligned pairs) */

/* ---------------- scratch (device globals; no runtime alloc) ---------------- */
__device__ float  g_kpre[ML * D_MODEL];
__device__ float  g_qpre[ML * D_MODEL];
__device__ float  g_vpre[ML * D_MODEL];
__device__ float  g_kn  [ML * D_MODEL];
__device__ float  g_qn  [ML * D_MODEL];
__device__ float  g_vs  [ML * D_MODEL];
__device__ float  g_bb  [ML * D_MODEL];
__device__ float  g_o   [ML * D_MODEL];
__device__ __half g_xh  [ML * D_MODEL];
__device__ __half g_xl  [ML * D_MODEL];
__device__ __half g_oh  [ML * D_MODEL];
__device__ __half g_ol  [ML * D_MODEL];
__device__ __half g_wsh [4 * DD];
__device__ __half g_wsl [4 * DD];

/* ---------------- packed f32x2 helpers (B300 FFMA2 via PTX) ----------------- */
typedef unsigned long long u64;
__device__ __forceinline__ u64 pk2(float lo, float hi) {
    u64 r; asm("mov.b64 %0, {%1,%2};" : "=l"(r) : "f"(lo), "f"(hi)); return r;
}
__device__ __forceinline__ void upk2(u64 v, float& lo, float& hi) {
    asm("mov.b64 {%0,%1}, %2;" : "=f"(lo), "=f"(hi) : "l"(v));
}
__device__ __forceinline__ u64 fma2(u64 a, u64 b, u64 c) {
    u64 r; asm("fma.rn.f32x2 %0, %1, %2, %3;" : "=l"(r) : "l"(a), "l"(b), "l"(c));
    return r;
}
__device__ __forceinline__ u64 mul2(u64 a, u64 b) {
    u64 r; asm("mul.rn.f32x2 %0, %1, %2;" : "=l"(r) : "l"(a), "l"(b)); return r;
}
__device__ __forceinline__ u64 add2(u64 a, u64 b) {
    u64 r; asm("add.rn.f32x2 %0, %1, %2;" : "=l"(r) : "l"(a), "l"(b)); return r;
}

/* ---------------- fp32 -> (hi,lo) fp16 split, vectorized -------------------- */
__global__ __launch_bounds__(256) void split_f2h(
    const float4* __restrict__ src, uint2* __restrict__ hi,
    uint2* __restrict__ lo, int n4)
{
    int i = blockIdx.x * blockDim.x + threadIdx.x;
    if (i >= n4) return;
    float4 v = src[i];
    __half2 h01 = __floats2half2_rn(v.x, v.y);
    __half2 h23 = __floats2half2_rn(v.z, v.w);
    __half2 l01 = __floats2half2_rn(v.x - __low2float(h01), v.y - __high2float(h01));
    __half2 l23 = __floats2half2_rn(v.z - __low2float(h23), v.w - __high2float(h23));
    hi[i] = make_uint2(*(uint32_t*)&h01, *(uint32_t*)&h23);
    lo[i] = make_uint2(*(uint32_t*)&l01, *(uint32_t*)&l23);
}

/* =================== tensor-core GEMM machinery (3x FP16) =================== */
#define HS      40
#define STG_B   30720
#define AH_OFF  0
#define AL_OFF  10240
#define BH_OFF  20480
#define BL_OFF  25600
#define GSM_BYTES (2 * STG_B)

__device__ __forceinline__ uint32_t smem_u32(const void* p) {
    uint32_t a;
    asm("{ .reg .u64 t; cvta.to.shared.u64 t, %1; cvt.u32.u64 %0, t; }"
        : "=r"(a) : "l"(p));
    return a;
}

#define LDSM_X4(r, a)                                                         \
    asm volatile("ldmatrix.sync.aligned.m8n8.x4.shared.b16 "                  \
                 "{%0,%1,%2,%3}, [%4];"                                       \
                 : "=r"((r)[0]), "=r"((r)[1]), "=r"((r)[2]), "=r"((r)[3])     \
                 : "r"(a))

#define MMA_F16B(d, a, b0, b1)                                                \
    asm volatile(                                                             \
        "mma.sync.aligned.m16n8k16.row.col.f32.f16.f16.f32 "                  \
        "{%0,%1,%2,%3}, {%4,%5,%6,%7}, {%8,%9}, {%0,%1,%2,%3};"               \
        : "+f"(d[0]), "+f"(d[1]), "+f"(d[2]), "+f"(d[3])                      \
        : "r"(a[0]), "r"(a[1]), "r"(a[2]), "r"(a[3]), "r"(b0), "r"(b1))

#define CP_ASYNC16(sa, gp)                                                    \
    asm volatile("cp.async.cg.shared.global [%0], [%1], 16;"                  \
                 :: "r"(sa), "l"(gp))

#define GEMM_BODY(bnG, Yptr, biasptr, Ncols)                                  \
    extern __shared__ char smg[];                                             \
    const uint32_t sbase = smem_u32(smg);                                     \
    const int tid = threadIdx.x;                                              \
    const int bm = blockIdx.y * 128;                                          \
    const int lane = tid & 31, w = tid >> 5;                                  \
    const int wm = (w >> 1) * 32, wn = (w & 1) * 32;                          \
    const int g = lane >> 2, tg = lane & 3;                                   \
    const int arow = (lane & 7) + ((lane >> 3) & 1) * 8;                      \
    const int acol = (lane >> 4) * 8;                                         \
    const int brow = ((lane >> 4) & 1) * 8 + (lane & 7);                      \
    const int bcol = ((lane >> 3) & 1) * 8;                                   \
    const int r4 = tid >> 2, c4 = tid & 3;                                    \
    const uint32_t so = r4 * 80 + c4 * 16;                                    \
    float acc[2][4][4];                                                       \
    _Pragma("unroll")                                                         \
    for (int mt = 0; mt < 2; mt++)                                            \
        _Pragma("unroll")                                                     \
        for (int nt = 0; nt < 4; nt++)                                        \
            _Pragma("unroll")                                                 \
            for (int e = 0; e < 4; e++) acc[mt][nt][e] = 0.f;                 \
    const int n_tiles = K >> 5;                                               \
    LOAD_TILE(0);                                                             \
    for (int t = 0; t < n_tiles; t++) {                                       \
        if (t + 1 < n_tiles) {                                                \
            LOAD_TILE(t + 1);                                                 \
            asm volatile("cp.async.wait_group 1;");                           \
        } else {                                                              \
            asm volatile("cp.async.wait_group 0;");                           \
        }                                                                     \
        __syncthreads();                                                      \
        const uint32_t sb = sbase + (t & 1) * STG_B;                          \
        _Pragma("unroll")                                                     \
        for (int kk = 0; kk < 2; kk++) {                                      \
            const int kc = kk * 16;                                           \
            uint32_t ah[2][4], al[2][4], bh[2][4], bl[2][4];                  \
            _Pragma("unroll")                                                 \
            for (int mt = 0; mt < 2; mt++) {                                  \
                uint32_t ad = sb + AH_OFF +                                   \
                              ((wm + mt * 16 + arow) * HS + kc + acol) * 2;   \
                LDSM_X4(ah[mt], ad);                                          \
                LDSM_X4(al[mt], ad + (AL_OFF - AH_OFF));                      \
            }                                                                 \
            _Pragma("unroll")                                                 \
            for (int a2 = 0; a2 < 2; a2++) {                                  \
                uint32_t bd = sb + BH_OFF +                                   \
                              ((wn + a2 * 16 + brow) * HS + kc + bcol) * 2;   \
                LDSM_X4(bh[a2], bd);                                          \
                LDSM_X4(bl[a2], bd + (BL_OFF - BH_OFF));                      \
            }                                                                 \
            _Pragma("unroll")                                                 \
            for (int mt = 0; mt < 2; mt++)                                    \
                _Pragma("unroll")                                             \
                for (int nt = 0; nt < 4; nt++) {                              \
                    const int hi2 = nt >> 1, p = (nt & 1) * 2;                \
                    MMA_F16B(acc[mt][nt], ah[mt], bh[hi2][p], bh[hi2][p+1]);  \
                    MMA_F16B(acc[mt][nt], ah[mt], bl[hi2][p], bl[hi2][p+1]);  \
                    MMA_F16B(acc[mt][nt], al[mt], bh[hi2][p], bh[hi2][p+1]);  \
                }                                                             \
        }                                                                     \
        __syncthreads();                                                      \
    }                                                                         \
    _Pragma("unroll")                                                         \
    for (int mt = 0; mt < 2; mt++) {                                          \
        const int row = bm + wm + mt * 16 + g;                                \
        _Pragma("unroll")                                                     \
        for (int nt = 0; nt < 4; nt++) {                                      \
            const int col = bnL + wn + nt * 8 + tg * 2;                       \
            const float b0 = (biasptr)[col], b1 = (biasptr)[col + 1];         \
            float2 v0 = make_float2(acc[mt][nt][0] + b0, acc[mt][nt][1] + b1);\
            float2 v1 = make_float2(acc[mt][nt][2] + b0, acc[mt][nt][3] + b1);\
            *(float2*)((Yptr) + (size_t)row * (Ncols) + col) = v0;            \
            *(float2*)((Yptr) + (size_t)(row + 8) * (Ncols) + col) = v1;      \
        }                                                                     \
    }

#define LOAD_TILE(t) do {                                                     \
        const uint32_t _sb = sbase + ((t) & 1) * STG_B;                       \
        const int _kb = (t) << 5;                                             \
        const size_t _ga0 = (size_t)(bm + r4) * K + _kb + c4 * 8;             \
        const size_t _ga1 = (size_t)(bm + 64 + r4) * K + _kb + c4 * 8;        \
        const size_t _gb0 = (size_t)(bnG + r4) * K + _kb + c4 * 8;            \
        CP_ASYNC16(_sb + AH_OFF + so,           Ahg + _ga0);                  \
        CP_ASYNC16(_sb + AH_OFF + so + 5120,    Ahg + _ga1);                  \
        CP_ASYNC16(_sb + AL_OFF + so,           Alg + _ga0);                  \
        CP_ASYNC16(_sb + AL_OFF + so + 5120,    Alg + _ga1);                  \
        CP_ASYNC16(_sb + BH_OFF + so,           Bhg + _gb0);                  \
        CP_ASYNC16(_sb + BL_OFF + so,           Blg + _gb0);                  \
        asm volatile("cp.async.commit_group;");                               \
    } while (0)

__global__ __launch_bounds__(256, 3) void gemm_qkv3(
    const __half* __restrict__ Ahg, const __half* __restrict__ Alg,
    const __half* __restrict__ Bhg, const __half* __restrict__ Blg,
    const float* __restrict__ bk, const float* __restrict__ bq,
    const float* __restrict__ bv,
    float* __restrict__ Yk, float* __restrict__ Yq, float* __restrict__ Yv,
    int M, int K)
{
    const int bnG = blockIdx.x * 64;
    const int seg = bnG >> 10;
    const int bnL = bnG & 1023;
    const float* bias = (seg == 0) ? bk : (seg == 1) ? bq : bv;
    float* Y = (seg == 0) ? Yk : (seg == 1) ? Yq : Yv;
    GEMM_BODY(bnG, Y, bias, D_MODEL)
}

__global__ __launch_bounds__(256, 3) void gemm_h3b(
    const __half* __restrict__ Ahg, const __half* __restrict__ Alg,
    const __half* __restrict__ Bhg, const __half* __restrict__ Blg,
    const float* __restrict__ bias, float* __restrict__ Y,
    int M, int N, int K)
{
    const int bnG = blockIdx.x * 64;
    const int bnL = bnG;
    GEMM_BODY(bnG, Y, bias, N)
}
#undef LOAD_TILE

/* -------- fused prep: short-conv(K=4) + beta + silu + L2 norm (float4) ------ */
__global__ __launch_bounds__(256) void prep_kernel(
    const float* __restrict__ x,
    const float* __restrict__ Wbeta, const float* __restrict__ bbeta,
    const float* __restrict__ ck, const float* __restrict__ cq,
    const float* __restrict__ cv)
{
    __shared__ float xrow[D_MODEL];
    __shared__ float eta_s[N_HEADS];

    const int bl = blockIdx.x;
    const int b = bl >> 11;
    const int l = bl & 2047;
    const int tid = threadIdx.x;
    const int d = tid * 4;                /* 4 channels per thread */
    const int h = tid >> 4;               /* head of these channels */

    /* x row to smem (for beta dot) */
    float4 xv = *(const float4*)(x + (size_t)bl * D_MODEL + d);
    *(float4*)&xrow[d] = xv;

    /* conv weights for 4 channels: rows d..d+3 of (Dm,4) => 4 float4 each */
    float4 cwk[4], cwq[4], cwv[4];
#pragma unroll
    for (int c = 0; c < 4; c++) {
        cwk[c] = ((const float4*)ck)[d + c];
        cwq[c] = ((const float4*)cq)[d + c];
        cwv[c] = ((const float4*)cv)[d + c];
    }

    float ak[4] = {0.f, 0.f, 0.f, 0.f};
    float aq[4] = {0.f, 0.f, 0.f, 0.f};
    float av[4] = {0.f, 0.f, 0.f, 0.f};
#pragma unroll
    for (int j = 0; j < 4; j++) {
        int ls = l + j - 3;
        if (ls >= 0) {
            size_t base = ((size_t)b * L_DIM + ls) * D_MODEL + d;
            float4 kp = *(const float4*)&g_kpre[base];
            float4 qp = *(const float4*)&g_qpre[base];
            float4 vp = *(const float4*)&g_vpre[base];
            const float* k4 = (const float*)&kp;
            const float* q4 = (const float*)&qp;
            const float* v4 = (const float*)&vp;
#pragma unroll
            for (int c = 0; c < 4; c++) {
                ak[c] += k4[c] * ((const float*)&cwk[c])[j];
                aq[c] += q4[c] * ((const float*)&cwq[c])[j];
                av[c] += v4[c] * ((const float*)&cwv[c])[j];
            }
        }
    }

    /* per-head L2 norms via 16-lane shfl groups */
    float sk = ak[0] * ak[0] + ak[1] * ak[1] + ak[2] * ak[2] + ak[3] * ak[3];
    float sq = aq[0] * aq[0] + aq[1] * aq[1] + aq[2] * aq[2] + aq[3] * aq[3];
#pragma unroll
    for (int o = 8; o > 0; o >>= 1) {
        sk += __shfl_xor_sync(0xffffffffu, sk, o);
        sq += __shfl_xor_sync(0xffffffffu, sq, o);
    }
    float knorm = sqrtf(sk) + 1e-6f;
    float qnorm = sqrtf(sq) + 1e-6f;

    __syncthreads();   /* xrow ready */

    /* beta = sigmoid(x @ Wbeta^T + b): warp w -> heads 2w, 2w+1 */
    {
        const int warp = tid >> 5, lane = tid & 31;
#pragma unroll
        for (int hh = 0; hh < 2; hh++) {
            int hb = warp * 2 + hh;
            float s = 0.f;
            const float* wb = Wbeta + hb * D_MODEL;
            for (int k = lane * 4; k < D_MODEL; k += 128) {
                float4 xr = *(const float4*)&xrow[k];
                float4 wr = *(const float4*)&wb[k];
                s += xr.x * wr.x + xr.y * wr.y + xr.z * wr.z + xr.w * wr.w;
            }
#pragma unroll
            for (int o = 16; o > 0; o >>= 1) s += __shfl_down_sync(0xffffffffu, s, o);
            if (lane == 0) eta_s[hb] = 1.f / (1.f + __expf(-(s + bbeta[hb])));
        }
    }
    __syncthreads();
    const float e = eta_s[h];

    float4 knv, qnv, vsv, bbv;
    float* kn4 = (float*)&knv; float* qn4 = (float*)&qnv;
    float* vs4 = (float*)&vsv; float* bb4 = (float*)&bbv;
#pragma unroll
    for (int c = 0; c < 4; c++) {
        float kn = ak[c] / knorm;
        float qn = aq[c] / qnorm;
        float vv = av[c];
        float sv = vv / (1.f + __expf(-vv));
        kn4[c] = kn; qn4[c] = qn; vs4[c] = e * sv; bb4[c] = e * kn;
    }
    size_t base = (((size_t)(b * N_HEADS + h)) * L_DIM + l) * D_HEAD + (d & 63);
    *(float4*)&g_kn[base] = knv;
    *(float4*)&g_qn[base] = qnv;
    *(float4*)&g_vs[base] = vsv;
    *(float4*)&g_bb[base] = bbv;
}

/* ---------------- chunked o2b weighted delta-rule scan (column-split) -------
   2 CTAs per (b,h); packed f32x2 math throughout. --------------------------- */
#define SMEM_FLOATS (4 * 64 * FS + 3 * 64 * HS2 + 512 + 256)

__global__ __launch_bounds__(256) void delta_kernel()
{
    extern __shared__ float smd[];
    float* Ks   = smd;                 /* 64 x 65 */
    float* Qs   = Ks + 64 * FS;
    float* Bss  = Qs + 64 * FS;
    float* Ts   = Bss + 64 * FS;
    float* Wt   = Ts + 64 * FS;        /* 64 x 34 (8B-aligned pairs) */
    float* Wa   = Wt + 64 * HS2;
    float* Us   = Wa + 64 * HS2;
    float* invD = Us + 64 * HS2;       /* 512 */
    float* Mb   = invD + 512;          /* 8 x 32 */

    const int tid = threadIdx.x;
    const int tx = tid & 15;
    const int ty = tid >> 4;
    const int pair = blockIdx.x >> 1;
    const int half = blockIdx.x & 1;
    const int col0 = half * 32;
    const int b = pair >> 4, h = pair & 15;

    for (int i = tid; i < 64 * HS2; i += 256) { Wt[i] = 0.f; Wa[i] = 0.f; }

    const size_t pbase = (size_t)pair * L_DIM * D_HEAD;
    const u64 ONE2 = pk2(1.f, 1.f);
    const u64 NEG1 = pk2(-1.f, -1.f);

    for (int chunk = 0; chunk < N_CHUNK; chunk++) {
        __syncthreads();
        const size_t cb = pbase + (size_t)chunk * 64 * D_HEAD;
        for (int i2 = tid; i2 < 4096; i2 += 256) {
            int s = (i2 >> 6) * FS + (i2 & 63);
            Ks[s]  = g_kn[cb + i2];
            Qs[s]  = g_qn[cb + i2];
            Bss[s] = g_bb[cb + i2];
        }
        for (int i2 = tid; i2 < 2048; i2 += 256) {
            int r = i2 >> 5, c = i2 & 31;
            Us[r * HS2 + c] = g_vs[cb + r * 64 + col0 + c];
        }
        __syncthreads();

        const float ts    = (float)(chunk * 64);
        const float tri0  = 0.5f * (1.f + ts) * ts;
        const float denw  = 0.5f * (65.f + ts) * (64.f + ts);
        const float Ssum  = 64.f * ts + 2080.f;
        const float coef1 = (ts / (ts + 64.f)) * ((1.f + ts) / (ts + 65.f));
        const float coef2 = (64.f / (ts + 64.f)) * ((2.f * ts + 65.f) / (ts + 65.f));

        /* A: T = strict_tril(B @ K^T)  (full 64x64, f32x2 packed along j) */
        {
            u64 acc2[4][2] = {};
            for (int k = 0; k < 64; k++) {
                float a0[4];
#pragma unroll
                for (int i = 0; i < 4; i++) a0[i] = Bss[(4 * ty + i) * FS + k];
                u64 b01 = pk2(Ks[(4 * tx + 0) * FS + k], Ks[(4 * tx + 1) * FS + k]);
                u64 b23 = pk2(Ks[(4 * tx + 2) * FS + k], Ks[(4 * tx + 3) * FS + k]);
#pragma unroll
                for (int i = 0; i < 4; i++) {
                    u64 as = pk2(a0[i], a0[i]);
                    acc2[i][0] = fma2(as, b01, acc2[i][0]);
                    acc2[i][1] = fma2(as, b23, acc2[i][1]);
                }
            }
#pragma unroll
            for (int i = 0; i < 4; i++) {
                float v0, v1, v2, v3;
                upk2(acc2[i][0], v0, v1);
                upk2(acc2[i][1], v2, v3);
                int r = 4 * ty + i;
                Ts[r * FS + 4 * tx + 0] = (r > 4 * tx + 0) ? v0 : 0.f;
                Ts[r * FS + 4 * tx + 1] = (r > 4 * tx + 1) ? v1 : 0.f;
                Ts[r * FS + 4 * tx + 2] = (r > 4 * tx + 2) ? v2 : 0.f;
                Ts[r * FS + 4 * tx + 3] = (r > 4 * tx + 3) ? v3 : 0.f;
            }
        }
        __syncthreads();

        /* C0: invert the 8 unit-lower 8x8 diagonal blocks (threads 0-63) */
        if (tid < 64) {
            const int blk = tid >> 3, c = tid & 7;
            const int r0 = blk * 8;
            float xcol[8];
#pragma unroll
            for (int r = 0; r < 8; r++) {
                float s = (r == c) ? 1.f : 0.f;
                for (int k2 = c; k2 < r; k2++)
                    s -= Ts[(r0 + r) * FS + r0 + k2] * xcol[k2];
                xcol[r] = s;
            }
#pragma unroll
            for (int r = 0; r < 8; r++) invD[(r0 + r) * 8 + c] = xcol[r];
        }

        /* B: RHS = V - B @ W_t   (64 x 32, into Us; packed) */
        {
            u64 acc2[4] = {};
            for (int k = 0; k < 64; k++) {
                u64 w01 = *(const u64*)&Wt[k * HS2 + 2 * tx];
#pragma unroll
                for (int i = 0; i < 4; i++) {
                    float a = Bss[(4 * ty + i) * FS + k];
                    acc2[i] = fma2(pk2(a, a), w01, acc2[i]);
                }
            }
#pragma unroll
            for (int i = 0; i < 4; i++) {
                u64* up = (u64*)&Us[(4 * ty + i) * HS2 + 2 * tx];
                *up = fma2(NEG1, acc2[i], *up);
            }
        }
        __syncthreads();

        /* C: blocked forward substitution  (I+T) U = RHS  (32 cols) */
        {
            const int cc = tid & 31, rr = tid >> 5;
            for (int ib = 0; ib < 8; ib++) {
                const int r0 = ib * 8;
                float s = 0.f;
                for (int j = 0; j < r0; j++)
                    s += Ts[(r0 + rr) * FS + j] * Us[j * HS2 + cc];
                float rhs = Us[(r0 + rr) * HS2 + cc] - s;
                Mb[rr * 32 + cc] = rhs;
                __syncthreads();
                s = rhs;
                for (int k2 = 0; k2 < rr; k2++)
                    s += invD[(r0 + rr) * 8 + k2] * Mb[k2 * 32 + cc];
                Us[(r0 + rr) * HS2 + cc] = s;
                __syncthreads();
            }
        }

        float csr[4], rdiv[4], arr[4];
#pragma unroll
        for (int i = 0; i < 4; i++) {
            float rr2 = (float)(4 * ty + i);
            float cs = (rr2 + 1.f) * ts + 0.5f * (rr2 + 1.f) * (rr2 + 2.f);
            csr[i]  = cs;
            rdiv[i] = 1.f / (tri0 + cs);
            arr[i]  = tri0 * rdiv[i];
        }

        /* D: O = (Q @ W_avg)*a + (Q @ W_t)*(1-a)   (packed) */
        u64 o2[4];
        {
            u64 acc1[4] = {}, acc2[4] = {};
            for (int k = 0; k < 64; k++) {
                u64 wa01 = *(const u64*)&Wa[k * HS2 + 2 * tx];
                u64 wt01 = *(const u64*)&Wt[k * HS2 + 2 * tx];
#pragma unroll
                for (int i = 0; i < 4; i++) {
                    float q = Qs[(4 * ty + i) * FS + k];
                    u64 qs2 = pk2(q, q);
                    acc1[i] = fma2(qs2, wa01, acc1[i]);
                    acc2[i] = fma2(qs2, wt01, acc2[i]);
                }
            }
#pragma unroll
            for (int i = 0; i < 4; i++)
                o2[i] = fma2(pk2(arr[i], arr[i]), acc1[i],
                             mul2(pk2(1.f - arr[i], 1.f - arr[i]), acc2[i]));
        }

        /* E: QK = Q @ K^T (full, into Ts; packed) */
        {
            u64 acc2[4][2] = {};
            for (int k = 0; k < 64; k++) {
                float q0[4];
#pragma unroll
                for (int i = 0; i < 4; i++) q0[i] = Qs[(4 * ty + i) * FS + k];
                u64 b01 = pk2(Ks[(4 * tx + 0) * FS + k], Ks[(4 * tx + 1) * FS + k]);
                u64 b23 = pk2(Ks[(4 * tx + 2) * FS + k], Ks[(4 * tx + 3) * FS + k]);
#pragma unroll
                for (int i = 0; i < 4; i++) {
                    u64 qs2 = pk2(q0[i], q0[i]);
                    acc2[i][0] = fma2(qs2, b01, acc2[i][0]);
                    acc2[i][1] = fma2(qs2, b23, acc2[i][1]);
                }
            }
#pragma unroll
            for (int i = 0; i < 4; i++) {
                float v0, v1, v2, v3;
                upk2(acc2[i][0], v0, v1);
                upk2(acc2[i][1], v2, v3);
                int r = (4 * ty + i) * FS + 4 * tx;
                Ts[r + 0] = v0; Ts[r + 1] = v1; Ts[r + 2] = v2; Ts[r + 3] = v3;
            }
        }
        __syncthreads();

        /* F: O += (T_mat o QK) @ U  (packed) */
        {
            for (int kp = 0; kp < 64; kp++) {
                float kf = (float)kp;
                float csk_m = kf * ts + 0.5f * kf * (kf + 1.f);
                u64 u01 = *(const u64*)&Us[kp * HS2 + 2 * tx];
#pragma unroll
                for (int i = 0; i < 4; i++) {
                    float num  = csr[i] - csk_m;
                    float sfac = (num >= 0.f) ? num * rdiv[i] : 0.f;
                    float sv   = sfac * Ts[(4 * ty + i) * FS + kp];
                    o2[i] = fma2(pk2(sv, sv), u01, o2[i]);
                }
            }
        }

        /* G: write raw O (RMS deferred) */
        {
            const int cidx = h * 64 + col0 + 2 * tx;
#pragma unroll
            for (int i = 0; i < 4; i++) {
                int l = chunk * 64 + 4 * ty + i;
                float v0, v1;
                upk2(o2[i], v0, v1);
                *(float2*)&g_o[((size_t)(b * L_DIM + l)) * D_MODEL + cidx] =
                    make_float2(v0, v1);
            }
        }

        /* H: W updates (packed) */
        {
            u64 p1[4] = {}, p2[4] = {};
            for (int r = 0; r < 64; r++) {
                float rr2  = (float)r;
                float idxr = ts + rr2 + 1.f;
                float csrr = (rr2 + 1.f) * ts + 0.5f * (rr2 + 1.f) * (rr2 + 2.f);
                float wr   = (idxr + Ssum - csrr) / denw;
                u64 uv = *(const u64*)&Us[r * HS2 + 2 * tx];
                u64 uw = mul2(pk2(wr, wr), uv);
#pragma unroll
                for (int i = 0; i < 4; i++) {
                    float kv = Ks[r * FS + 4 * ty + i];
                    u64 ks2 = pk2(kv, kv);
                    p1[i] = fma2(ks2, uv, p1[i]);
                    p2[i] = fma2(ks2, uw, p2[i]);
                }
            }
            u64 c1 = pk2(coef1, coef1), c2 = pk2(coef2, coef2);
#pragma unroll
            for (int i = 0; i < 4; i++) {
                int idx2 = (4 * ty + i) * HS2 + 2 * tx;
                u64* wtp = (u64*)&Wt[idx2];
                u64* wap = (u64*)&Wa[idx2];
                u64 wold = *wtp, waold = *wap;
                *wap = fma2(c1, waold, fma2(c2, wold, p2[i]));
                *wtp = fma2(ONE2, p1[i], wold);
            }
        }
    }
}

/* -------- RMS norm over head dim + fp16 hi/lo split for final GEMM ---------- */
__global__ __launch_bounds__(256) void rms_split(const float* __restrict__ rms_w)
{
    const int bl = blockIdx.x, tid = threadIdx.x;
    float4 v = ((const float4*)g_o)[(size_t)bl * 256 + tid];
    float ss = v.x * v.x + v.y * v.y + v.z * v.z + v.w * v.w;
#pragma unroll
    for (int o = 8; o > 0; o >>= 1) ss += __shfl_xor_sync(0xffffffffu, ss, o);
    float scale = rsqrtf(ss * (1.f / 64.f) + 1e-6f);
    float4 rw = ((const float4*)rms_w)[tid & 15];
    float a0 = v.x * scale * rw.x, a1 = v.y * scale * rw.y;
    float a2 = v.z * scale * rw.z, a3 = v.w * scale * rw.w;
    __half2 h01 = __floats2half2_rn(a0, a1);
    __half2 h23 = __floats2half2_rn(a2, a3);
    __half2 l01 = __floats2half2_rn(a0 - __low2float(h01), a1 - __high2float(h01));
    __half2 l23 = __floats2half2_rn(a2 - __low2float(h23), a3 - __high2float(h23));
    ((uint2*)g_oh)[(size_t)bl * 256 + tid] = make_uint2(*(uint32_t*)&h01, *(uint32_t*)&h23);
    ((uint2*)g_ol)[(size_t)bl * 256 + tid] = make_uint2(*(uint32_t*)&l01, *(uint32_t*)&l23);
}

/* ------------------------------- launcher ----------------------------------*/
extern "C" void kernel_launch(void* const* d_in, const int* in_sizes, int n_in,
                              void* d_out, int out_size)
{
    (void)in_sizes; (void)n_in; (void)out_size;
    const float* x     = (const float*)d_in[0];
    const float* Wk    = (const float*)d_in[1];
    const float* bk    = (const float*)d_in[2];
    const float* Wq    = (const float*)d_in[3];
    const float* bq    = (const float*)d_in[4];
    const float* Wv    = (const float*)d_in[5];
    const float* bv    = (const float*)d_in[6];
    const float* Wbeta = (const float*)d_in[7];
    const float* bbeta = (const float*)d_in[8];
    const float* ck    = (const float*)d_in[9];
    const float* cq    = (const float*)d_in[10];
    const float* cv    = (const float*)d_in[11];
    const float* rms_w = (const float*)d_in[12];
    const float* Wout  = (const float*)d_in[13];
    const float* bout  = (const float*)d_in[14];
    float* out = (float*)d_out;

    float *kpre, *qpre, *vpre;
    __half *xh, *xl, *oh, *ol, *wsh, *wsl;
    cudaGetSymbolAddress((void**)&kpre, g_kpre);
    cudaGetSymbolAddress((void**)&qpre, g_qpre);
    cudaGetSymbolAddress((void**)&vpre, g_vpre);
    cudaGetSymbolAddress((void**)&xh, g_xh);
    cudaGetSymbolAddress((void**)&xl, g_xl);
    cudaGetSymbolAddress((void**)&oh, g_oh);
    cudaGetSymbolAddress((void**)&ol, g_ol);
    cudaGetSymbolAddress((void**)&wsh, g_wsh);
    cudaGetSymbolAddress((void**)&wsl, g_wsl);

    split_f2h<<<(ML * D_MODEL / 4 + 255) / 256, 256>>>(
        (const float4*)x, (uint2*)xh, (uint2*)xl, ML * D_MODEL / 4);
    split_f2h<<<(DD / 4 + 255) / 256, 256>>>(
        (const float4*)Wk, (uint2*)wsh, (uint2*)wsl, DD / 4);
    split_f2h<<<(DD / 4 + 255) / 256, 256>>>(
        (const float4*)Wq, (uint2*)(wsh + DD), (uint2*)(wsl + DD), DD / 4);
    split_f2h<<<(DD / 4 + 255) / 256, 256>>>(
        (const float4*)Wv, (uint2*)(wsh + 2 * DD), (uint2*)(wsl + 2 * DD), DD / 4);
    split_f2h<<<(DD / 4 + 255) / 256, 256>>>(
        (const float4*)Wout, (uint2*)(wsh + 3 * DD), (uint2*)(wsl + 3 * DD), DD / 4);

    cudaFuncSetAttribute(gemm_qkv3, cudaFuncAttributeMaxDynamicSharedMemorySize,
                         GSM_BYTES);
    cudaFuncSetAttribute(gemm_h3b, cudaFuncAttributeMaxDynamicSharedMemorySize,
                         GSM_BYTES);

    gemm_qkv3<<<dim3(48, 64), 256, GSM_BYTES>>>(
        xh, xl, wsh, wsl, bk, bq, bv, kpre, qpre, vpre, ML, D_MODEL);

    prep_kernel<<<ML, 256>>>(x, Wbeta, bbeta, ck, cq, cv);

    size_t smem_bytes = SMEM_FLOATS * sizeof(float);
    cudaFuncSetAttribute(delta_kernel, cudaFuncAttributeMaxDynamicSharedMemorySize,
                         (int)smem_bytes);
    delta_kernel<<<2 * N_PAIR, 256, smem_bytes>>>();

    rms_split<<<ML, 256>>>(rms_w);

    gemm_h3b<<<dim3(16, 64), 256, GSM_BYTES>>>(
        oh, ol, wsh + 3 * DD, wsl + 3 * DD, bout, out, ML, D_MODEL, D_MODEL);
}

// round 9
// speedup vs baseline: 1.1578x; 1.1578x over previous
#include <cuda_runtime.h>
#include <cuda_fp16.h>
#include <math.h>
#include <stdint.h>

#define B_DIM   4
#define L_DIM   2048
#define D_MODEL 1024
#define N_HEADS 16
#define D_HEAD  64
#define ML      (B_DIM * L_DIM)
#define N_PAIR  (B_DIM * N_HEADS)
#define N_CHUNK (L_DIM / 64)
#define DD      (D_MODEL * D_MODEL)
#define FS      65                       /* full-array smem stride */
#define HSX     33                       /* half-array smem stride */

/* ---------------- scratch (device globals; no runtime alloc) ---------------- */
__device__ float  g_kpre[ML * D_MODEL];
__device__ float  g_qpre[ML * D_MODEL];
__device__ float  g_vpre[ML * D_MODEL];
__device__ float  g_kn  [ML * D_MODEL];
__device__ float  g_qn  [ML * D_MODEL];
__device__ float  g_vs  [ML * D_MODEL];
__device__ float  g_bb  [ML * D_MODEL];
__device__ float  g_o   [ML * D_MODEL];
__device__ __half g_xh  [ML * D_MODEL];
__device__ __half g_xl  [ML * D_MODEL];
__device__ __half g_oh  [ML * D_MODEL];
__device__ __half g_ol  [ML * D_MODEL];
__device__ __half g_wsh [4 * DD];
__device__ __half g_wsl [4 * DD];

/* ---------------- fp32 -> (hi,lo) fp16 split, vectorized -------------------- */
__device__ __forceinline__ void split4(float4 v, uint2& hi, uint2& lo) {
    __half2 h01 = __floats2half2_rn(v.x, v.y);
    __half2 h23 = __floats2half2_rn(v.z, v.w);
    __half2 l01 = __floats2half2_rn(v.x - __low2float(h01), v.y - __high2float(h01));
    __half2 l23 = __floats2half2_rn(v.z - __low2float(h23), v.w - __high2float(h23));
    hi = make_uint2(*(uint32_t*)&h01, *(uint32_t*)&h23);
    lo = make_uint2(*(uint32_t*)&l01, *(uint32_t*)&l23);
}

__global__ __launch_bounds__(256) void split_f2h(
    const float4* __restrict__ src, uint2* __restrict__ hi,
    uint2* __restrict__ lo, int n4)
{
    int i = blockIdx.x * blockDim.x + threadIdx.x;
    if (i >= n4) return;
    uint2 h, l;
    split4(src[i], h, l);
    hi[i] = h; lo[i] = l;
}

/* all 4 weight matrices in one launch (segments of DD/4 float4 each) */
__global__ __launch_bounds__(256) void split_w4(
    const float4* __restrict__ w0, const float4* __restrict__ w1,
    const float4* __restrict__ w2, const float4* __restrict__ w3,
    uint2* __restrict__ hi, uint2* __restrict__ lo)
{
    int i = blockIdx.x * blockDim.x + threadIdx.x;   /* 0 .. 4*DD/4-1 */
    int seg = i >> 18;                               /* DD/4 = 2^18 */
    int off = i & ((DD / 4) - 1);
    const float4* src = (seg == 0) ? w0 : (seg == 1) ? w1 : (seg == 2) ? w2 : w3;
    uint2 h, l;
    split4(src[off], h, l);
    hi[i] = h; lo[i] = l;
}

/* =================== tensor-core GEMM machinery (FP16 splits) =============== */
#define HS      40

__device__ __forceinline__ uint32_t smem_u32(const void* p) {
    uint32_t a;
    asm("{ .reg .u64 t; cvta.to.shared.u64 t, %1; cvt.u32.u64 %0, t; }"
        : "=r"(a) : "l"(p));
    return a;
}

#define LDSM_X4(r, a)                                                         \
    asm volatile("ldmatrix.sync.aligned.m8n8.x4.shared.b16 "                  \
                 "{%0,%1,%2,%3}, [%4];"                                       \
                 : "=r"((r)[0]), "=r"((r)[1]), "=r"((r)[2]), "=r"((r)[3])     \
                 : "r"(a))

#define MMA_F16B(d, a, b0, b1)                                                \
    asm volatile(                                                             \
        "mma.sync.aligned.m16n8k16.row.col.f32.f16.f16.f32 "                  \
        "{%0,%1,%2,%3}, {%4,%5,%6,%7}, {%8,%9}, {%0,%1,%2,%3};"               \
        : "+f"(d[0]), "+f"(d[1]), "+f"(d[2]), "+f"(d[3])                      \
        : "r"(a[0]), "r"(a[1]), "r"(a[2]), "r"(a[3]), "r"(b0), "r"(b1))

#define CP_ASYNC16(sa, gp)                                                    \
    asm volatile("cp.async.cg.shared.global [%0], [%1], 16;"                  \
                 :: "r"(sa), "l"(gp))

/* ---------- 2-pass QKV GEMM: Y = Ah @ (Bh+Bl)^T + bias ---------------------
   CTA 128x64x32, 8 warps (32x32). smem/stage: Ah(128)+Bh(64)+Bl(64) rows.  */
#define QS_AH   0
#define QS_BH   10240
#define QS_BL   15360
#define QSTG    20480
#define QSM_BYTES (2 * QSTG)

__global__ __launch_bounds__(256, 3) void gemm_qkv2(
    const __half* __restrict__ Ahg,
    const __half* __restrict__ Bhg, const __half* __restrict__ Blg,
    const float* __restrict__ bk, const float* __restrict__ bq,
    const float* __restrict__ bv,
    float* __restrict__ Yk, float* __restrict__ Yq, float* __restrict__ Yv,
    int M, int K)
{
    extern __shared__ char smg[];
    const uint32_t sbase = smem_u32(smg);

    const int tid = threadIdx.x;
    const int bm = blockIdx.y * 128;
    const int bnG = blockIdx.x * 64;
    const int seg = bnG >> 10;
    const int bnL = bnG & 1023;
    const float* bias = (seg == 0) ? bk : (seg == 1) ? bq : bv;
    float* Y = (seg == 0) ? Yk : (seg == 1) ? Yq : Yv;

    const int lane = tid & 31, w = tid >> 5;
    const int wm = (w >> 1) * 32, wn = (w & 1) * 32;
    const int g = lane >> 2, tg = lane & 3;
    const int arow = (lane & 7) + ((lane >> 3) & 1) * 8;
    const int acol = (lane >> 4) * 8;
    const int brow = ((lane >> 4) & 1) * 8 + (lane & 7);
    const int bcol = ((lane >> 3) & 1) * 8;
    const int r4 = tid >> 2, c4 = tid & 3;
    const uint32_t so = r4 * 80 + c4 * 16;

    float acc[2][4][4];
#pragma unroll
    for (int mt = 0; mt < 2; mt++)
#pragma unroll
        for (int nt = 0; nt < 4; nt++)
#pragma unroll
            for (int e = 0; e < 4; e++) acc[mt][nt][e] = 0.f;

    const int n_tiles = K >> 5;

#define QLOAD(t) do {                                                         \
        const uint32_t _sb = sbase + ((t) & 1) * QSTG;                        \
        const int _kb = (t) << 5;                                             \
        const size_t _ga0 = (size_t)(bm + r4) * K + _kb + c4 * 8;             \
        const size_t _ga1 = (size_t)(bm + 64 + r4) * K + _kb + c4 * 8;        \
        const size_t _gb0 = (size_t)(bnG + r4) * K + _kb + c4 * 8;            \
        CP_ASYNC16(_sb + QS_AH + so,        Ahg + _ga0);                      \
        CP_ASYNC16(_sb + QS_AH + so + 5120, Ahg + _ga1);                      \
        CP_ASYNC16(_sb + QS_BH + so,        Bhg + _gb0);                      \
        CP_ASYNC16(_sb + QS_BL + so,        Blg + _gb0);                      \
        asm volatile("cp.async.commit_group;");                               \
    } while (0)

    QLOAD(0);
    for (int t = 0; t < n_tiles; t++) {
        if (t + 1 < n_tiles) {
            QLOAD(t + 1);
            asm volatile("cp.async.wait_group 1;");
        } else {
            asm volatile("cp.async.wait_group 0;");
        }
        __syncthreads();

        const uint32_t sb = sbase + (t & 1) * QSTG;
#pragma unroll
        for (int kk = 0; kk < 2; kk++) {
            const int kc = kk * 16;
            uint32_t ah[2][4], bh[2][4], bl[2][4];
#pragma unroll
            for (int mt = 0; mt < 2; mt++) {
                uint32_t ad = sb + QS_AH +
                              ((wm + mt * 16 + arow) * HS + kc + acol) * 2;
                LDSM_X4(ah[mt], ad);
            }
#pragma unroll
            for (int a2 = 0; a2 < 2; a2++) {
                uint32_t bd = sb + QS_BH +
                              ((wn + a2 * 16 + brow) * HS + kc + bcol) * 2;
                LDSM_X4(bh[a2], bd);
                LDSM_X4(bl[a2], bd + (QS_BL - QS_BH));
            }
#pragma unroll
            for (int mt = 0; mt < 2; mt++)
#pragma unroll
                for (int nt = 0; nt < 4; nt++) {
                    const int hi2 = nt >> 1, p = (nt & 1) * 2;
                    MMA_F16B(acc[mt][nt], ah[mt], bh[hi2][p], bh[hi2][p + 1]);
                    MMA_F16B(acc[mt][nt], ah[mt], bl[hi2][p], bl[hi2][p + 1]);
                }
        }
        __syncthreads();
    }
#undef QLOAD

#pragma unroll
    for (int mt = 0; mt < 2; mt++) {
        const int row = bm + wm + mt * 16 + g;
#pragma unroll
        for (int nt = 0; nt < 4; nt++) {
            const int col = bnL + wn + nt * 8 + tg * 2;
            const float b0 = bias[col], b1 = bias[col + 1];
            float2 v0 = make_float2(acc[mt][nt][0] + b0, acc[mt][nt][1] + b1);
            float2 v1 = make_float2(acc[mt][nt][2] + b0, acc[mt][nt][3] + b1);
            *(float2*)(Y + (size_t)row * D_MODEL + col) = v0;
            *(float2*)(Y + (size_t)(row + 8) * D_MODEL + col) = v1;
        }
    }
}

/* ---------- 3-pass final GEMM (exact-ish): Y = (Ah+Al)@(Bh+Bl)^T + bias ----- */
#define STG_B   30720
#define AH_OFF  0
#define AL_OFF  10240
#define BH_OFF  20480
#define BL_OFF  25600
#define GSM_BYTES (2 * STG_B)

__global__ __launch_bounds__(256, 3) void gemm_h3b(
    const __half* __restrict__ Ahg, const __half* __restrict__ Alg,
    const __half* __restrict__ Bhg, const __half* __restrict__ Blg,
    const float* __restrict__ bias, float* __restrict__ Y,
    int M, int N, int K)
{
    extern __shared__ char smg[];
    const uint32_t sbase = smem_u32(smg);

    const int tid = threadIdx.x;
    const int bm = blockIdx.y * 128;
    const int bnG = blockIdx.x * 64;
    const int bnL = bnG;

    const int lane = tid & 31, w = tid >> 5;
    const int wm = (w >> 1) * 32, wn = (w & 1) * 32;
    const int g = lane >> 2, tg = lane & 3;
    const int arow = (lane & 7) + ((lane >> 3) & 1) * 8;
    const int acol = (lane >> 4) * 8;
    const int brow = ((lane >> 4) & 1) * 8 + (lane & 7);
    const int bcol = ((lane >> 3) & 1) * 8;
    const int r4 = tid >> 2, c4 = tid & 3;
    const uint32_t so = r4 * 80 + c4 * 16;

    float acc[2][4][4];
#pragma unroll
    for (int mt = 0; mt < 2; mt++)
#pragma unroll
        for (int nt = 0; nt < 4; nt++)
#pragma unroll
            for (int e = 0; e < 4; e++) acc[mt][nt][e] = 0.f;

    const int n_tiles = K >> 5;

#define LOAD_TILE(t) do {                                                     \
        const uint32_t _sb = sbase + ((t) & 1) * STG_B;                       \
        const int _kb = (t) << 5;                                             \
        const size_t _ga0 = (size_t)(bm + r4) * K + _kb + c4 * 8;             \
        const size_t _ga1 = (size_t)(bm + 64 + r4) * K + _kb + c4 * 8;        \
        const size_t _gb0 = (size_t)(bnG + r4) * K + _kb + c4 * 8;            \
        CP_ASYNC16(_sb + AH_OFF + so,           Ahg + _ga0);                  \
        CP_ASYNC16(_sb + AH_OFF + so + 5120,    Ahg + _ga1);                  \
        CP_ASYNC16(_sb + AL_OFF + so,           Alg + _ga0);                  \
        CP_ASYNC16(_sb + AL_OFF + so + 5120,    Alg + _ga1);                  \
        CP_ASYNC16(_sb + BH_OFF + so,           Bhg + _gb0);                  \
        CP_ASYNC16(_sb + BL_OFF + so,           Blg + _gb0);                  \
        asm volatile("cp.async.commit_group;");                               \
    } while (0)

    LOAD_TILE(0);
    for (int t = 0; t < n_tiles; t++) {
        if (t + 1 < n_tiles) {
            LOAD_TILE(t + 1);
            asm volatile("cp.async.wait_group 1;");
        } else {
            asm volatile("cp.async.wait_group 0;");
        }
        __syncthreads();

        const uint32_t sb = sbase + (t & 1) * STG_B;
#pragma unroll
        for (int kk = 0; kk < 2; kk++) {
            const int kc = kk * 16;
            uint32_t ah[2][4], al[2][4], bh[2][4], bl[2][4];
#pragma unroll
            for (int mt = 0; mt < 2; mt++) {
                uint32_t ad = sb + AH_OFF +
                              ((wm + mt * 16 + arow) * HS + kc + acol) * 2;
                LDSM_X4(ah[mt], ad);
                LDSM_X4(al[mt], ad + (AL_OFF - AH_OFF));
            }
#pragma unroll
            for (int a2 = 0; a2 < 2; a2++) {
                uint32_t bd = sb + BH_OFF +
                              ((wn + a2 * 16 + brow) * HS + kc + bcol) * 2;
                LDSM_X4(bh[a2], bd);
                LDSM_X4(bl[a2], bd + (BL_OFF - BH_OFF));
            }
#pragma unroll
            for (int mt = 0; mt < 2; mt++)
#pragma unroll
                for (int nt = 0; nt < 4; nt++) {
                    const int hi2 = nt >> 1, p = (nt & 1) * 2;
                    MMA_F16B(acc[mt][nt], ah[mt], bh[hi2][p], bh[hi2][p + 1]);
                    MMA_F16B(acc[mt][nt], ah[mt], bl[hi2][p], bl[hi2][p + 1]);
                    MMA_F16B(acc[mt][nt], al[mt], bh[hi2][p], bh[hi2][p + 1]);
                }
        }
        __syncthreads();
    }
#undef LOAD_TILE

#pragma unroll
    for (int mt = 0; mt < 2; mt++) {
        const int row = bm + wm + mt * 16 + g;
#pragma unroll
        for (int nt = 0; nt < 4; nt++) {
            const int col = bnL + wn + nt * 8 + tg * 2;
            const float b0 = bias[col], b1 = bias[col + 1];
            float2 v0 = make_float2(acc[mt][nt][0] + b0, acc[mt][nt][1] + b1);
            float2 v1 = make_float2(acc[mt][nt][2] + b0, acc[mt][nt][3] + b1);
            *(float2*)(Y + (size_t)row * N + col) = v0;
            *(float2*)(Y + (size_t)(row + 8) * N + col) = v1;
        }
    }
}

/* -------- fused: short-conv(K=4) + beta + silu + L2 norm (round-7 version) -- */
__global__ __launch_bounds__(256) void prep_kernel(
    const float* __restrict__ x,
    const float* __restrict__ Wbeta, const float* __restrict__ bbeta,
    const float* __restrict__ ck, const float* __restrict__ cq,
    const float* __restrict__ cv)
{
    __shared__ float xrow[D_MODEL];
    __shared__ float ks[D_MODEL], qs[D_MODEL], vs[D_MODEL];
    __shared__ float eta_s[N_HEADS], kn_s[N_HEADS], qn_s[N_HEADS];

    const int bl = blockIdx.x;
    const int b = bl >> 11;
    const int l = bl & 2047;
    const int tid = threadIdx.x;

    for (int d = tid; d < D_MODEL; d += 256) xrow[d] = x[(size_t)bl * D_MODEL + d];

    for (int d = tid; d < D_MODEL; d += 256) {
        float ak = 0.f, aq = 0.f, av = 0.f;
#pragma unroll
        for (int j = 0; j < 4; j++) {
            int ls = l + j - 3;
            if (ls >= 0) {
                size_t idx = ((size_t)b * L_DIM + ls) * D_MODEL + d;
                ak += g_kpre[idx] * ck[d * 4 + j];
                aq += g_qpre[idx] * cq[d * 4 + j];
                av += g_vpre[idx] * cv[d * 4 + j];
            }
        }
        ks[d] = ak; qs[d] = aq; vs[d] = av;
    }
    __syncthreads();

    const int warp = tid >> 5, lane = tid & 31;
    for (int h = warp; h < N_HEADS; h += 8) {
        float s = 0.f;
        const float* wb = Wbeta + h * D_MODEL;
        for (int k = lane; k < D_MODEL; k += 32) s += xrow[k] * wb[k];
#pragma unroll
        for (int o = 16; o > 0; o >>= 1) s += __shfl_down_sync(0xffffffffu, s, o);
        if (lane == 0) eta_s[h] = 1.f / (1.f + __expf(-(s + bbeta[h])));
    }
    for (int h = warp; h < N_HEADS; h += 8) {
        float a0 = ks[h * 64 + lane], a1 = ks[h * 64 + 32 + lane];
        float sk = a0 * a0 + a1 * a1;
        float q0 = qs[h * 64 + lane], q1 = qs[h * 64 + 32 + lane];
        float sq = q0 * q0 + q1 * q1;
#pragma unroll
        for (int o = 16; o > 0; o >>= 1) {
            sk += __shfl_down_sync(0xffffffffu, sk, o);
            sq += __shfl_down_sync(0xffffffffu, sq, o);
        }
        if (lane == 0) { kn_s[h] = sqrtf(sk); qn_s[h] = sqrtf(sq); }
    }
    __syncthreads();

    for (int d = tid; d < D_MODEL; d += 256) {
        int h = d >> 6;
        float kn = ks[d] / (kn_s[h] + 1e-6f);
        float qn = qs[d] / (qn_s[h] + 1e-6f);
        float vv = vs[d];
        float sv = vv / (1.f + __expf(-vv));
        float e = eta_s[h];
        size_t base = (((size_t)(b * N_HEADS + h)) * L_DIM + l) * D_HEAD + (d & 63);
        g_kn[base] = kn;
        g_qn[base] = qn;
        g_vs[base] = e * sv;
        g_bb[base] = e * kn;
    }
}

/* ---------------- chunked o2b weighted delta-rule scan (round-7 version) ---- */
#define SMEM_FLOATS (4 * 64 * FS + 3 * 64 * HSX + 512 + 256)

__global__ __launch_bounds__(256) void delta_kernel()
{
    extern __shared__ float smd[];
    float* Ks   = smd;                 /* 64 x 65 */
    float* Qs   = Ks + 64 * FS;
    float* Bss  = Qs + 64 * FS;
    float* Ts   = Bss + 64 * FS;
    float* Wt   = Ts + 64 * FS;        /* 64 x 33 */
    float* Wa   = Wt + 64 * HSX;
    float* Us   = Wa + 64 * HSX;
    float* invD = Us + 64 * HSX;       /* 512 */
    float* Mb   = invD + 512;          /* 8 x 32 */

    const int tid = threadIdx.x;
    const int tx = tid & 15;
    const int ty = tid >> 4;
    const int pair = blockIdx.x >> 1;
    const int half = blockIdx.x & 1;
    const int col0 = half * 32;
    const int b = pair >> 4, h = pair & 15;

    for (int i = tid; i < 64 * HSX; i += 256) { Wt[i] = 0.f; Wa[i] = 0.f; }

    const size_t pbase = (size_t)pair * L_DIM * D_HEAD;

    for (int chunk = 0; chunk < N_CHUNK; chunk++) {
        __syncthreads();
        const size_t cb = pbase + (size_t)chunk * 64 * D_HEAD;
        for (int i2 = tid; i2 < 4096; i2 += 256) {
            int s = (i2 >> 6) * FS + (i2 & 63);
            Ks[s]  = g_kn[cb + i2];
            Qs[s]  = g_qn[cb + i2];
            Bss[s] = g_bb[cb + i2];
        }
        for (int i2 = tid; i2 < 2048; i2 += 256) {
            int r = i2 >> 5, c = i2 & 31;
            Us[r * HSX + c] = g_vs[cb + r * 64 + col0 + c];
        }
        __syncthreads();

        const float ts    = (float)(chunk * 64);
        const float tri0  = 0.5f * (1.f + ts) * ts;
        const float denw  = 0.5f * (65.f + ts) * (64.f + ts);
        const float Ssum  = 64.f * ts + 2080.f;
        const float coef1 = (ts / (ts + 64.f)) * ((1.f + ts) / (ts + 65.f));
        const float coef2 = (64.f / (ts + 64.f)) * ((2.f * ts + 65.f) / (ts + 65.f));

        /* A: T = strict_tril(B @ K^T)  (full 64x64) */
        {
            float acc[4][4] = {};
            for (int k = 0; k < 64; k++) {
                float a0[4], b0[4];
#pragma unroll
                for (int i = 0; i < 4; i++) a0[i] = Bss[(4 * ty + i) * FS + k];
#pragma unroll
                for (int j = 0; j < 4; j++) b0[j] = Ks[(4 * tx + j) * FS + k];
#pragma unroll
                for (int i = 0; i < 4; i++)
#pragma unroll
                    for (int j = 0; j < 4; j++) acc[i][j] += a0[i] * b0[j];
            }
#pragma unroll
            for (int i = 0; i < 4; i++)
#pragma unroll
                for (int j = 0; j < 4; j++) {
                    int r = 4 * ty + i, c = 4 * tx + j;
                    Ts[r * FS + c] = (r > c) ? acc[i][j] : 0.f;
                }
        }
        __syncthreads();

        /* C0: invert the 8 unit-lower 8x8 diagonal blocks (threads 0-63) */
        if (tid < 64) {
            const int blk = tid >> 3, c = tid & 7;
            const int r0 = blk * 8;
            float xcol[8];
#pragma unroll
            for (int r = 0; r < 8; r++) {
                float s = (r == c) ? 1.f : 0.f;
                for (int k2 = c; k2 < r; k2++)
                    s -= Ts[(r0 + r) * FS + r0 + k2] * xcol[k2];
                xcol[r] = s;
            }
#pragma unroll
            for (int r = 0; r < 8; r++) invD[(r0 + r) * 8 + c] = xcol[r];
        }

        /* B: RHS = V - B @ W_t   (64 x 32, into Us) */
        {
            float acc[4][2] = {};
            for (int k = 0; k < 64; k++) {
                float a0[4], w0[2];
#pragma unroll
                for (int i = 0; i < 4; i++) a0[i] = Bss[(4 * ty + i) * FS + k];
#pragma unroll
                for (int j = 0; j < 2; j++) w0[j] = Wt[k * HSX + 2 * tx + j];
#pragma unroll
                for (int i = 0; i < 4; i++)
#pragma unroll
                    for (int j = 0; j < 2; j++) acc[i][j] += a0[i] * w0[j];
            }
#pragma unroll
            for (int i = 0; i < 4; i++)
#pragma unroll
                for (int j = 0; j < 2; j++)
                    Us[(4 * ty + i) * HSX + 2 * tx + j] -= acc[i][j];
        }
        __syncthreads();

        /* C: blocked forward substitution  (I+T) U = RHS  (32 cols) */
        {
            const int cc = tid & 31, rr = tid >> 5;
            for (int ib = 0; ib < 8; ib++) {
                const int r0 = ib * 8;
                float s = 0.f;
                for (int j = 0; j < r0; j++)
                    s += Ts[(r0 + rr) * FS + j] * Us[j * HSX + cc];
                float rhs = Us[(r0 + rr) * HSX + cc] - s;
                Mb[rr * 32 + cc] = rhs;
                __syncthreads();
                s = rhs;
                for (int k2 = 0; k2 < rr; k2++)
                    s += invD[(r0 + rr) * 8 + k2] * Mb[k2 * 32 + cc];
                Us[(r0 + rr) * HSX + cc] = s;
                __syncthreads();
            }
        }

        float csr[4], rdiv[4], arr[4];
#pragma unroll
        for (int i = 0; i < 4; i++) {
            float rr2 = (float)(4 * ty + i);
            float cs = (rr2 + 1.f) * ts + 0.5f * (rr2 + 1.f) * (rr2 + 2.f);
            csr[i]  = cs;
            rdiv[i] = 1.f / (tri0 + cs);
            arr[i]  = tri0 * rdiv[i];
        }

        /* D: O = (Q @ W_avg)*a + (Q @ W_t)*(1-a)   (64 x 32) */
        float o[4][2];
        {
            float acc1[4][2] = {}, acc2[4][2] = {};
            for (int k = 0; k < 64; k++) {
                float q0[4], wa0[2], wt0[2];
#pragma unroll
                for (int i = 0; i < 4; i++) q0[i] = Qs[(4 * ty + i) * FS + k];
#pragma unroll
                for (int j = 0; j < 2; j++) {
                    wa0[j] = Wa[k * HSX + 2 * tx + j];
                    wt0[j] = Wt[k * HSX + 2 * tx + j];
                }
#pragma unroll
                for (int i = 0; i < 4; i++)
#pragma unroll
                    for (int j = 0; j < 2; j++) {
                        acc1[i][j] += q0[i] * wa0[j];
                        acc2[i][j] += q0[i] * wt0[j];
                    }
            }
#pragma unroll
            for (int i = 0; i < 4; i++)
#pragma unroll
                for (int j = 0; j < 2; j++)
                    o[i][j] = acc1[i][j] * arr[i] + acc2[i][j] * (1.f - arr[i]);
        }

        /* E: QK = Q @ K^T (full, into Ts) */
        {
            float acc[4][4] = {};
            for (int k = 0; k < 64; k++) {
                float q0[4], k0[4];
#pragma unroll
                for (int i = 0; i < 4; i++) q0[i] = Qs[(4 * ty + i) * FS + k];
#pragma unroll
                for (int j = 0; j < 4; j++) k0[j] = Ks[(4 * tx + j) * FS + k];
#pragma unroll
                for (int i = 0; i < 4; i++)
#pragma unroll
                    for (int j = 0; j < 4; j++) acc[i][j] += q0[i] * k0[j];
            }
#pragma unroll
            for (int i = 0; i < 4; i++)
#pragma unroll
                for (int j = 0; j < 4; j++)
                    Ts[(4 * ty + i) * FS + 4 * tx + j] = acc[i][j];
        }
        __syncthreads();

        /* F: O += (T_mat o QK) @ U */
        {
            for (int kp = 0; kp < 64; kp++) {
                float kf = (float)kp;
                float csk_m = kf * ts + 0.5f * kf * (kf + 1.f);
                float u0[2];
#pragma unroll
                for (int j = 0; j < 2; j++) u0[j] = Us[kp * HSX + 2 * tx + j];
#pragma unroll
                for (int i = 0; i < 4; i++) {
                    float num  = csr[i] - csk_m;
                    float sfac = (num >= 0.f) ? num * rdiv[i] : 0.f;
                    float sv   = sfac * Ts[(4 * ty + i) * FS + kp];
#pragma unroll
                    for (int j = 0; j < 2; j++) o[i][j] += sv * u0[j];
                }
            }
        }

        /* G: write raw O (RMS deferred) */
        {
            const int cidx = h * 64 + col0 + 2 * tx;
#pragma unroll
            for (int i = 0; i < 4; i++) {
                int l = chunk * 64 + 4 * ty + i;
                *(float2*)&g_o[((size_t)(b * L_DIM + l)) * D_MODEL + cidx] =
                    make_float2(o[i][0], o[i][1]);
            }
        }

        /* H: W updates (64 x 32) */
        {
            float p1[4][2] = {}, p2[4][2] = {};
            for (int r = 0; r < 64; r++) {
                float rr2  = (float)r;
                float idxr = ts + rr2 + 1.f;
                float csrr = (rr2 + 1.f) * ts + 0.5f * (rr2 + 1.f) * (rr2 + 2.f);
                float wr   = (idxr + Ssum - csrr) / denw;
                float kv[4], uv[2];
#pragma unroll
                for (int i = 0; i < 4; i++) kv[i] = Ks[r * FS + 4 * ty + i];
#pragma unroll
                for (int j = 0; j < 2; j++) uv[j] = Us[r * HSX + 2 * tx + j];
#pragma unroll
                for (int i = 0; i < 4; i++)
#pragma unroll
                    for (int j = 0; j < 2; j++) {
                        p1[i][j] += kv[i] * uv[j];
                        p2[i][j] += kv[i] * uv[j] * wr;
                    }
            }
#pragma unroll
            for (int i = 0; i < 4; i++)
#pragma unroll
                for (int j = 0; j < 2; j++) {
                    int idx2 = (4 * ty + i) * HSX + 2 * tx + j;
                    float wold = Wt[idx2], waold = Wa[idx2];
                    Wa[idx2] = coef1 * waold + coef2 * wold + p2[i][j];
                    Wt[idx2] = wold + p1[i][j];
                }
        }
    }
}

/* -------- RMS norm over head dim + fp16 hi/lo split for final GEMM ---------- */
__global__ __launch_bounds__(256) void rms_split(const float* __restrict__ rms_w)
{
    const int bl = blockIdx.x, tid = threadIdx.x;
    float4 v = ((const float4*)g_o)[(size_t)bl * 256 + tid];
    float ss = v.x * v.x + v.y * v.y + v.z * v.z + v.w * v.w;
#pragma unroll
    for (int o = 8; o > 0; o >>= 1) ss += __shfl_xor_sync(0xffffffffu, ss, o);
    float scale = rsqrtf(ss * (1.f / 64.f) + 1e-6f);
    float4 rw = ((const float4*)rms_w)[tid & 15];
    float a0 = v.x * scale * rw.x, a1 = v.y * scale * rw.y;
    float a2 = v.z * scale * rw.z, a3 = v.w * scale * rw.w;
    __half2 h01 = __floats2half2_rn(a0, a1);
    __half2 h23 = __floats2half2_rn(a2, a3);
    __half2 l01 = __floats2half2_rn(a0 - __low2float(h01), a1 - __high2float(h01));
    __half2 l23 = __floats2half2_rn(a2 - __low2float(h23), a3 - __high2float(h23));
    ((uint2*)g_oh)[(size_t)bl * 256 + tid] = make_uint2(*(uint32_t*)&h01, *(uint32_t*)&h23);
    ((uint2*)g_ol)[(size_t)bl * 256 + tid] = make_uint2(*(uint32_t*)&l01, *(uint32_t*)&l23);
}

/* ------------------------------- launcher ----------------------------------*/
extern "C" void kernel_launch(void* const* d_in, const int* in_sizes, int n_in,
                              void* d_out, int out_size)
{
    (void)in_sizes; (void)n_in; (void)out_size;
    const float* x     = (const float*)d_in[0];
    const float* Wk    = (const float*)d_in[1];
    const float* bk    = (const float*)d_in[2];
    const float* Wq    = (const float*)d_in[3];
    const float* bq    = (const float*)d_in[4];
    const float* Wv    = (const float*)d_in[5];
    const float* bv    = (const float*)d_in[6];
    const float* Wbeta = (const float*)d_in[7];
    const float* bbeta = (const float*)d_in[8];
    const float* ck    = (const float*)d_in[9];
    const float* cq    = (const float*)d_in[10];
    const float* cv    = (const float*)d_in[11];
    const float* rms_w = (const float*)d_in[12];
    const float* Wout  = (const float*)d_in[13];
    const float* bout  = (const float*)d_in[14];
    float* out = (float*)d_out;

    float *kpre, *qpre, *vpre;
    __half *xh, *xl, *oh, *ol, *wsh, *wsl;
    cudaGetSymbolAddress((void**)&kpre, g_kpre);
    cudaGetSymbolAddress((void**)&qpre, g_qpre);
    cudaGetSymbolAddress((void**)&vpre, g_vpre);
    cudaGetSymbolAddress((void**)&xh, g_xh);
    cudaGetSymbolAddress((void**)&xl, g_xl);
    cudaGetSymbolAddress((void**)&oh, g_oh);
    cudaGetSymbolAddress((void**)&ol, g_ol);
    cudaGetSymbolAddress((void**)&wsh, g_wsh);
    cudaGetSymbolAddress((void**)&wsl, g_wsl);

    split_f2h<<<(ML * D_MODEL / 4 + 255) / 256, 256>>>(
        (const float4*)x, (uint2*)xh, (uint2*)xl, ML * D_MODEL / 4);
    split_w4<<<(4 * DD / 4) / 256, 256>>>(
        (const float4*)Wk, (const float4*)Wq, (const float4*)Wv,
        (const float4*)Wout, (uint2*)wsh, (uint2*)wsl);

    cudaFuncSetAttribute(gemm_qkv2, cudaFuncAttributeMaxDynamicSharedMemorySize,
                         QSM_BYTES);
    cudaFuncSetAttribute(gemm_h3b, cudaFuncAttributeMaxDynamicSharedMemorySize,
                         GSM_BYTES);

    gemm_qkv2<<<dim3(48, 64), 256, QSM_BYTES>>>(
        xh, wsh, wsl, bk, bq, bv, kpre, qpre, vpre, ML, D_MODEL);

    prep_kernel<<<ML, 256>>>(x, Wbeta, bbeta, ck, cq, cv);

    size_t smem_bytes = SMEM_FLOATS * sizeof(float);
    cudaFuncSetAttribute(delta_kernel, cudaFuncAttributeMaxDynamicSharedMemorySize,
                         (int)smem_bytes);
    delta_kernel<<<2 * N_PAIR, 256, smem_bytes>>>();

    rms_split<<<ML, 256>>>(rms_w);

    gemm_h3b<<<dim3(16, 64), 256, GSM_BYTES>>>(
        oh, ol, wsh + 3 * DD, wsl + 3 * DD, bout, out, ML, D_MODEL, D_MODEL);
}

// round 10
// speedup vs baseline: 1.1803x; 1.0194x over previous
#include <cuda_runtime.h>
#include <cuda_fp16.h>
#include <math.h>
#include <stdint.h>

#define B_DIM   4
#define L_DIM   2048
#define D_MODEL 1024
#define N_HEADS 16
#define D_HEAD  64
#define ML      (B_DIM * L_DIM)
#define N_PAIR  (B_DIM * N_HEADS)
#define N_CHUNK (L_DIM / 64)
#define DD      (D_MODEL * D_MODEL)
#define FS      65                       /* full-array smem stride */
#define HSX     33                       /* half-array smem stride */

/* ---------------- scratch (device globals; no runtime alloc) ---------------- */
__device__ float  g_kpre[ML * D_MODEL];
__device__ float  g_qpre[ML * D_MODEL];
__device__ float  g_vpre[ML * D_MODEL];
__device__ float  g_kn  [ML * D_MODEL];
__device__ float  g_qn  [ML * D_MODEL];
__device__ float  g_vs  [ML * D_MODEL];
__device__ float  g_bb  [ML * D_MODEL];
__device__ float  g_o   [ML * D_MODEL];
__device__ __half g_xh  [ML * D_MODEL];
__device__ __half g_xl  [ML * D_MODEL];
__device__ __half g_oh  [ML * D_MODEL];
__device__ __half g_ol  [ML * D_MODEL];
__device__ __half g_wsh [4 * DD];
__device__ __half g_wsl [4 * DD];

/* ---------------- fp32 -> (hi,lo) fp16 split, vectorized -------------------- */
__device__ __forceinline__ void split4(float4 v, uint2& hi, uint2& lo) {
    __half2 h01 = __floats2half2_rn(v.x, v.y);
    __half2 h23 = __floats2half2_rn(v.z, v.w);
    __half2 l01 = __floats2half2_rn(v.x - __low2float(h01), v.y - __high2float(h01));
    __half2 l23 = __floats2half2_rn(v.z - __low2float(h23), v.w - __high2float(h23));
    hi = make_uint2(*(uint32_t*)&h01, *(uint32_t*)&h23);
    lo = make_uint2(*(uint32_t*)&l01, *(uint32_t*)&l23);
}

__global__ __launch_bounds__(256) void split_f2h(
    const float4* __restrict__ src, uint2* __restrict__ hi,
    uint2* __restrict__ lo, int n4)
{
    int i = blockIdx.x * blockDim.x + threadIdx.x;
    if (i >= n4) return;
    uint2 h, l;
    split4(src[i], h, l);
    hi[i] = h; lo[i] = l;
}

__global__ __launch_bounds__(256) void split_w4(
    const float4* __restrict__ w0, const float4* __restrict__ w1,
    const float4* __restrict__ w2, const float4* __restrict__ w3,
    uint2* __restrict__ hi, uint2* __restrict__ lo)
{
    int i = blockIdx.x * blockDim.x + threadIdx.x;
    int seg = i >> 18;                               /* DD/4 = 2^18 */
    int off = i & ((DD / 4) - 1);
    const float4* src = (seg == 0) ? w0 : (seg == 1) ? w1 : (seg == 2) ? w2 : w3;
    uint2 h, l;
    split4(src[off], h, l);
    hi[i] = h; lo[i] = l;
}

/* =================== tensor-core GEMM machinery (FP16 splits) =============== */
#define HS      40

__device__ __forceinline__ uint32_t smem_u32(const void* p) {
    uint32_t a;
    asm("{ .reg .u64 t; cvta.to.shared.u64 t, %1; cvt.u32.u64 %0, t; }"
        : "=r"(a) : "l"(p));
    return a;
}

#define LDSM_X4(r, a)                                                         \
    asm volatile("ldmatrix.sync.aligned.m8n8.x4.shared.b16 "                  \
                 "{%0,%1,%2,%3}, [%4];"                                       \
                 : "=r"((r)[0]), "=r"((r)[1]), "=r"((r)[2]), "=r"((r)[3])     \
                 : "r"(a))

#define MMA_F16B(d, a, b0, b1)                                                \
    asm volatile(                                                             \
        "mma.sync.aligned.m16n8k16.row.col.f32.f16.f16.f32 "                  \
        "{%0,%1,%2,%3}, {%4,%5,%6,%7}, {%8,%9}, {%0,%1,%2,%3};"               \
        : "+f"(d[0]), "+f"(d[1]), "+f"(d[2]), "+f"(d[3])                      \
        : "r"(a[0]), "r"(a[1]), "r"(a[2]), "r"(a[3]), "r"(b0), "r"(b1))

#define CP_ASYNC16(sa, gp)                                                    \
    asm volatile("cp.async.cg.shared.global [%0], [%1], 16;"                  \
                 :: "r"(sa), "l"(gp))

/* ---------- 2-pass QKV GEMM, 3-stage pipeline: Y = Ah @ (Bh+Bl)^T + bias ---- */
#define QS_AH   0
#define QS_BH   10240
#define QS_BL   15360
#define QSTG    20480
#define QSM_BYTES (3 * QSTG)

__global__ __launch_bounds__(256, 3) void gemm_qkv2(
    const __half* __restrict__ Ahg,
    const __half* __restrict__ Bhg, const __half* __restrict__ Blg,
    const float* __restrict__ bk, const float* __restrict__ bq,
    const float* __restrict__ bv,
    float* __restrict__ Yk, float* __restrict__ Yq, float* __restrict__ Yv,
    int M, int K)
{
    extern __shared__ char smg[];
    const uint32_t sbase = smem_u32(smg);

    const int tid = threadIdx.x;
    const int bm = blockIdx.y * 128;
    const int bnG = blockIdx.x * 64;
    const int seg = bnG >> 10;
    const int bnL = bnG & 1023;
    const float* bias = (seg == 0) ? bk : (seg == 1) ? bq : bv;
    float* Y = (seg == 0) ? Yk : (seg == 1) ? Yq : Yv;

    const int lane = tid & 31, w = tid >> 5;
    const int wm = (w >> 1) * 32, wn = (w & 1) * 32;
    const int g = lane >> 2, tg = lane & 3;
    const int arow = (lane & 7) + ((lane >> 3) & 1) * 8;
    const int acol = (lane >> 4) * 8;
    const int brow = ((lane >> 4) & 1) * 8 + (lane & 7);
    const int bcol = ((lane >> 3) & 1) * 8;
    const int r4 = tid >> 2, c4 = tid & 3;
    const uint32_t so = r4 * 80 + c4 * 16;

    float acc[2][4][4];
#pragma unroll
    for (int mt = 0; mt < 2; mt++)
#pragma unroll
        for (int nt = 0; nt < 4; nt++)
#pragma unroll
            for (int e = 0; e < 4; e++) acc[mt][nt][e] = 0.f;

    const int n_tiles = K >> 5;

#define QLOAD(t) do {                                                         \
        const uint32_t _sb = sbase + ((t) % 3) * QSTG;                        \
        const int _kb = (t) << 5;                                             \
        const size_t _ga0 = (size_t)(bm + r4) * K + _kb + c4 * 8;             \
        const size_t _ga1 = (size_t)(bm + 64 + r4) * K + _kb + c4 * 8;        \
        const size_t _gb0 = (size_t)(bnG + r4) * K + _kb + c4 * 8;            \
        CP_ASYNC16(_sb + QS_AH + so,        Ahg + _ga0);                      \
        CP_ASYNC16(_sb + QS_AH + so + 5120, Ahg + _ga1);                      \
        CP_ASYNC16(_sb + QS_BH + so,        Bhg + _gb0);                      \
        CP_ASYNC16(_sb + QS_BL + so,        Blg + _gb0);                      \
        asm volatile("cp.async.commit_group;");                               \
    } while (0)

    QLOAD(0);
    QLOAD(1);
    for (int t = 0; t < n_tiles; t++) {
        if (t + 2 < n_tiles) {
            QLOAD(t + 2);
            asm volatile("cp.async.wait_group 2;");
        } else if (t + 1 < n_tiles) {
            asm volatile("cp.async.wait_group 1;");
        } else {
            asm volatile("cp.async.wait_group 0;");
        }
        __syncthreads();

        const uint32_t sb = sbase + (t % 3) * QSTG;
#pragma unroll
        for (int kk = 0; kk < 2; kk++) {
            const int kc = kk * 16;
            uint32_t ah[2][4], bh[2][4], bl[2][4];
#pragma unroll
            for (int mt = 0; mt < 2; mt++) {
                uint32_t ad = sb + QS_AH +
                              ((wm + mt * 16 + arow) * HS + kc + acol) * 2;
                LDSM_X4(ah[mt], ad);
            }
#pragma unroll
            for (int a2 = 0; a2 < 2; a2++) {
                uint32_t bd = sb + QS_BH +
                              ((wn + a2 * 16 + brow) * HS + kc + bcol) * 2;
                LDSM_X4(bh[a2], bd);
                LDSM_X4(bl[a2], bd + (QS_BL - QS_BH));
            }
#pragma unroll
            for (int mt = 0; mt < 2; mt++)
#pragma unroll
                for (int nt = 0; nt < 4; nt++) {
                    const int hi2 = nt >> 1, p = (nt & 1) * 2;
                    MMA_F16B(acc[mt][nt], ah[mt], bh[hi2][p], bh[hi2][p + 1]);
                    MMA_F16B(acc[mt][nt], ah[mt], bl[hi2][p], bl[hi2][p + 1]);
                }
        }
        __syncthreads();
    }
#undef QLOAD

#pragma unroll
    for (int mt = 0; mt < 2; mt++) {
        const int row = bm + wm + mt * 16 + g;
#pragma unroll
        for (int nt = 0; nt < 4; nt++) {
            const int col = bnL + wn + nt * 8 + tg * 2;
            const float b0 = bias[col], b1 = bias[col + 1];
            float2 v0 = make_float2(acc[mt][nt][0] + b0, acc[mt][nt][1] + b1);
            float2 v1 = make_float2(acc[mt][nt][2] + b0, acc[mt][nt][3] + b1);
            *(float2*)(Y + (size_t)row * D_MODEL + col) = v0;
            *(float2*)(Y + (size_t)(row + 8) * D_MODEL + col) = v1;
        }
    }
}

/* ---------- 3-pass final GEMM: Y = (Ah+Al)@(Bh+Bl)^T + bias ----------------- */
#define STG_B   30720
#define AH_OFF  0
#define AL_OFF  10240
#define BH_OFF  20480
#define BL_OFF  25600
#define GSM_BYTES (2 * STG_B)

__global__ __launch_bounds__(256, 3) void gemm_h3b(
    const __half* __restrict__ Ahg, const __half* __restrict__ Alg,
    const __half* __restrict__ Bhg, const __half* __restrict__ Blg,
    const float* __restrict__ bias, float* __restrict__ Y,
    int M, int N, int K)
{
    extern __shared__ char smg[];
    const uint32_t sbase = smem_u32(smg);

    const int tid = threadIdx.x;
    const int bm = blockIdx.y * 128;
    const int bnG = blockIdx.x * 64;
    const int bnL = bnG;

    const int lane = tid & 31, w = tid >> 5;
    const int wm = (w >> 1) * 32, wn = (w & 1) * 32;
    const int g = lane >> 2, tg = lane & 3;
    const int arow = (lane & 7) + ((lane >> 3) & 1) * 8;
    const int acol = (lane >> 4) * 8;
    const int brow = ((lane >> 4) & 1) * 8 + (lane & 7);
    const int bcol = ((lane >> 3) & 1) * 8;
    const int r4 = tid >> 2, c4 = tid & 3;
    const uint32_t so = r4 * 80 + c4 * 16;

    float acc[2][4][4];
#pragma unroll
    for (int mt = 0; mt < 2; mt++)
#pragma unroll
        for (int nt = 0; nt < 4; nt++)
#pragma unroll
            for (int e = 0; e < 4; e++) acc[mt][nt][e] = 0.f;

    const int n_tiles = K >> 5;

#define LOAD_TILE(t) do {                                                     \
        const uint32_t _sb = sbase + ((t) & 1) * STG_B;                       \
        const int _kb = (t) << 5;                                             \
        const size_t _ga0 = (size_t)(bm + r4) * K + _kb + c4 * 8;             \
        const size_t _ga1 = (size_t)(bm + 64 + r4) * K + _kb + c4 * 8;        \
        const size_t _gb0 = (size_t)(bnG + r4) * K + _kb + c4 * 8;            \
        CP_ASYNC16(_sb + AH_OFF + so,           Ahg + _ga0);                  \
        CP_ASYNC16(_sb + AH_OFF + so + 5120,    Ahg + _ga1);                  \
        CP_ASYNC16(_sb + AL_OFF + so,           Alg + _ga0);                  \
        CP_ASYNC16(_sb + AL_OFF + so + 5120,    Alg + _ga1);                  \
        CP_ASYNC16(_sb + BH_OFF + so,           Bhg + _gb0);                  \
        CP_ASYNC16(_sb + BL_OFF + so,           Blg + _gb0);                  \
        asm volatile("cp.async.commit_group;");                               \
    } while (0)

    LOAD_TILE(0);
    for (int t = 0; t < n_tiles; t++) {
        if (t + 1 < n_tiles) {
            LOAD_TILE(t + 1);
            asm volatile("cp.async.wait_group 1;");
        } else {
            asm volatile("cp.async.wait_group 0;");
        }
        __syncthreads();

        const uint32_t sb = sbase + (t & 1) * STG_B;
#pragma unroll
        for (int kk = 0; kk < 2; kk++) {
            const int kc = kk * 16;
            uint32_t ah[2][4], al[2][4], bh[2][4], bl[2][4];
#pragma unroll
            for (int mt = 0; mt < 2; mt++) {
                uint32_t ad = sb + AH_OFF +
                              ((wm + mt * 16 + arow) * HS + kc + acol) * 2;
                LDSM_X4(ah[mt], ad);
                LDSM_X4(al[mt], ad + (AL_OFF - AH_OFF));
            }
#pragma unroll
            for (int a2 = 0; a2 < 2; a2++) {
                uint32_t bd = sb + BH_OFF +
                              ((wn + a2 * 16 + brow) * HS + kc + bcol) * 2;
                LDSM_X4(bh[a2], bd);
                LDSM_X4(bl[a2], bd + (BL_OFF - BH_OFF));
            }
#pragma unroll
            for (int mt = 0; mt < 2; mt++)
#pragma unroll
                for (int nt = 0; nt < 4; nt++) {
                    const int hi2 = nt >> 1, p = (nt & 1) * 2;
                    MMA_F16B(acc[mt][nt], ah[mt], bh[hi2][p], bh[hi2][p + 1]);
                    MMA_F16B(acc[mt][nt], ah[mt], bl[hi2][p], bl[hi2][p + 1]);
                    MMA_F16B(acc[mt][nt], al[mt], bh[hi2][p], bh[hi2][p + 1]);
                }
        }
        __syncthreads();
    }
#undef LOAD_TILE

#pragma unroll
    for (int mt = 0; mt < 2; mt++) {
        const int row = bm + wm + mt * 16 + g;
#pragma unroll
        for (int nt = 0; nt < 4; nt++) {
            const int col = bnL + wn + nt * 8 + tg * 2;
            const float b0 = bias[col], b1 = bias[col + 1];
            float2 v0 = make_float2(acc[mt][nt][0] + b0, acc[mt][nt][1] + b1);
            float2 v1 = make_float2(acc[mt][nt][2] + b0, acc[mt][nt][3] + b1);
            *(float2*)(Y + (size_t)row * N + col) = v0;
            *(float2*)(Y + (size_t)(row + 8) * N + col) = v1;
        }
    }
}

/* -------- prep8: 8 tokens/CTA, register sliding window over conv taps -------
   thread owns 4 channels; 11 rows loaded once instead of 16 rows re-read. --- */
__global__ __launch_bounds__(256) void prep8(
    const float* __restrict__ x,
    const float* __restrict__ Wbeta, const float* __restrict__ bbeta,
    const float* __restrict__ ck, const float* __restrict__ cq,
    const float* __restrict__ cv)
{
    __shared__ float xs[8 * D_MODEL];     /* 32 KB */
    __shared__ float eta_s[8][N_HEADS];

    const int bid = blockIdx.x;           /* 0..1023 */
    const int b = bid >> 8;
    const int l0 = (bid & 255) * 8;
    const int tid = threadIdx.x;
    const int d = tid * 4;
    const int h = tid >> 4;
    const int lane = tid & 31;

    /* x rows -> smem (for beta) */
#pragma unroll
    for (int i = 0; i < 8; i++) {
        int idx = i * 256 + tid;          /* 2048 float4 total */
        int t = idx >> 8, c = idx & 255;
        ((float4*)xs)[t * 256 + c] =
            *(const float4*)(x + ((size_t)(b * L_DIM + l0 + t)) * D_MODEL + c * 4);
    }
    __syncthreads();

    /* beta: warp w handles token w; 16 head-dots each */
    {
        const int t = tid >> 5;
        const float* xr = xs + t * D_MODEL;
        for (int hb = 0; hb < N_HEADS; hb++) {
            float s = 0.f;
            const float* wb = Wbeta + hb * D_MODEL;
            for (int k = lane * 4; k < D_MODEL; k += 128) {
                float4 xv = *(const float4*)(xr + k);
                float4 wv = *(const float4*)(wb + k);
                s += xv.x * wv.x + xv.y * wv.y + xv.z * wv.z + xv.w * wv.w;
            }
#pragma unroll
            for (int o = 16; o > 0; o >>= 1) s += __shfl_down_sync(0xffffffffu, s, o);
            if (lane == 0) eta_s[t][hb] = 1.f / (1.f + __expf(-(s + bbeta[hb])));
        }
    }

    /* conv weights: 4 taps for each of this thread's 4 channels */
    float4 cwk[4], cwq[4], cwv[4];
#pragma unroll
    for (int c = 0; c < 4; c++) {
        cwk[c] = ((const float4*)ck)[d + c];
        cwq[c] = ((const float4*)cq)[d + c];
        cwv[c] = ((const float4*)cv)[d + c];
    }

    /* sliding window: slot j holds row (l0 + t - 3 + j) at token t via (t+j)&3 */
    float4 wk[4], wq[4], wv[4];
#pragma unroll
    for (int j = 0; j < 3; j++) {
        int ls = l0 - 3 + j;
        if (ls >= 0) {
            size_t base = ((size_t)(b * L_DIM + ls)) * D_MODEL + d;
            wk[j] = *(const float4*)&g_kpre[base];
            wq[j] = *(const float4*)&g_qpre[base];
            wv[j] = *(const float4*)&g_vpre[base];
        } else {
            wk[j] = wq[j] = wv[j] = make_float4(0.f, 0.f, 0.f, 0.f);
        }
    }
    __syncthreads();   /* eta ready */

#pragma unroll
    for (int t = 0; t < 8; t++) {
        {
            size_t base = ((size_t)(b * L_DIM + l0 + t)) * D_MODEL + d;
            wk[(t + 3) & 3] = *(const float4*)&g_kpre[base];
            wq[(t + 3) & 3] = *(const float4*)&g_qpre[base];
            wv[(t + 3) & 3] = *(const float4*)&g_vpre[base];
        }
        float ak[4] = {0.f, 0.f, 0.f, 0.f};
        float aq[4] = {0.f, 0.f, 0.f, 0.f};
        float av[4] = {0.f, 0.f, 0.f, 0.f};
#pragma unroll
        for (int j = 0; j < 4; j++) {
            const int sl = (t + j) & 3;
            const float* kj = (const float*)&wk[sl];
            const float* qj = (const float*)&wq[sl];
            const float* vj = (const float*)&wv[sl];
#pragma unroll
            for (int c = 0; c < 4; c++) {
                ak[c] += kj[c] * ((const float*)&cwk[c])[j];
                aq[c] += qj[c] * ((const float*)&cwq[c])[j];
                av[c] += vj[c] * ((const float*)&cwv[c])[j];
            }
        }
        /* per-head L2 norms: reduce over the 16-thread head group */
        float sk = ak[0] * ak[0] + ak[1] * ak[1] + ak[2] * ak[2] + ak[3] * ak[3];
        float sq = aq[0] * aq[0] + aq[1] * aq[1] + aq[2] * aq[2] + aq[3] * aq[3];
#pragma unroll
        for (int o = 8; o > 0; o >>= 1) {
            sk += __shfl_xor_sync(0xffffffffu, sk, o);
            sq += __shfl_xor_sync(0xffffffffu, sq, o);
        }
        const float rkn = 1.f / (sqrtf(sk) + 1e-6f);
        const float rqn = 1.f / (sqrtf(sq) + 1e-6f);
        const float e = eta_s[t][h];

        float4 knv, qnv, vsv, bbv;
#pragma unroll
        for (int c = 0; c < 4; c++) {
            float kn = ak[c] * rkn;
            float qn = aq[c] * rqn;
            float vv = av[c];
            float sv = vv / (1.f + __expf(-vv));
            ((float*)&knv)[c] = kn;
            ((float*)&qnv)[c] = qn;
            ((float*)&vsv)[c] = e * sv;
            ((float*)&bbv)[c] = e * kn;
        }
        size_t obase = (((size_t)(b * N_HEADS + h)) * L_DIM + l0 + t) * D_HEAD + (d & 63);
        *(float4*)&g_kn[obase] = knv;
        *(float4*)&g_qn[obase] = qnv;
        *(float4*)&g_vs[obase] = vsv;
        *(float4*)&g_bb[obase] = bbv;
    }
}

/* ---------------- chunked o2b weighted delta-rule scan (round-7 version) ---- */
#define SMEM_FLOATS (4 * 64 * FS + 3 * 64 * HSX + 512 + 256)

__global__ __launch_bounds__(256) void delta_kernel()
{
    extern __shared__ float smd[];
    float* Ks   = smd;
    float* Qs   = Ks + 64 * FS;
    float* Bss  = Qs + 64 * FS;
    float* Ts   = Bss + 64 * FS;
    float* Wt   = Ts + 64 * FS;
    float* Wa   = Wt + 64 * HSX;
    float* Us   = Wa + 64 * HSX;
    float* invD = Us + 64 * HSX;
    float* Mb   = invD + 512;

    const int tid = threadIdx.x;
    const int tx = tid & 15;
    const int ty = tid >> 4;
    const int pair = blockIdx.x >> 1;
    const int half = blockIdx.x & 1;
    const int col0 = half * 32;
    const int b = pair >> 4, h = pair & 15;

    for (int i = tid; i < 64 * HSX; i += 256) { Wt[i] = 0.f; Wa[i] = 0.f; }

    const size_t pbase = (size_t)pair * L_DIM * D_HEAD;

    for (int chunk = 0; chunk < N_CHUNK; chunk++) {
        __syncthreads();
        const size_t cb = pbase + (size_t)chunk * 64 * D_HEAD;
        for (int i2 = tid; i2 < 4096; i2 += 256) {
            int s = (i2 >> 6) * FS + (i2 & 63);
            Ks[s]  = g_kn[cb + i2];
            Qs[s]  = g_qn[cb + i2];
            Bss[s] = g_bb[cb + i2];
        }
        for (int i2 = tid; i2 < 2048; i2 += 256) {
            int r = i2 >> 5, c = i2 & 31;
            Us[r * HSX + c] = g_vs[cb + r * 64 + col0 + c];
        }
        __syncthreads();

        const float ts    = (float)(chunk * 64);
        const float tri0  = 0.5f * (1.f + ts) * ts;
        const float denw  = 0.5f * (65.f + ts) * (64.f + ts);
        const float Ssum  = 64.f * ts + 2080.f;
        const float coef1 = (ts / (ts + 64.f)) * ((1.f + ts) / (ts + 65.f));
        const float coef2 = (64.f / (ts + 64.f)) * ((2.f * ts + 65.f) / (ts + 65.f));

        /* A: T = strict_tril(B @ K^T) */
        {
            float acc[4][4] = {};
            for (int k = 0; k < 64; k++) {
                float a0[4], b0[4];
#pragma unroll
                for (int i = 0; i < 4; i++) a0[i] = Bss[(4 * ty + i) * FS + k];
#pragma unroll
                for (int j = 0; j < 4; j++) b0[j] = Ks[(4 * tx + j) * FS + k];
#pragma unroll
                for (int i = 0; i < 4; i++)
#pragma unroll
                    for (int j = 0; j < 4; j++) acc[i][j] += a0[i] * b0[j];
            }
#pragma unroll
            for (int i = 0; i < 4; i++)
#pragma unroll
                for (int j = 0; j < 4; j++) {
                    int r = 4 * ty + i, c = 4 * tx + j;
                    Ts[r * FS + c] = (r > c) ? acc[i][j] : 0.f;
                }
        }
        __syncthreads();

        /* C0: invert the 8 unit-lower 8x8 diagonal blocks */
        if (tid < 64) {
            const int blk = tid >> 3, c = tid & 7;
            const int r0 = blk * 8;
            float xcol[8];
#pragma unroll
            for (int r = 0; r < 8; r++) {
                float s = (r == c) ? 1.f : 0.f;
                for (int k2 = c; k2 < r; k2++)
                    s -= Ts[(r0 + r) * FS + r0 + k2] * xcol[k2];
                xcol[r] = s;
            }
#pragma unroll
            for (int r = 0; r < 8; r++) invD[(r0 + r) * 8 + c] = xcol[r];
        }

        /* B: RHS = V - B @ W_t */
        {
            float acc[4][2] = {};
            for (int k = 0; k < 64; k++) {
                float a0[4], w0[2];
#pragma unroll
                for (int i = 0; i < 4; i++) a0[i] = Bss[(4 * ty + i) * FS + k];
#pragma unroll
                for (int j = 0; j < 2; j++) w0[j] = Wt[k * HSX + 2 * tx + j];
#pragma unroll
                for (int i = 0; i < 4; i++)
#pragma unroll
                    for (int j = 0; j < 2; j++) acc[i][j] += a0[i] * w0[j];
            }
#pragma unroll
            for (int i = 0; i < 4; i++)
#pragma unroll
                for (int j = 0; j < 2; j++)
                    Us[(4 * ty + i) * HSX + 2 * tx + j] -= acc[i][j];
        }
        __syncthreads();

        /* C: blocked forward substitution */
        {
            const int cc = tid & 31, rr = tid >> 5;
            for (int ib = 0; ib < 8; ib++) {
                const int r0 = ib * 8;
                float s = 0.f;
                for (int j = 0; j < r0; j++)
                    s += Ts[(r0 + rr) * FS + j] * Us[j * HSX + cc];
                float rhs = Us[(r0 + rr) * HSX + cc] - s;
                Mb[rr * 32 + cc] = rhs;
                __syncthreads();
                s = rhs;
                for (int k2 = 0; k2 < rr; k2++)
                    s += invD[(r0 + rr) * 8 + k2] * Mb[k2 * 32 + cc];
                Us[(r0 + rr) * HSX + cc] = s;
                __syncthreads();
            }
        }

        float csr[4], rdiv[4], arr[4];
#pragma unroll
        for (int i = 0; i < 4; i++) {
            float rr2 = (float)(4 * ty + i);
            float cs = (rr2 + 1.f) * ts + 0.5f * (rr2 + 1.f) * (rr2 + 2.f);
            csr[i]  = cs;
            rdiv[i] = 1.f / (tri0 + cs);
            arr[i]  = tri0 * rdiv[i];
        }

        /* D: O = (Q @ W_avg)*a + (Q @ W_t)*(1-a) */
        float o[4][2];
        {
            float acc1[4][2] = {}, acc2[4][2] = {};
            for (int k = 0; k < 64; k++) {
                float q0[4], wa0[2], wt0[2];
#pragma unroll
                for (int i = 0; i < 4; i++) q0[i] = Qs[(4 * ty + i) * FS + k];
#pragma unroll
                for (int j = 0; j < 2; j++) {
                    wa0[j] = Wa[k * HSX + 2 * tx + j];
                    wt0[j] = Wt[k * HSX + 2 * tx + j];
                }
#pragma unroll
                for (int i = 0; i < 4; i++)
#pragma unroll
                    for (int j = 0; j < 2; j++) {
                        acc1[i][j] += q0[i] * wa0[j];
                        acc2[i][j] += q0[i] * wt0[j];
                    }
            }
#pragma unroll
            for (int i = 0; i < 4; i++)
#pragma unroll
                for (int j = 0; j < 2; j++)
                    o[i][j] = acc1[i][j] * arr[i] + acc2[i][j] * (1.f - arr[i]);
        }

        /* E: QK = Q @ K^T (into Ts) */
        {
            float acc[4][4] = {};
            for (int k = 0; k < 64; k++) {
                float q0[4], k0[4];
#pragma unroll
                for (int i = 0; i < 4; i++) q0[i] = Qs[(4 * ty + i) * FS + k];
#pragma unroll
                for (int j = 0; j < 4; j++) k0[j] = Ks[(4 * tx + j) * FS + k];
#pragma unroll
                for (int i = 0; i < 4; i++)
#pragma unroll
                    for (int j = 0; j < 4; j++) acc[i][j] += q0[i] * k0[j];
            }
#pragma unroll
            for (int i = 0; i < 4; i++)
#pragma unroll
                for (int j = 0; j < 4; j++)
                    Ts[(4 * ty + i) * FS + 4 * tx + j] = acc[i][j];
        }
        __syncthreads();

        /* F: O += (T_mat o QK) @ U */
        {
            for (int kp = 0; kp < 64; kp++) {
                float kf = (float)kp;
                float csk_m = kf * ts + 0.5f * kf * (kf + 1.f);
                float u0[2];
#pragma unroll
                for (int j = 0; j < 2; j++) u0[j] = Us[kp * HSX + 2 * tx + j];
#pragma unroll
                for (int i = 0; i < 4; i++) {
                    float num  = csr[i] - csk_m;
                    float sfac = (num >= 0.f) ? num * rdiv[i] : 0.f;
                    float sv   = sfac * Ts[(4 * ty + i) * FS + kp];
#pragma unroll
                    for (int j = 0; j < 2; j++) o[i][j] += sv * u0[j];
                }
            }
        }

        /* G: write raw O (RMS deferred) */
        {
            const int cidx = h * 64 + col0 + 2 * tx;
#pragma unroll
            for (int i = 0; i < 4; i++) {
                int l = chunk * 64 + 4 * ty + i;
                *(float2*)&g_o[((size_t)(b * L_DIM + l)) * D_MODEL + cidx] =
                    make_float2(o[i][0], o[i][1]);
            }
        }

        /* H: W updates */
        {
            float p1[4][2] = {}, p2[4][2] = {};
            for (int r = 0; r < 64; r++) {
                float rr2  = (float)r;
                float idxr = ts + rr2 + 1.f;
                float csrr = (rr2 + 1.f) * ts + 0.5f * (rr2 + 1.f) * (rr2 + 2.f);
                float wr   = (idxr + Ssum - csrr) / denw;
                float kv[4], uv[2];
#pragma unroll
                for (int i = 0; i < 4; i++) kv[i] = Ks[r * FS + 4 * ty + i];
#pragma unroll
                for (int j = 0; j < 2; j++) uv[j] = Us[r * HSX + 2 * tx + j];
#pragma unroll
                for (int i = 0; i < 4; i++)
#pragma unroll
                    for (int j = 0; j < 2; j++) {
                        p1[i][j] += kv[i] * uv[j];
                        p2[i][j] += kv[i] * uv[j] * wr;
                    }
            }
#pragma unroll
            for (int i = 0; i < 4; i++)
#pragma unroll
                for (int j = 0; j < 2; j++) {
                    int idx2 = (4 * ty + i) * HSX + 2 * tx + j;
                    float wold = Wt[idx2], waold = Wa[idx2];
                    Wa[idx2] = coef1 * waold + coef2 * wold + p2[i][j];
                    Wt[idx2] = wold + p1[i][j];
                }
        }
    }
}

/* -------- RMS norm over head dim + fp16 hi/lo split for final GEMM ---------- */
__global__ __launch_bounds__(256) void rms_split(const float* __restrict__ rms_w)
{
    const int bl = blockIdx.x, tid = threadIdx.x;
    float4 v = ((const float4*)g_o)[(size_t)bl * 256 + tid];
    float ss = v.x * v.x + v.y * v.y + v.z * v.z + v.w * v.w;
#pragma unroll
    for (int o = 8; o > 0; o >>= 1) ss += __shfl_xor_sync(0xffffffffu, ss, o);
    float scale = rsqrtf(ss * (1.f / 64.f) + 1e-6f);
    float4 rw = ((const float4*)rms_w)[tid & 15];
    float a0 = v.x * scale * rw.x, a1 = v.y * scale * rw.y;
    float a2 = v.z * scale * rw.z, a3 = v.w * scale * rw.w;
    __half2 h01 = __floats2half2_rn(a0, a1);
    __half2 h23 = __floats2half2_rn(a2, a3);
    __half2 l01 = __floats2half2_rn(a0 - __low2float(h01), a1 - __high2float(h01));
    __half2 l23 = __floats2half2_rn(a2 - __low2float(h23), a3 - __high2float(h23));
    ((uint2*)g_oh)[(size_t)bl * 256 + tid] = make_uint2(*(uint32_t*)&h01, *(uint32_t*)&h23);
    ((uint2*)g_ol)[(size_t)bl * 256 + tid] = make_uint2(*(uint32_t*)&l01, *(uint32_t*)&l23);
}

/* ------------------------------- launcher ----------------------------------*/
extern "C" void kernel_launch(void* const* d_in, const int* in_sizes, int n_in,
                              void* d_out, int out_size)
{
    (void)in_sizes; (void)n_in; (void)out_size;
    const float* x     = (const float*)d_in[0];
    const float* Wk    = (const float*)d_in[1];
    const float* bk    = (const float*)d_in[2];
    const float* Wq    = (const float*)d_in[3];
    const float* bq    = (const float*)d_in[4];
    const float* Wv    = (const float*)d_in[5];
    const float* bv    = (const float*)d_in[6];
    const float* Wbeta = (const float*)d_in[7];
    const float* bbeta = (const float*)d_in[8];
    const float* ck    = (const float*)d_in[9];
    const float* cq    = (const float*)d_in[10];
    const float* cv    = (const float*)d_in[11];
    const float* rms_w = (const float*)d_in[12];
    const float* Wout  = (const float*)d_in[13];
    const float* bout  = (const float*)d_in[14];
    float* out = (float*)d_out;

    float *kpre, *qpre, *vpre;
    __half *xh, *xl, *oh, *ol, *wsh, *wsl;
    cudaGetSymbolAddress((void**)&kpre, g_kpre);
    cudaGetSymbolAddress((void**)&qpre, g_qpre);
    cudaGetSymbolAddress((void**)&vpre, g_vpre);
    cudaGetSymbolAddress((void**)&xh, g_xh);
    cudaGetSymbolAddress((void**)&xl, g_xl);
    cudaGetSymbolAddress((void**)&oh, g_oh);
    cudaGetSymbolAddress((void**)&ol, g_ol);
    cudaGetSymbolAddress((void**)&wsh, g_wsh);
    cudaGetSymbolAddress((void**)&wsl, g_wsl);

    split_f2h<<<(ML * D_MODEL / 4 + 255) / 256, 256>>>(
        (const float4*)x, (uint2*)xh, (uint2*)xl, ML * D_MODEL / 4);
    split_w4<<<(4 * DD / 4) / 256, 256>>>(
        (const float4*)Wk, (const float4*)Wq, (const float4*)Wv,
        (const float4*)Wout, (uint2*)wsh, (uint2*)wsl);

    cudaFuncSetAttribute(gemm_qkv2, cudaFuncAttributeMaxDynamicSharedMemorySize,
                         QSM_BYTES);
    cudaFuncSetAttribute(gemm_h3b, cudaFuncAttributeMaxDynamicSharedMemorySize,
                         GSM_BYTES);

    gemm_qkv2<<<dim3(48, 64), 256, QSM_BYTES>>>(
        xh, wsh, wsl, bk, bq, bv, kpre, qpre, vpre, ML, D_MODEL);

    prep8<<<B_DIM * (L_DIM / 8), 256>>>(x, Wbeta, bbeta, ck, cq, cv);

    size_t smem_bytes = SMEM_FLOATS * sizeof(float);
    cudaFuncSetAttribute(delta_kernel, cudaFuncAttributeMaxDynamicSharedMemorySize,
                         (int)smem_bytes);
    delta_kernel<<<2 * N_PAIR, 256, smem_bytes>>>();

    rms_split<<<ML, 256>>>(rms_w);

    gemm_h3b<<<dim3(16, 64), 256, GSM_BYTES>>>(
        oh, ol, wsh + 3 * DD, wsl + 3 * DD, bout, out, ML, D_MODEL, D_MODEL);
}

// round 11
// speedup vs baseline: 1.2374x; 1.0484x over previous
#include <cuda_runtime.h>
#include <cuda_fp16.h>
#include <math.h>
#include <stdint.h>

#define B_DIM   4
#define L_DIM   2048
#define D_MODEL 1024
#define N_HEADS 16
#define D_HEAD  64
#define ML      (B_DIM * L_DIM)
#define N_PAIR  (B_DIM * N_HEADS)
#define N_CHUNK (L_DIM / 64)
#define DD      (D_MODEL * D_MODEL)
#define FS      65                       /* full fp32 smem stride */
#define HSX     33                       /* half-width fp32 smem stride */
#define HX      72                       /* fp16 tile stride (halves) */

/* ---------------- scratch (device globals; no runtime alloc) ---------------- */
__device__ float  g_kpre[ML * D_MODEL];
__device__ float  g_qpre[ML * D_MODEL];
__device__ float  g_vpre[ML * D_MODEL];
__device__ float  g_kn  [ML * D_MODEL];
__device__ float  g_qn  [ML * D_MODEL];
__device__ float  g_vs  [ML * D_MODEL];
__device__ float  g_bb  [ML * D_MODEL];
__device__ float  g_o   [ML * D_MODEL];
__device__ __half g_xh  [ML * D_MODEL];
__device__ __half g_xl  [ML * D_MODEL];
__device__ __half g_oh  [ML * D_MODEL];
__device__ __half g_ol  [ML * D_MODEL];
__device__ __half g_wsh [4 * DD];
__device__ __half g_wsl [4 * DD];

/* ---------------- fp32 -> (hi,lo) fp16 split, vectorized -------------------- */
__device__ __forceinline__ void split4(float4 v, uint2& hi, uint2& lo) {
    __half2 h01 = __floats2half2_rn(v.x, v.y);
    __half2 h23 = __floats2half2_rn(v.z, v.w);
    __half2 l01 = __floats2half2_rn(v.x - __low2float(h01), v.y - __high2float(h01));
    __half2 l23 = __floats2half2_rn(v.z - __low2float(h23), v.w - __high2float(h23));
    hi = make_uint2(*(uint32_t*)&h01, *(uint32_t*)&h23);
    lo = make_uint2(*(uint32_t*)&l01, *(uint32_t*)&l23);
}

__global__ __launch_bounds__(256) void split_f2h(
    const float4* __restrict__ src, uint2* __restrict__ hi,
    uint2* __restrict__ lo, int n4)
{
    int i = blockIdx.x * blockDim.x + threadIdx.x;
    if (i >= n4) return;
    uint2 h, l;
    split4(src[i], h, l);
    hi[i] = h; lo[i] = l;
}

__global__ __launch_bounds__(256) void split_w4(
    const float4* __restrict__ w0, const float4* __restrict__ w1,
    const float4* __restrict__ w2, const float4* __restrict__ w3,
    uint2* __restrict__ hi, uint2* __restrict__ lo)
{
    int i = blockIdx.x * blockDim.x + threadIdx.x;
    int seg = i >> 18;                               /* DD/4 = 2^18 */
    int off = i & ((DD / 4) - 1);
    const float4* src = (seg == 0) ? w0 : (seg == 1) ? w1 : (seg == 2) ? w2 : w3;
    uint2 h, l;
    split4(src[off], h, l);
    hi[i] = h; lo[i] = l;
}

/* =================== tensor-core GEMM machinery (FP16 splits) =============== */
#define HS      40

__device__ __forceinline__ uint32_t smem_u32(const void* p) {
    uint32_t a;
    asm("{ .reg .u64 t; cvta.to.shared.u64 t, %1; cvt.u32.u64 %0, t; }"
        : "=r"(a) : "l"(p));
    return a;
}

#define LDSM_X4(r, a)                                                         \
    asm volatile("ldmatrix.sync.aligned.m8n8.x4.shared.b16 "                  \
                 "{%0,%1,%2,%3}, [%4];"                                       \
                 : "=r"((r)[0]), "=r"((r)[1]), "=r"((r)[2]), "=r"((r)[3])     \
                 : "r"(a))

#define MMA_F16B(d, a, b0, b1)                                                \
    asm volatile(                                                             \
        "mma.sync.aligned.m16n8k16.row.col.f32.f16.f16.f32 "                  \
        "{%0,%1,%2,%3}, {%4,%5,%6,%7}, {%8,%9}, {%0,%1,%2,%3};"               \
        : "+f"(d[0]), "+f"(d[1]), "+f"(d[2]), "+f"(d[3])                      \
        : "r"(a[0]), "r"(a[1]), "r"(a[2]), "r"(a[3]), "r"(b0), "r"(b1))

#define CP_ASYNC16(sa, gp)                                                    \
    asm volatile("cp.async.cg.shared.global [%0], [%1], 16;"                  \
                 :: "r"(sa), "l"(gp))

/* ---------- 2-pass QKV GEMM, 3-stage pipeline ------------------------------ */
#define QS_AH   0
#define QS_BH   10240
#define QS_BL   15360
#define QSTG    20480
#define QSM_BYTES (3 * QSTG)

__global__ __launch_bounds__(256, 3) void gemm_qkv2(
    const __half* __restrict__ Ahg,
    const __half* __restrict__ Bhg, const __half* __restrict__ Blg,
    const float* __restrict__ bk, const float* __restrict__ bq,
    const float* __restrict__ bv,
    float* __restrict__ Yk, float* __restrict__ Yq, float* __restrict__ Yv,
    int M, int K)
{
    extern __shared__ char smg[];
    const uint32_t sbase = smem_u32(smg);

    const int tid = threadIdx.x;
    const int bm = blockIdx.y * 128;
    const int bnG = blockIdx.x * 64;
    const int seg = bnG >> 10;
    const int bnL = bnG & 1023;
    const float* bias = (seg == 0) ? bk : (seg == 1) ? bq : bv;
    float* Y = (seg == 0) ? Yk : (seg == 1) ? Yq : Yv;

    const int lane = tid & 31, w = tid >> 5;
    const int wm = (w >> 1) * 32, wn = (w & 1) * 32;
    const int g = lane >> 2, tg = lane & 3;
    const int arow = (lane & 7) + ((lane >> 3) & 1) * 8;
    const int acol = (lane >> 4) * 8;
    const int brow = ((lane >> 4) & 1) * 8 + (lane & 7);
    const int bcol = ((lane >> 3) & 1) * 8;
    const int r4 = tid >> 2, c4 = tid & 3;
    const uint32_t so = r4 * 80 + c4 * 16;

    float acc[2][4][4];
#pragma unroll
    for (int mt = 0; mt < 2; mt++)
#pragma unroll
        for (int nt = 0; nt < 4; nt++)
#pragma unroll
            for (int e = 0; e < 4; e++) acc[mt][nt][e] = 0.f;

    const int n_tiles = K >> 5;

#define QLOAD(t) do {                                                         \
        const uint32_t _sb = sbase + ((t) % 3) * QSTG;                        \
        const int _kb = (t) << 5;                                             \
        const size_t _ga0 = (size_t)(bm + r4) * K + _kb + c4 * 8;             \
        const size_t _ga1 = (size_t)(bm + 64 + r4) * K + _kb + c4 * 8;        \
        const size_t _gb0 = (size_t)(bnG + r4) * K + _kb + c4 * 8;            \
        CP_ASYNC16(_sb + QS_AH + so,        Ahg + _ga0);                      \
        CP_ASYNC16(_sb + QS_AH + so + 5120, Ahg + _ga1);                      \
        CP_ASYNC16(_sb + QS_BH + so,        Bhg + _gb0);                      \
        CP_ASYNC16(_sb + QS_BL + so,        Blg + _gb0);                      \
        asm volatile("cp.async.commit_group;");                               \
    } while (0)

    QLOAD(0);
    QLOAD(1);
    for (int t = 0; t < n_tiles; t++) {
        if (t + 2 < n_tiles) {
            QLOAD(t + 2);
            asm volatile("cp.async.wait_group 2;");
        } else if (t + 1 < n_tiles) {
            asm volatile("cp.async.wait_group 1;");
        } else {
            asm volatile("cp.async.wait_group 0;");
        }
        __syncthreads();

        const uint32_t sb = sbase + (t % 3) * QSTG;
#pragma unroll
        for (int kk = 0; kk < 2; kk++) {
            const int kc = kk * 16;
            uint32_t ah[2][4], bh[2][4], bl[2][4];
#pragma unroll
            for (int mt = 0; mt < 2; mt++) {
                uint32_t ad = sb + QS_AH +
                              ((wm + mt * 16 + arow) * HS + kc + acol) * 2;
                LDSM_X4(ah[mt], ad);
            }
#pragma unroll
            for (int a2 = 0; a2 < 2; a2++) {
                uint32_t bd = sb + QS_BH +
                              ((wn + a2 * 16 + brow) * HS + kc + bcol) * 2;
                LDSM_X4(bh[a2], bd);
                LDSM_X4(bl[a2], bd + (QS_BL - QS_BH));
            }
#pragma unroll
            for (int mt = 0; mt < 2; mt++)
#pragma unroll
                for (int nt = 0; nt < 4; nt++) {
                    const int hi2 = nt >> 1, p = (nt & 1) * 2;
                    MMA_F16B(acc[mt][nt], ah[mt], bh[hi2][p], bh[hi2][p + 1]);
                    MMA_F16B(acc[mt][nt], ah[mt], bl[hi2][p], bl[hi2][p + 1]);
                }
        }
        __syncthreads();
    }
#undef QLOAD

#pragma unroll
    for (int mt = 0; mt < 2; mt++) {
        const int row = bm + wm + mt * 16 + g;
#pragma unroll
        for (int nt = 0; nt < 4; nt++) {
            const int col = bnL + wn + nt * 8 + tg * 2;
            const float b0 = bias[col], b1 = bias[col + 1];
            float2 v0 = make_float2(acc[mt][nt][0] + b0, acc[mt][nt][1] + b1);
            float2 v1 = make_float2(acc[mt][nt][2] + b0, acc[mt][nt][3] + b1);
            *(float2*)(Y + (size_t)row * D_MODEL + col) = v0;
            *(float2*)(Y + (size_t)(row + 8) * D_MODEL + col) = v1;
        }
    }
}

/* ---------- 3-pass final GEMM: Y = (Ah+Al)@(Bh+Bl)^T + bias ----------------- */
#define STG_B   30720
#define AH_OFF  0
#define AL_OFF  10240
#define BH_OFF  20480
#define BL_OFF  25600
#define GSM_BYTES (2 * STG_B)

__global__ __launch_bounds__(256, 3) void gemm_h3b(
    const __half* __restrict__ Ahg, const __half* __restrict__ Alg,
    const __half* __restrict__ Bhg, const __half* __restrict__ Blg,
    const float* __restrict__ bias, float* __restrict__ Y,
    int M, int N, int K)
{
    extern __shared__ char smg[];
    const uint32_t sbase = smem_u32(smg);

    const int tid = threadIdx.x;
    const int bm = blockIdx.y * 128;
    const int bnG = blockIdx.x * 64;
    const int bnL = bnG;

    const int lane = tid & 31, w = tid >> 5;
    const int wm = (w >> 1) * 32, wn = (w & 1) * 32;
    const int g = lane >> 2, tg = lane & 3;
    const int arow = (lane & 7) + ((lane >> 3) & 1) * 8;
    const int acol = (lane >> 4) * 8;
    const int brow = ((lane >> 4) & 1) * 8 + (lane & 7);
    const int bcol = ((lane >> 3) & 1) * 8;
    const int r4 = tid >> 2, c4 = tid & 3;
    const uint32_t so = r4 * 80 + c4 * 16;

    float acc[2][4][4];
#pragma unroll
    for (int mt = 0; mt < 2; mt++)
#pragma unroll
        for (int nt = 0; nt < 4; nt++)
#pragma unroll
            for (int e = 0; e < 4; e++) acc[mt][nt][e] = 0.f;

    const int n_tiles = K >> 5;

#define LOAD_TILE(t) do {                                                     \
        const uint32_t _sb = sbase + ((t) & 1) * STG_B;                       \
        const int _kb = (t) << 5;                                             \
        const size_t _ga0 = (size_t)(bm + r4) * K + _kb + c4 * 8;             \
        const size_t _ga1 = (size_t)(bm + 64 + r4) * K + _kb + c4 * 8;        \
        const size_t _gb0 = (size_t)(bnG + r4) * K + _kb + c4 * 8;            \
        CP_ASYNC16(_sb + AH_OFF + so,           Ahg + _ga0);                  \
        CP_ASYNC16(_sb + AH_OFF + so + 5120,    Ahg + _ga1);                  \
        CP_ASYNC16(_sb + AL_OFF + so,           Alg + _ga0);                  \
        CP_ASYNC16(_sb + AL_OFF + so + 5120,    Alg + _ga1);                  \
        CP_ASYNC16(_sb + BH_OFF + so,           Bhg + _gb0);                  \
        CP_ASYNC16(_sb + BL_OFF + so,           Blg + _gb0);                  \
        asm volatile("cp.async.commit_group;");                               \
    } while (0)

    LOAD_TILE(0);
    for (int t = 0; t < n_tiles; t++) {
        if (t + 1 < n_tiles) {
            LOAD_TILE(t + 1);
            asm volatile("cp.async.wait_group 1;");
        } else {
            asm volatile("cp.async.wait_group 0;");
        }
        __syncthreads();

        const uint32_t sb = sbase + (t & 1) * STG_B;
#pragma unroll
        for (int kk = 0; kk < 2; kk++) {
            const int kc = kk * 16;
            uint32_t ah[2][4], al[2][4], bh[2][4], bl[2][4];
#pragma unroll
            for (int mt = 0; mt < 2; mt++) {
                uint32_t ad = sb + AH_OFF +
                              ((wm + mt * 16 + arow) * HS + kc + acol) * 2;
                LDSM_X4(ah[mt], ad);
                LDSM_X4(al[mt], ad + (AL_OFF - AH_OFF));
            }
#pragma unroll
            for (int a2 = 0; a2 < 2; a2++) {
                uint32_t bd = sb + BH_OFF +
                              ((wn + a2 * 16 + brow) * HS + kc + bcol) * 2;
                LDSM_X4(bh[a2], bd);
                LDSM_X4(bl[a2], bd + (BL_OFF - BH_OFF));
            }
#pragma unroll
            for (int mt = 0; mt < 2; mt++)
#pragma unroll
                for (int nt = 0; nt < 4; nt++) {
                    const int hi2 = nt >> 1, p = (nt & 1) * 2;
                    MMA_F16B(acc[mt][nt], ah[mt], bh[hi2][p], bh[hi2][p + 1]);
                    MMA_F16B(acc[mt][nt], ah[mt], bl[hi2][p], bl[hi2][p + 1]);
                    MMA_F16B(acc[mt][nt], al[mt], bh[hi2][p], bh[hi2][p + 1]);
                }
        }
        __syncthreads();
    }
#undef LOAD_TILE

#pragma unroll
    for (int mt = 0; mt < 2; mt++) {
        const int row = bm + wm + mt * 16 + g;
#pragma unroll
        for (int nt = 0; nt < 4; nt++) {
            const int col = bnL + wn + nt * 8 + tg * 2;
            const float b0 = bias[col], b1 = bias[col + 1];
            float2 v0 = make_float2(acc[mt][nt][0] + b0, acc[mt][nt][1] + b1);
            float2 v1 = make_float2(acc[mt][nt][2] + b0, acc[mt][nt][3] + b1);
            *(float2*)(Y + (size_t)row * N + col) = v0;
            *(float2*)(Y + (size_t)(row + 8) * N + col) = v1;
        }
    }
}

/* -------- prep8: 512 threads, 2 channels/thread, 8 tokens/CTA --------------- */
__global__ __launch_bounds__(512, 2) void prep8(
    const float* __restrict__ x,
    const float* __restrict__ Wbeta, const float* __restrict__ bbeta,
    const float* __restrict__ ck, const float* __restrict__ cq,
    const float* __restrict__ cv)
{
    __shared__ float xs[8 * D_MODEL];
    __shared__ float eta_s[8][N_HEADS];

    const int bid = blockIdx.x;
    const int b = bid >> 8;
    const int l0 = (bid & 255) * 8;
    const int tid = threadIdx.x;
    const int d = tid * 2;                /* channels d, d+1 */
    const int h = tid >> 5;               /* warp == head group */
    const int lane = tid & 31;
    const int w = tid >> 5;

#pragma unroll
    for (int i = 0; i < 4; i++) {
        int idx = i * 512 + tid;
        int t = idx >> 8, c = idx & 255;
        ((float4*)xs)[t * 256 + c] =
            *(const float4*)(x + ((size_t)(b * L_DIM + l0 + t)) * D_MODEL + c * 4);
    }
    __syncthreads();

    /* beta: warp w -> token w>>1, heads (w&1)*8 .. +7 */
    {
        const int t = w >> 1;
        const int hb0 = (w & 1) * 8;
        const float* xr = xs + t * D_MODEL;
#pragma unroll
        for (int hh = 0; hh < 8; hh++) {
            int hb = hb0 + hh;
            float s = 0.f;
            const float* wb = Wbeta + hb * D_MODEL;
            for (int k = lane * 4; k < D_MODEL; k += 128) {
                float4 xv = *(const float4*)(xr + k);
                float4 wv = *(const float4*)(wb + k);
                s += xv.x * wv.x + xv.y * wv.y + xv.z * wv.z + xv.w * wv.w;
            }
#pragma unroll
            for (int o = 16; o > 0; o >>= 1) s += __shfl_down_sync(0xffffffffu, s, o);
            if (lane == 0) eta_s[t][hb] = 1.f / (1.f + __expf(-(s + bbeta[hb])));
        }
    }

    /* conv weights for 2 channels */
    float4 cwk[2], cwq[2], cwv[2];
#pragma unroll
    for (int c = 0; c < 2; c++) {
        cwk[c] = ((const float4*)ck)[d + c];
        cwq[c] = ((const float4*)cq)[d + c];
        cwv[c] = ((const float4*)cv)[d + c];
    }

    /* sliding window */
    float2 wk[4], wq[4], wv[4];
#pragma unroll
    for (int j = 0; j < 3; j++) {
        int ls = l0 - 3 + j;
        if (ls >= 0) {
            size_t base = ((size_t)(b * L_DIM + ls)) * D_MODEL + d;
            wk[j] = *(const float2*)&g_kpre[base];
            wq[j] = *(const float2*)&g_qpre[base];
            wv[j] = *(const float2*)&g_vpre[base];
        } else {
            wk[j] = wq[j] = wv[j] = make_float2(0.f, 0.f);
        }
    }
    __syncthreads();

#pragma unroll
    for (int t = 0; t < 8; t++) {
        {
            size_t base = ((size_t)(b * L_DIM + l0 + t)) * D_MODEL + d;
            wk[(t + 3) & 3] = *(const float2*)&g_kpre[base];
            wq[(t + 3) & 3] = *(const float2*)&g_qpre[base];
            wv[(t + 3) & 3] = *(const float2*)&g_vpre[base];
        }
        float ak0 = 0.f, ak1 = 0.f, aq0 = 0.f, aq1 = 0.f, av0 = 0.f, av1 = 0.f;
#pragma unroll
        for (int j = 0; j < 4; j++) {
            const int sl = (t + j) & 3;
            float wk0 = ((const float*)&cwk[0])[j], wk1 = ((const float*)&cwk[1])[j];
            float wq0 = ((const float*)&cwq[0])[j], wq1 = ((const float*)&cwq[1])[j];
            float wv0 = ((const float*)&cwv[0])[j], wv1 = ((const float*)&cwv[1])[j];
            ak0 += wk[sl].x * wk0; ak1 += wk[sl].y * wk1;
            aq0 += wq[sl].x * wq0; aq1 += wq[sl].y * wq1;
            av0 += wv[sl].x * wv0; av1 += wv[sl].y * wv1;
        }
        float sk = ak0 * ak0 + ak1 * ak1;
        float sq = aq0 * aq0 + aq1 * aq1;
#pragma unroll
        for (int o = 16; o > 0; o >>= 1) {
            sk += __shfl_xor_sync(0xffffffffu, sk, o);
            sq += __shfl_xor_sync(0xffffffffu, sq, o);
        }
        const float rkn = 1.f / (sqrtf(sk) + 1e-6f);
        const float rqn = 1.f / (sqrtf(sq) + 1e-6f);
        const float e = eta_s[t][h];

        float kn0 = ak0 * rkn, kn1 = ak1 * rkn;
        float qn0 = aq0 * rqn, qn1 = aq1 * rqn;
        float sv0 = av0 / (1.f + __expf(-av0));
        float sv1 = av1 / (1.f + __expf(-av1));
        size_t obase = (((size_t)(b * N_HEADS + h)) * L_DIM + l0 + t) * D_HEAD + (d & 63);
        *(float2*)&g_kn[obase] = make_float2(kn0, kn1);
        *(float2*)&g_qn[obase] = make_float2(qn0, qn1);
        *(float2*)&g_vs[obase] = make_float2(e * sv0, e * sv1);
        *(float2*)&g_bb[obase] = make_float2(e * kn0, e * kn1);
    }
}

/* ---------------- chunked o2b weighted delta-rule scan ----------------------
   column-split (2 CTAs/pair); T and QK computed together by one 128x64x64
   fp16 3-pass HMMA (warps 0-3 -> T, warps 4-7 -> QK). ----------------------- */
#define F16T    (64 * HX)                /* halves per fp16 tile */
#define SMEM_FLOATS (5 * 64 * FS + 3 * 64 * HSX + 512 + 256 + 6 * (F16T / 2))

__global__ __launch_bounds__(256) void delta_kernel()
{
    extern __shared__ float smd[];
    float* Ks   = smd;
    float* Qs   = Ks + 64 * FS;
    float* Bss  = Qs + 64 * FS;
    float* Ts   = Bss + 64 * FS;
    float* Qk   = Ts + 64 * FS;
    float* Wt   = Qk + 64 * FS;
    float* Wa   = Wt + 64 * HSX;
    float* Us   = Wa + 64 * HSX;
    float* invD = Us + 64 * HSX;          /* 512 */
    float* Mb   = invD + 512;             /* 256 */
    __half* Kh  = (__half*)(Mb + 256);
    __half* Kl  = Kh + F16T;
    __half* Bh2 = Kl + F16T;
    __half* Bl2 = Bh2 + F16T;
    __half* Qh  = Bl2 + F16T;
    __half* Ql  = Qh + F16T;

    const int tid = threadIdx.x;
    const int tx = tid & 15;
    const int ty = tid >> 4;
    const int lane = tid & 31, w = tid >> 5;
    const int g = lane >> 2, tg = lane & 3;
    const int arow = (lane & 7) + ((lane >> 3) & 1) * 8;
    const int acol = (lane >> 4) * 8;
    const int brow = ((lane >> 4) & 1) * 8 + (lane & 7);
    const int bcol = ((lane >> 3) & 1) * 8;

    const int pair = blockIdx.x >> 1;
    const int half = blockIdx.x & 1;
    const int col0 = half * 32;
    const int b = pair >> 4, h = pair & 15;

    for (int i = tid; i < 64 * HSX; i += 256) { Wt[i] = 0.f; Wa[i] = 0.f; }

    const size_t pbase = (size_t)pair * L_DIM * D_HEAD;
    const uint32_t khB = smem_u32(Kh), klB = smem_u32(Kl);

    for (int chunk = 0; chunk < N_CHUNK; chunk++) {
        __syncthreads();
        const size_t cb = pbase + (size_t)chunk * 64 * D_HEAD;
        for (int i2 = tid; i2 < 4096; i2 += 256) {
            int r = i2 >> 6, c = i2 & 63;
            float kv = g_kn[cb + i2];
            float qv = g_qn[cb + i2];
            float bv = g_bb[cb + i2];
            Ks[r * FS + c] = kv;
            Qs[r * FS + c] = qv;
            Bss[r * FS + c] = bv;
            __half hh;
            hh = __float2half_rn(kv);
            Kh[r * HX + c] = hh;
            Kl[r * HX + c] = __float2half_rn(kv - __half2float(hh));
            hh = __float2half_rn(qv);
            Qh[r * HX + c] = hh;
            Ql[r * HX + c] = __float2half_rn(qv - __half2float(hh));
            hh = __float2half_rn(bv);
            Bh2[r * HX + c] = hh;
            Bl2[r * HX + c] = __float2half_rn(bv - __half2float(hh));
        }
        for (int i2 = tid; i2 < 2048; i2 += 256) {
            int r = i2 >> 5, c = i2 & 31;
            Us[r * HSX + c] = g_vs[cb + r * 64 + col0 + c];
        }
        __syncthreads();

        const float ts    = (float)(chunk * 64);
        const float tri0  = 0.5f * (1.f + ts) * ts;
        const float denw  = 0.5f * (65.f + ts) * (64.f + ts);
        const float Ssum  = 64.f * ts + 2080.f;
        const float coef1 = (ts / (ts + 64.f)) * ((1.f + ts) / (ts + 65.f));
        const float coef2 = (64.f / (ts + 64.f)) * ((2.f * ts + 65.f) / (ts + 65.f));

        /* A+E fused: [B;Q] @ K^T via fp16 3-pass HMMA.
           warps 0-3: T rows 16w (tril mask); warps 4-7: QK rows 16(w-4). */
        {
            const uint32_t ahB = smem_u32((w < 4) ? Bh2 : Qh);
            const uint32_t alB = smem_u32((w < 4) ? Bl2 : Ql);
            const int r0 = (w & 3) * 16;
            float acc[8][4];
#pragma unroll
            for (int j = 0; j < 8; j++)
#pragma unroll
                for (int e = 0; e < 4; e++) acc[j][e] = 0.f;

#pragma unroll
            for (int ks = 0; ks < 4; ks++) {
                const int kc = ks * 16;
                uint32_t ah[4], al[4], bh[4][4], bl[4][4];
                const uint32_t aoff = ((r0 + arow) * HX + kc + acol) * 2;
                LDSM_X4(ah, ahB + aoff);
                LDSM_X4(al, alB + aoff);
#pragma unroll
                for (int nt = 0; nt < 4; nt++) {
                    const uint32_t boff = ((nt * 16 + brow) * HX + kc + bcol) * 2;
                    LDSM_X4(bh[nt], khB + boff);
                    LDSM_X4(bl[nt], klB + boff);
                }
#pragma unroll
                for (int j = 0; j < 8; j++) {
                    const int grp = j >> 1, p = (j & 1) * 2;
                    MMA_F16B(acc[j], ah, bh[grp][p], bh[grp][p + 1]);
                    MMA_F16B(acc[j], ah, bl[grp][p], bl[grp][p + 1]);
                    MMA_F16B(acc[j], al, bh[grp][p], bh[grp][p + 1]);
                }
            }
            if (w < 4) {
#pragma unroll
                for (int j = 0; j < 8; j++) {
                    const int C = j * 8 + tg * 2;
                    const int R1 = r0 + g, R2 = r0 + g + 8;
                    Ts[R1 * FS + C]     = (R1 > C)     ? acc[j][0] : 0.f;
                    Ts[R1 * FS + C + 1] = (R1 > C + 1) ? acc[j][1] : 0.f;
                    Ts[R2 * FS + C]     = (R2 > C)     ? acc[j][2] : 0.f;
                    Ts[R2 * FS + C + 1] = (R2 > C + 1) ? acc[j][3] : 0.f;
                }
            } else {
#pragma unroll
                for (int j = 0; j < 8; j++) {
                    const int C = j * 8 + tg * 2;
                    const int R1 = r0 + g, R2 = r0 + g + 8;
                    Qk[R1 * FS + C]     = acc[j][0];
                    Qk[R1 * FS + C + 1] = acc[j][1];
                    Qk[R2 * FS + C]     = acc[j][2];
                    Qk[R2 * FS + C + 1] = acc[j][3];
                }
            }
        }
        __syncthreads();

        /* C0: invert the 8 unit-lower 8x8 diagonal blocks */
        if (tid < 64) {
            const int blk = tid >> 3, c = tid & 7;
            const int r0 = blk * 8;
            float xcol[8];
#pragma unroll
            for (int r = 0; r < 8; r++) {
                float s = (r == c) ? 1.f : 0.f;
                for (int k2 = c; k2 < r; k2++)
                    s -= Ts[(r0 + r) * FS + r0 + k2] * xcol[k2];
                xcol[r] = s;
            }
#pragma unroll
            for (int r = 0; r < 8; r++) invD[(r0 + r) * 8 + c] = xcol[r];
        }

        /* B: RHS = V - B @ W_t */
        {
            float acc[4][2] = {};
            for (int k = 0; k < 64; k++) {
                float a0[4], w0[2];
#pragma unroll
                for (int i = 0; i < 4; i++) a0[i] = Bss[(4 * ty + i) * FS + k];
#pragma unroll
                for (int j = 0; j < 2; j++) w0[j] = Wt[k * HSX + 2 * tx + j];
#pragma unroll
                for (int i = 0; i < 4; i++)
#pragma unroll
                    for (int j = 0; j < 2; j++) acc[i][j] += a0[i] * w0[j];
            }
#pragma unroll
            for (int i = 0; i < 4; i++)
#pragma unroll
                for (int j = 0; j < 2; j++)
                    Us[(4 * ty + i) * HSX + 2 * tx + j] -= acc[i][j];
        }
        __syncthreads();

        /* C: blocked forward substitution */
        {
            const int cc = tid & 31, rr = tid >> 5;
            for (int ib = 0; ib < 8; ib++) {
                const int r0 = ib * 8;
                float s = 0.f;
                for (int j = 0; j < r0; j++)
                    s += Ts[(r0 + rr) * FS + j] * Us[j * HSX + cc];
                float rhs = Us[(r0 + rr) * HSX + cc] - s;
                Mb[rr * 32 + cc] = rhs;
                __syncthreads();
                s = rhs;
                for (int k2 = 0; k2 < rr; k2++)
                    s += invD[(r0 + rr) * 8 + k2] * Mb[k2 * 32 + cc];
                Us[(r0 + rr) * HSX + cc] = s;
                __syncthreads();
            }
        }

        float csr[4], rdiv[4], arr[4];
#pragma unroll
        for (int i = 0; i < 4; i++) {
            float rr2 = (float)(4 * ty + i);
            float cs = (rr2 + 1.f) * ts + 0.5f * (rr2 + 1.f) * (rr2 + 2.f);
            csr[i]  = cs;
            rdiv[i] = 1.f / (tri0 + cs);
            arr[i]  = tri0 * rdiv[i];
        }

        /* D: O = (Q @ W_avg)*a + (Q @ W_t)*(1-a) */
        float o[4][2];
        {
            float acc1[4][2] = {}, acc2[4][2] = {};
            for (int k = 0; k < 64; k++) {
                float q0[4], wa0[2], wt0[2];
#pragma unroll
                for (int i = 0; i < 4; i++) q0[i] = Qs[(4 * ty + i) * FS + k];
#pragma unroll
                for (int j = 0; j < 2; j++) {
                    wa0[j] = Wa[k * HSX + 2 * tx + j];
                    wt0[j] = Wt[k * HSX + 2 * tx + j];
                }
#pragma unroll
                for (int i = 0; i < 4; i++)
#pragma unroll
                    for (int j = 0; j < 2; j++) {
                        acc1[i][j] += q0[i] * wa0[j];
                        acc2[i][j] += q0[i] * wt0[j];
                    }
            }
#pragma unroll
            for (int i = 0; i < 4; i++)
#pragma unroll
                for (int j = 0; j < 2; j++)
                    o[i][j] = acc1[i][j] * arr[i] + acc2[i][j] * (1.f - arr[i]);
        }

        /* F: O += (T_mat o QK) @ U */
        {
            for (int kp = 0; kp < 64; kp++) {
                float kf = (float)kp;
                float csk_m = kf * ts + 0.5f * kf * (kf + 1.f);
                float u0[2];
#pragma unroll
                for (int j = 0; j < 2; j++) u0[j] = Us[kp * HSX + 2 * tx + j];
#pragma unroll
                for (int i = 0; i < 4; i++) {
                    float num  = csr[i] - csk_m;
                    float sfac = (num >= 0.f) ? num * rdiv[i] : 0.f;
                    float sv   = sfac * Qk[(4 * ty + i) * FS + kp];
#pragma unroll
                    for (int j = 0; j < 2; j++) o[i][j] += sv * u0[j];
                }
            }
        }

        /* G: write raw O (RMS deferred) */
        {
            const int cidx = h * 64 + col0 + 2 * tx;
#pragma unroll
            for (int i = 0; i < 4; i++) {
                int l = chunk * 64 + 4 * ty + i;
                *(float2*)&g_o[((size_t)(b * L_DIM + l)) * D_MODEL + cidx] =
                    make_float2(o[i][0], o[i][1]);
            }
        }
        __syncthreads();   /* all D-reads of Wt/Wa done before H writes */

        /* H: W updates */
        {
            float p1[4][2] = {}, p2[4][2] = {};
            for (int r = 0; r < 64; r++) {
                float rr2  = (float)r;
                float idxr = ts + rr2 + 1.f;
                float csrr = (rr2 + 1.f) * ts + 0.5f * (rr2 + 1.f) * (rr2 + 2.f);
                float wr   = (idxr + Ssum - csrr) / denw;
                float kv[4], uv[2];
#pragma unroll
                for (int i = 0; i < 4; i++) kv[i] = Ks[r * FS + 4 * ty + i];
#pragma unroll
                for (int j = 0; j < 2; j++) uv[j] = Us[r * HSX + 2 * tx + j];
#pragma unroll
                for (int i = 0; i < 4; i++)
#pragma unroll
                    for (int j = 0; j < 2; j++) {
                        p1[i][j] += kv[i] * uv[j];
                        p2[i][j] += kv[i] * uv[j] * wr;
                    }
            }
#pragma unroll
            for (int i = 0; i < 4; i++)
#pragma unroll
                for (int j = 0; j < 2; j++) {
                    int idx2 = (4 * ty + i) * HSX + 2 * tx + j;
                    float wold = Wt[idx2], waold = Wa[idx2];
                    Wa[idx2] = coef1 * waold + coef2 * wold + p2[i][j];
                    Wt[idx2] = wold + p1[i][j];
                }
        }
    }
}

/* -------- RMS norm over head dim + fp16 hi/lo split for final GEMM ---------- */
__global__ __launch_bounds__(256) void rms_split(const float* __restrict__ rms_w)
{
    const int bl = blockIdx.x, tid = threadIdx.x;
    float4 v = ((const float4*)g_o)[(size_t)bl * 256 + tid];
    float ss = v.x * v.x + v.y * v.y + v.z * v.z + v.w * v.w;
#pragma unroll
    for (int o = 8; o > 0; o >>= 1) ss += __shfl_xor_sync(0xffffffffu, ss, o);
    float scale = rsqrtf(ss * (1.f / 64.f) + 1e-6f);
    float4 rw = ((const float4*)rms_w)[tid & 15];
    float a0 = v.x * scale * rw.x, a1 = v.y * scale * rw.y;
    float a2 = v.z * scale * rw.z, a3 = v.w * scale * rw.w;
    __half2 h01 = __floats2half2_rn(a0, a1);
    __half2 h23 = __floats2half2_rn(a2, a3);
    __half2 l01 = __floats2half2_rn(a0 - __low2float(h01), a1 - __high2float(h01));
    __half2 l23 = __floats2half2_rn(a2 - __low2float(h23), a3 - __high2float(h23));
    ((uint2*)g_oh)[(size_t)bl * 256 + tid] = make_uint2(*(uint32_t*)&h01, *(uint32_t*)&h23);
    ((uint2*)g_ol)[(size_t)bl * 256 + tid] = make_uint2(*(uint32_t*)&l01, *(uint32_t*)&l23);
}

/* ------------------------------- launcher ----------------------------------*/
extern "C" void kernel_launch(void* const* d_in, const int* in_sizes, int n_in,
                              void* d_out, int out_size)
{
    (void)in_sizes; (void)n_in; (void)out_size;
    const float* x     = (const float*)d_in[0];
    const float* Wk    = (const float*)d_in[1];
    const float* bk    = (const float*)d_in[2];
    const float* Wq    = (const float*)d_in[3];
    const float* bq    = (const float*)d_in[4];
    const float* Wv    = (const float*)d_in[5];
    const float* bv    = (const float*)d_in[6];
    const float* Wbeta = (const float*)d_in[7];
    const float* bbeta = (const float*)d_in[8];
    const float* ck    = (const float*)d_in[9];
    const float* cq    = (const float*)d_in[10];
    const float* cv    = (const float*)d_in[11];
    const float* rms_w = (const float*)d_in[12];
    const float* Wout  = (const float*)d_in[13];
    const float* bout  = (const float*)d_in[14];
    float* out = (float*)d_out;

    float *kpre, *qpre, *vpre;
    __half *xh, *xl, *oh, *ol, *wsh, *wsl;
    cudaGetSymbolAddress((void**)&kpre, g_kpre);
    cudaGetSymbolAddress((void**)&qpre, g_qpre);
    cudaGetSymbolAddress((void**)&vpre, g_vpre);
    cudaGetSymbolAddress((void**)&xh, g_xh);
    cudaGetSymbolAddress((void**)&xl, g_xl);
    cudaGetSymbolAddress((void**)&oh, g_oh);
    cudaGetSymbolAddress((void**)&ol, g_ol);
    cudaGetSymbolAddress((void**)&wsh, g_wsh);
    cudaGetSymbolAddress((void**)&wsl, g_wsl);

    split_f2h<<<(ML * D_MODEL / 4 + 255) / 256, 256>>>(
        (const float4*)x, (uint2*)xh, (uint2*)xl, ML * D_MODEL / 4);
    split_w4<<<(4 * DD / 4) / 256, 256>>>(
        (const float4*)Wk, (const float4*)Wq, (const float4*)Wv,
        (const float4*)Wout, (uint2*)wsh, (uint2*)wsl);

    cudaFuncSetAttribute(gemm_qkv2, cudaFuncAttributeMaxDynamicSharedMemorySize,
                         QSM_BYTES);
    cudaFuncSetAttribute(gemm_h3b, cudaFuncAttributeMaxDynamicSharedMemorySize,
                         GSM_BYTES);

    gemm_qkv2<<<dim3(48, 64), 256, QSM_BYTES>>>(
        xh, wsh, wsl, bk, bq, bv, kpre, qpre, vpre, ML, D_MODEL);

    prep8<<<B_DIM * (L_DIM / 8), 512>>>(x, Wbeta, bbeta, ck, cq, cv);

    size_t smem_bytes = SMEM_FLOATS * sizeof(float);
    cudaFuncSetAttribute(delta_kernel, cudaFuncAttributeMaxDynamicSharedMemorySize,
                         (int)smem_bytes);
    delta_kernel<<<2 * N_PAIR, 256, smem_bytes>>>();

    rms_split<<<ML, 256>>>(rms_w);

    gemm_h3b<<<dim3(16, 64), 256, GSM_BYTES>>>(
        oh, ol, wsh + 3 * DD, wsl + 3 * DD, bout, out, ML, D_MODEL, D_MODEL);
}

// round 12
// speedup vs baseline: 1.2947x; 1.0463x over previous
#include <cuda_runtime.h>
#include <cuda_fp16.h>
#include <math.h>
#include <stdint.h>

#define B_DIM   4
#define L_DIM   2048
#define D_MODEL 1024
#define N_HEADS 16
#define D_HEAD  64
#define ML      (B_DIM * L_DIM)
#define N_PAIR  (B_DIM * N_HEADS)
#define N_CHUNK (L_DIM / 64)
#define DD      (D_MODEL * D_MODEL)
#define FS      65                       /* full fp32 smem stride */
#define HSX     33                       /* half-width fp32 smem stride */
#define HX      72                       /* fp16 tile stride (halves) */

/* ---------------- scratch (device globals; no runtime alloc) ---------------- */
__device__ float  g_kpre[ML * D_MODEL];
__device__ float  g_qpre[ML * D_MODEL];
__device__ float  g_vpre[ML * D_MODEL];
__device__ float  g_kn  [ML * D_MODEL];
__device__ float  g_qn  [ML * D_MODEL];
__device__ float  g_vs  [ML * D_MODEL];
__device__ float  g_bb  [ML * D_MODEL];
__device__ float  g_o   [ML * D_MODEL];
__device__ __half g_xh  [ML * D_MODEL];
__device__ __half g_oh  [ML * D_MODEL];
__device__ __half g_wsh [4 * DD];
__device__ __half g_wsl [4 * DD];

/* ---------------- fp32 -> fp16 splits, vectorized --------------------------- */
__device__ __forceinline__ void split4(float4 v, uint2& hi, uint2& lo) {
    __half2 h01 = __floats2half2_rn(v.x, v.y);
    __half2 h23 = __floats2half2_rn(v.z, v.w);
    __half2 l01 = __floats2half2_rn(v.x - __low2float(h01), v.y - __high2float(h01));
    __half2 l23 = __floats2half2_rn(v.z - __low2float(h23), v.w - __high2float(h23));
    hi = make_uint2(*(uint32_t*)&h01, *(uint32_t*)&h23);
    lo = make_uint2(*(uint32_t*)&l01, *(uint32_t*)&l23);
}

/* x: hi only (QKV 2-pass never reads A's residual) */
__global__ __launch_bounds__(256) void split_hi(
    const float4* __restrict__ src, uint2* __restrict__ hi, int n4)
{
    int i = blockIdx.x * blockDim.x + threadIdx.x;
    if (i >= n4) return;
    float4 v = src[i];
    __half2 h01 = __floats2half2_rn(v.x, v.y);
    __half2 h23 = __floats2half2_rn(v.z, v.w);
    hi[i] = make_uint2(*(uint32_t*)&h01, *(uint32_t*)&h23);
}

__global__ __launch_bounds__(256) void split_w4(
    const float4* __restrict__ w0, const float4* __restrict__ w1,
    const float4* __restrict__ w2, const float4* __restrict__ w3,
    uint2* __restrict__ hi, uint2* __restrict__ lo)
{
    int i = blockIdx.x * blockDim.x + threadIdx.x;
    int seg = i >> 18;                               /* DD/4 = 2^18 */
    int off = i & ((DD / 4) - 1);
    const float4* src = (seg == 0) ? w0 : (seg == 1) ? w1 : (seg == 2) ? w2 : w3;
    uint2 h, l;
    split4(src[off], h, l);
    hi[i] = h; lo[i] = l;
}

/* =================== tensor-core GEMM machinery (FP16) ====================== */
#define HS      40

__device__ __forceinline__ uint32_t smem_u32(const void* p) {
    uint32_t a;
    asm("{ .reg .u64 t; cvta.to.shared.u64 t, %1; cvt.u32.u64 %0, t; }"
        : "=r"(a) : "l"(p));
    return a;
}

#define LDSM_X4(r, a)                                                         \
    asm volatile("ldmatrix.sync.aligned.m8n8.x4.shared.b16 "                  \
                 "{%0,%1,%2,%3}, [%4];"                                       \
                 : "=r"((r)[0]), "=r"((r)[1]), "=r"((r)[2]), "=r"((r)[3])     \
                 : "r"(a))

#define MMA_F16B(d, a, b0, b1)                                                \
    asm volatile(                                                             \
        "mma.sync.aligned.m16n8k16.row.col.f32.f16.f16.f32 "                  \
        "{%0,%1,%2,%3}, {%4,%5,%6,%7}, {%8,%9}, {%0,%1,%2,%3};"               \
        : "+f"(d[0]), "+f"(d[1]), "+f"(d[2]), "+f"(d[3])                      \
        : "r"(a[0]), "r"(a[1]), "r"(a[2]), "r"(a[3]), "r"(b0), "r"(b1))

#define CP_ASYNC16(sa, gp)                                                    \
    asm volatile("cp.async.cg.shared.global [%0], [%1], 16;"                  \
                 :: "r"(sa), "l"(gp))

/* ---------- shared 2-pass mainloop (A hi only; B hi+lo), 3-stage pipeline --- */
#define QS_AH   0
#define QS_BH   10240
#define QS_BL   15360
#define QSTG    20480
#define QSM_BYTES (3 * QSTG)

#define GEMM2_BODY(Yptr, biasptr)                                             \
    extern __shared__ char smg[];                                             \
    const uint32_t sbase = smem_u32(smg);                                     \
    const int tid = threadIdx.x;                                              \
    const int bm = blockIdx.y * 128;                                          \
    const int lane = tid & 31, w = tid >> 5;                                  \
    const int wm = (w >> 1) * 32, wn = (w & 1) * 32;                          \
    const int g = lane >> 2, tg = lane & 3;                                   \
    const int arow = (lane & 7) + ((lane >> 3) & 1) * 8;                      \
    const int acol = (lane >> 4) * 8;                                         \
    const int brow = ((lane >> 4) & 1) * 8 + (lane & 7);                      \
    const int bcol = ((lane >> 3) & 1) * 8;                                   \
    const int r4 = tid >> 2, c4 = tid & 3;                                    \
    const uint32_t so = r4 * 80 + c4 * 16;                                    \
    float acc[2][4][4];                                                       \
    _Pragma("unroll")                                                         \
    for (int mt = 0; mt < 2; mt++)                                            \
        _Pragma("unroll")                                                     \
        for (int nt = 0; nt < 4; nt++)                                        \
            _Pragma("unroll")                                                 \
            for (int e = 0; e < 4; e++) acc[mt][nt][e] = 0.f;                 \
    const int n_tiles = K >> 5;                                               \
    QLOAD(0);                                                                 \
    QLOAD(1);                                                                 \
    for (int t = 0; t < n_tiles; t++) {                                       \
        if (t + 2 < n_tiles) {                                                \
            QLOAD(t + 2);                                                     \
            asm volatile("cp.async.wait_group 2;");                           \
        } else if (t + 1 < n_tiles) {                                         \
            asm volatile("cp.async.wait_group 1;");                           \
        } else {                                                              \
            asm volatile("cp.async.wait_group 0;");                           \
        }                                                                     \
        __syncthreads();                                                      \
        const uint32_t sb = sbase + (t % 3) * QSTG;                           \
        _Pragma("unroll")                                                     \
        for (int kk = 0; kk < 2; kk++) {                                      \
            const int kc = kk * 16;                                           \
            uint32_t ah[2][4], bh[2][4], bl[2][4];                            \
            _Pragma("unroll")                                                 \
            for (int mt = 0; mt < 2; mt++) {                                  \
                uint32_t ad = sb + QS_AH +                                    \
                              ((wm + mt * 16 + arow) * HS + kc + acol) * 2;   \
                LDSM_X4(ah[mt], ad);                                          \
            }                                                                 \
            _Pragma("unroll")                                                 \
            for (int a2 = 0; a2 < 2; a2++) {                                  \
                uint32_t bd = sb + QS_BH +                                    \
                              ((wn + a2 * 16 + brow) * HS + kc + bcol) * 2;   \
                LDSM_X4(bh[a2], bd);                                          \
                LDSM_X4(bl[a2], bd + (QS_BL - QS_BH));                        \
            }                                                                 \
            _Pragma("unroll")                                                 \
            for (int mt = 0; mt < 2; mt++)                                    \
                _Pragma("unroll")                                             \
                for (int nt = 0; nt < 4; nt++) {                              \
                    const int hi2 = nt >> 1, p = (nt & 1) * 2;                \
                    MMA_F16B(acc[mt][nt], ah[mt], bh[hi2][p], bh[hi2][p+1]);  \
                    MMA_F16B(acc[mt][nt], ah[mt], bl[hi2][p], bl[hi2][p+1]);  \
                }                                                             \
        }                                                                     \
        __syncthreads();                                                      \
    }                                                                         \
    _Pragma("unroll")                                                         \
    for (int mt = 0; mt < 2; mt++) {                                          \
        const int row = bm + wm + mt * 16 + g;                                \
        _Pragma("unroll")                                                     \
        for (int nt = 0; nt < 4; nt++) {                                      \
            const int col = bnL + wn + nt * 8 + tg * 2;                       \
            const float b0 = (biasptr)[col], b1 = (biasptr)[col + 1];         \
            float2 v0 = make_float2(acc[mt][nt][0] + b0, acc[mt][nt][1] + b1);\
            float2 v1 = make_float2(acc[mt][nt][2] + b0, acc[mt][nt][3] + b1);\
            *(float2*)((Yptr) + (size_t)row * D_MODEL + col) = v0;            \
            *(float2*)((Yptr) + (size_t)(row + 8) * D_MODEL + col) = v1;      \
        }                                                                     \
    }

#define QLOAD(t) do {                                                         \
        const uint32_t _sb = sbase + ((t) % 3) * QSTG;                        \
        const int _kb = (t) << 5;                                             \
        const size_t _ga0 = (size_t)(bm + r4) * K + _kb + c4 * 8;             \
        const size_t _ga1 = (size_t)(bm + 64 + r4) * K + _kb + c4 * 8;        \
        const size_t _gb0 = (size_t)(bnG + r4) * K + _kb + c4 * 8;            \
        CP_ASYNC16(_sb + QS_AH + so,        Ahg + _ga0);                      \
        CP_ASYNC16(_sb + QS_AH + so + 5120, Ahg + _ga1);                      \
        CP_ASYNC16(_sb + QS_BH + so,        Bhg + _gb0);                      \
        CP_ASYNC16(_sb + QS_BL + so,        Blg + _gb0);                      \
        asm volatile("cp.async.commit_group;");                               \
    } while (0)

__global__ __launch_bounds__(256, 3) void gemm_qkv2(
    const __half* __restrict__ Ahg,
    const __half* __restrict__ Bhg, const __half* __restrict__ Blg,
    const float* __restrict__ bk, const float* __restrict__ bq,
    const float* __restrict__ bv,
    float* __restrict__ Yk, float* __restrict__ Yq, float* __restrict__ Yv,
    int M, int K)
{
    const int bnG = blockIdx.x * 64;
    const int seg = bnG >> 10;
    const int bnL = bnG & 1023;
    const float* bias = (seg == 0) ? bk : (seg == 1) ? bq : bv;
    float* Y = (seg == 0) ? Yk : (seg == 1) ? Yq : Yv;
    GEMM2_BODY(Y, bias)
}

__global__ __launch_bounds__(256, 3) void gemm_h2b(
    const __half* __restrict__ Ahg,
    const __half* __restrict__ Bhg, const __half* __restrict__ Blg,
    const float* __restrict__ bias, float* __restrict__ Y,
    int M, int K)
{
    const int bnG = blockIdx.x * 64;
    const int bnL = bnG;
    GEMM2_BODY(Y, bias)
}
#undef QLOAD

/* -------- prep8: 512 threads, 2 channels/thread, 8 tokens/CTA --------------- */
__global__ __launch_bounds__(512, 2) void prep8(
    const float* __restrict__ x,
    const float* __restrict__ Wbeta, const float* __restrict__ bbeta,
    const float* __restrict__ ck, const float* __restrict__ cq,
    const float* __restrict__ cv)
{
    __shared__ float xs[8 * D_MODEL];
    __shared__ float eta_s[8][N_HEADS];

    const int bid = blockIdx.x;
    const int b = bid >> 8;
    const int l0 = (bid & 255) * 8;
    const int tid = threadIdx.x;
    const int d = tid * 2;
    const int h = tid >> 5;
    const int lane = tid & 31;
    const int w = tid >> 5;

#pragma unroll
    for (int i = 0; i < 4; i++) {
        int idx = i * 512 + tid;
        int t = idx >> 8, c = idx & 255;
        ((float4*)xs)[t * 256 + c] =
            *(const float4*)(x + ((size_t)(b * L_DIM + l0 + t)) * D_MODEL + c * 4);
    }
    __syncthreads();

    {
        const int t = w >> 1;
        const int hb0 = (w & 1) * 8;
        const float* xr = xs + t * D_MODEL;
#pragma unroll
        for (int hh = 0; hh < 8; hh++) {
            int hb = hb0 + hh;
            float s = 0.f;
            const float* wb = Wbeta + hb * D_MODEL;
            for (int k = lane * 4; k < D_MODEL; k += 128) {
                float4 xv = *(const float4*)(xr + k);
                float4 wv = *(const float4*)(wb + k);
                s += xv.x * wv.x + xv.y * wv.y + xv.z * wv.z + xv.w * wv.w;
            }
#pragma unroll
            for (int o = 16; o > 0; o >>= 1) s += __shfl_down_sync(0xffffffffu, s, o);
            if (lane == 0) eta_s[t][hb] = 1.f / (1.f + __expf(-(s + bbeta[hb])));
        }
    }

    float4 cwk[2], cwq[2], cwv[2];
#pragma unroll
    for (int c = 0; c < 2; c++) {
        cwk[c] = ((const float4*)ck)[d + c];
        cwq[c] = ((const float4*)cq)[d + c];
        cwv[c] = ((const float4*)cv)[d + c];
    }

    float2 wk[4], wq[4], wv[4];
#pragma unroll
    for (int j = 0; j < 3; j++) {
        int ls = l0 - 3 + j;
        if (ls >= 0) {
            size_t base = ((size_t)(b * L_DIM + ls)) * D_MODEL + d;
            wk[j] = *(const float2*)&g_kpre[base];
            wq[j] = *(const float2*)&g_qpre[base];
            wv[j] = *(const float2*)&g_vpre[base];
        } else {
            wk[j] = wq[j] = wv[j] = make_float2(0.f, 0.f);
        }
    }
    __syncthreads();

#pragma unroll
    for (int t = 0; t < 8; t++) {
        {
            size_t base = ((size_t)(b * L_DIM + l0 + t)) * D_MODEL + d;
            wk[(t + 3) & 3] = *(const float2*)&g_kpre[base];
            wq[(t + 3) & 3] = *(const float2*)&g_qpre[base];
            wv[(t + 3) & 3] = *(const float2*)&g_vpre[base];
        }
        float ak0 = 0.f, ak1 = 0.f, aq0 = 0.f, aq1 = 0.f, av0 = 0.f, av1 = 0.f;
#pragma unroll
        for (int j = 0; j < 4; j++) {
            const int sl = (t + j) & 3;
            float wk0 = ((const float*)&cwk[0])[j], wk1 = ((const float*)&cwk[1])[j];
            float wq0 = ((const float*)&cwq[0])[j], wq1 = ((const float*)&cwq[1])[j];
            float wv0 = ((const float*)&cwv[0])[j], wv1 = ((const float*)&cwv[1])[j];
            ak0 += wk[sl].x * wk0; ak1 += wk[sl].y * wk1;
            aq0 += wq[sl].x * wq0; aq1 += wq[sl].y * wq1;
            av0 += wv[sl].x * wv0; av1 += wv[sl].y * wv1;
        }
        float sk = ak0 * ak0 + ak1 * ak1;
        float sq = aq0 * aq0 + aq1 * aq1;
#pragma unroll
        for (int o = 16; o > 0; o >>= 1) {
            sk += __shfl_xor_sync(0xffffffffu, sk, o);
            sq += __shfl_xor_sync(0xffffffffu, sq, o);
        }
        const float rkn = 1.f / (sqrtf(sk) + 1e-6f);
        const float rqn = 1.f / (sqrtf(sq) + 1e-6f);
        const float e = eta_s[t][h];

        float kn0 = ak0 * rkn, kn1 = ak1 * rkn;
        float qn0 = aq0 * rqn, qn1 = aq1 * rqn;
        float sv0 = av0 / (1.f + __expf(-av0));
        float sv1 = av1 / (1.f + __expf(-av1));
        size_t obase = (((size_t)(b * N_HEADS + h)) * L_DIM + l0 + t) * D_HEAD + (d & 63);
        *(float2*)&g_kn[obase] = make_float2(kn0, kn1);
        *(float2*)&g_qn[obase] = make_float2(qn0, qn1);
        *(float2*)&g_vs[obase] = make_float2(e * sv0, e * sv1);
        *(float2*)&g_bb[obase] = make_float2(e * kn0, e * kn1);
    }
}

/* ---------------- chunked o2b weighted delta-rule scan (round-11 version) --- */
#define F16T    (64 * HX)
#define SMEM_FLOATS (5 * 64 * FS + 3 * 64 * HSX + 512 + 256 + 6 * (F16T / 2))

__global__ __launch_bounds__(256) void delta_kernel()
{
    extern __shared__ float smd[];
    float* Ks   = smd;
    float* Qs   = Ks + 64 * FS;
    float* Bss  = Qs + 64 * FS;
    float* Ts   = Bss + 64 * FS;
    float* Qk   = Ts + 64 * FS;
    float* Wt   = Qk + 64 * FS;
    float* Wa   = Wt + 64 * HSX;
    float* Us   = Wa + 64 * HSX;
    float* invD = Us + 64 * HSX;
    float* Mb   = invD + 512;
    __half* Kh  = (__half*)(Mb + 256);
    __half* Kl  = Kh + F16T;
    __half* Bh2 = Kl + F16T;
    __half* Bl2 = Bh2 + F16T;
    __half* Qh  = Bl2 + F16T;
    __half* Ql  = Qh + F16T;

    const int tid = threadIdx.x;
    const int tx = tid & 15;
    const int ty = tid >> 4;
    const int lane = tid & 31, w = tid >> 5;
    const int g = lane >> 2, tg = lane & 3;
    const int arow = (lane & 7) + ((lane >> 3) & 1) * 8;
    const int acol = (lane >> 4) * 8;
    const int brow = ((lane >> 4) & 1) * 8 + (lane & 7);
    const int bcol = ((lane >> 3) & 1) * 8;

    const int pair = blockIdx.x >> 1;
    const int half = blockIdx.x & 1;
    const int col0 = half * 32;
    const int b = pair >> 4, h = pair & 15;

    for (int i = tid; i < 64 * HSX; i += 256) { Wt[i] = 0.f; Wa[i] = 0.f; }

    const size_t pbase = (size_t)pair * L_DIM * D_HEAD;
    const uint32_t khB = smem_u32(Kh), klB = smem_u32(Kl);

    for (int chunk = 0; chunk < N_CHUNK; chunk++) {
        __syncthreads();
        const size_t cb = pbase + (size_t)chunk * 64 * D_HEAD;
        for (int i2 = tid; i2 < 4096; i2 += 256) {
            int r = i2 >> 6, c = i2 & 63;
            float kv = g_kn[cb + i2];
            float qv = g_qn[cb + i2];
            float bv = g_bb[cb + i2];
            Ks[r * FS + c] = kv;
            Qs[r * FS + c] = qv;
            Bss[r * FS + c] = bv;
            __half hh;
            hh = __float2half_rn(kv);
            Kh[r * HX + c] = hh;
            Kl[r * HX + c] = __float2half_rn(kv - __half2float(hh));
            hh = __float2half_rn(qv);
            Qh[r * HX + c] = hh;
            Ql[r * HX + c] = __float2half_rn(qv - __half2float(hh));
            hh = __float2half_rn(bv);
            Bh2[r * HX + c] = hh;
            Bl2[r * HX + c] = __float2half_rn(bv - __half2float(hh));
        }
        for (int i2 = tid; i2 < 2048; i2 += 256) {
            int r = i2 >> 5, c = i2 & 31;
            Us[r * HSX + c] = g_vs[cb + r * 64 + col0 + c];
        }
        __syncthreads();

        const float ts    = (float)(chunk * 64);
        const float tri0  = 0.5f * (1.f + ts) * ts;
        const float denw  = 0.5f * (65.f + ts) * (64.f + ts);
        const float Ssum  = 64.f * ts + 2080.f;
        const float coef1 = (ts / (ts + 64.f)) * ((1.f + ts) / (ts + 65.f));
        const float coef2 = (64.f / (ts + 64.f)) * ((2.f * ts + 65.f) / (ts + 65.f));

        /* A+E fused: [B;Q] @ K^T via fp16 3-pass HMMA */
        {
            const uint32_t ahB = smem_u32((w < 4) ? Bh2 : Qh);
            const uint32_t alB = smem_u32((w < 4) ? Bl2 : Ql);
            const int r0 = (w & 3) * 16;
            float acc[8][4];
#pragma unroll
            for (int j = 0; j < 8; j++)
#pragma unroll
                for (int e = 0; e < 4; e++) acc[j][e] = 0.f;

#pragma unroll
            for (int ks = 0; ks < 4; ks++) {
                const int kc = ks * 16;
                uint32_t ah[4], al[4], bh[4][4], bl[4][4];
                const uint32_t aoff = ((r0 + arow) * HX + kc + acol) * 2;
                LDSM_X4(ah, ahB + aoff);
                LDSM_X4(al, alB + aoff);
#pragma unroll
                for (int nt = 0; nt < 4; nt++) {
                    const uint32_t boff = ((nt * 16 + brow) * HX + kc + bcol) * 2;
                    LDSM_X4(bh[nt], khB + boff);
                    LDSM_X4(bl[nt], klB + boff);
                }
#pragma unroll
                for (int j = 0; j < 8; j++) {
                    const int grp = j >> 1, p = (j & 1) * 2;
                    MMA_F16B(acc[j], ah, bh[grp][p], bh[grp][p + 1]);
                    MMA_F16B(acc[j], ah, bl[grp][p], bl[grp][p + 1]);
                    MMA_F16B(acc[j], al, bh[grp][p], bh[grp][p + 1]);
                }
            }
            if (w < 4) {
#pragma unroll
                for (int j = 0; j < 8; j++) {
                    const int C = j * 8 + tg * 2;
                    const int R1 = r0 + g, R2 = r0 + g + 8;
                    Ts[R1 * FS + C]     = (R1 > C)     ? acc[j][0] : 0.f;
                    Ts[R1 * FS + C + 1] = (R1 > C + 1) ? acc[j][1] : 0.f;
                    Ts[R2 * FS + C]     = (R2 > C)     ? acc[j][2] : 0.f;
                    Ts[R2 * FS + C + 1] = (R2 > C + 1) ? acc[j][3] : 0.f;
                }
            } else {
#pragma unroll
                for (int j = 0; j < 8; j++) {
                    const int C = j * 8 + tg * 2;
                    const int R1 = r0 + g, R2 = r0 + g + 8;
                    Qk[R1 * FS + C]     = acc[j][0];
                    Qk[R1 * FS + C + 1] = acc[j][1];
                    Qk[R2 * FS + C]     = acc[j][2];
                    Qk[R2 * FS + C + 1] = acc[j][3];
                }
            }
        }
        __syncthreads();

        /* C0: invert the 8 unit-lower 8x8 diagonal blocks */
        if (tid < 64) {
            const int blk = tid >> 3, c = tid & 7;
            const int r0 = blk * 8;
            float xcol[8];
#pragma unroll
            for (int r = 0; r < 8; r++) {
                float s = (r == c) ? 1.f : 0.f;
                for (int k2 = c; k2 < r; k2++)
                    s -= Ts[(r0 + r) * FS + r0 + k2] * xcol[k2];
                xcol[r] = s;
            }
#pragma unroll
            for (int r = 0; r < 8; r++) invD[(r0 + r) * 8 + c] = xcol[r];
        }

        /* B: RHS = V - B @ W_t */
        {
            float acc[4][2] = {};
            for (int k = 0; k < 64; k++) {
                float a0[4], w0[2];
#pragma unroll
                for (int i = 0; i < 4; i++) a0[i] = Bss[(4 * ty + i) * FS + k];
#pragma unroll
                for (int j = 0; j < 2; j++) w0[j] = Wt[k * HSX + 2 * tx + j];
#pragma unroll
                for (int i = 0; i < 4; i++)
#pragma unroll
                    for (int j = 0; j < 2; j++) acc[i][j] += a0[i] * w0[j];
            }
#pragma unroll
            for (int i = 0; i < 4; i++)
#pragma unroll
                for (int j = 0; j < 2; j++)
                    Us[(4 * ty + i) * HSX + 2 * tx + j] -= acc[i][j];
        }
        __syncthreads();

        /* C: blocked forward substitution */
        {
            const int cc = tid & 31, rr = tid >> 5;
            for (int ib = 0; ib < 8; ib++) {
                const int r0 = ib * 8;
                float s = 0.f;
                for (int j = 0; j < r0; j++)
                    s += Ts[(r0 + rr) * FS + j] * Us[j * HSX + cc];
                float rhs = Us[(r0 + rr) * HSX + cc] - s;
                Mb[rr * 32 + cc] = rhs;
                __syncthreads();
                s = rhs;
                for (int k2 = 0; k2 < rr; k2++)
                    s += invD[(r0 + rr) * 8 + k2] * Mb[k2 * 32 + cc];
                Us[(r0 + rr) * HSX + cc] = s;
                __syncthreads();
            }
        }

        float csr[4], rdiv[4], arr[4];
#pragma unroll
        for (int i = 0; i < 4; i++) {
            float rr2 = (float)(4 * ty + i);
            float cs = (rr2 + 1.f) * ts + 0.5f * (rr2 + 1.f) * (rr2 + 2.f);
            csr[i]  = cs;
            rdiv[i] = 1.f / (tri0 + cs);
            arr[i]  = tri0 * rdiv[i];
        }

        /* D: O = (Q @ W_avg)*a + (Q @ W_t)*(1-a) */
        float o[4][2];
        {
            float acc1[4][2] = {}, acc2[4][2] = {};
            for (int k = 0; k < 64; k++) {
                float q0[4], wa0[2], wt0[2];
#pragma unroll
                for (int i = 0; i < 4; i++) q0[i] = Qs[(4 * ty + i) * FS + k];
#pragma unroll
                for (int j = 0; j < 2; j++) {
                    wa0[j] = Wa[k * HSX + 2 * tx + j];
                    wt0[j] = Wt[k * HSX + 2 * tx + j];
                }
#pragma unroll
                for (int i = 0; i < 4; i++)
#pragma unroll
                    for (int j = 0; j < 2; j++) {
                        acc1[i][j] += q0[i] * wa0[j];
                        acc2[i][j] += q0[i] * wt0[j];
                    }
            }
#pragma unroll
            for (int i = 0; i < 4; i++)
#pragma unroll
                for (int j = 0; j < 2; j++)
                    o[i][j] = acc1[i][j] * arr[i] + acc2[i][j] * (1.f - arr[i]);
        }

        /* F: O += (T_mat o QK) @ U */
        {
            for (int kp = 0; kp < 64; kp++) {
                float kf = (float)kp;
                float csk_m = kf * ts + 0.5f * kf * (kf + 1.f);
                float u0[2];
#pragma unroll
                for (int j = 0; j < 2; j++) u0[j] = Us[kp * HSX + 2 * tx + j];
#pragma unroll
                for (int i = 0; i < 4; i++) {
                    float num  = csr[i] - csk_m;
                    float sfac = (num >= 0.f) ? num * rdiv[i] : 0.f;
                    float sv   = sfac * Qk[(4 * ty + i) * FS + kp];
#pragma unroll
                    for (int j = 0; j < 2; j++) o[i][j] += sv * u0[j];
                }
            }
        }

        /* G: write raw O (RMS deferred) */
        {
            const int cidx = h * 64 + col0 + 2 * tx;
#pragma unroll
            for (int i = 0; i < 4; i++) {
                int l = chunk * 64 + 4 * ty + i;
                *(float2*)&g_o[((size_t)(b * L_DIM + l)) * D_MODEL + cidx] =
                    make_float2(o[i][0], o[i][1]);
            }
        }
        __syncthreads();

        /* H: W updates */
        {
            float p1[4][2] = {}, p2[4][2] = {};
            for (int r = 0; r < 64; r++) {
                float rr2  = (float)r;
                float idxr = ts + rr2 + 1.f;
                float csrr = (rr2 + 1.f) * ts + 0.5f * (rr2 + 1.f) * (rr2 + 2.f);
                float wr   = (idxr + Ssum - csrr) / denw;
                float kv[4], uv[2];
#pragma unroll
                for (int i = 0; i < 4; i++) kv[i] = Ks[r * FS + 4 * ty + i];
#pragma unroll
                for (int j = 0; j < 2; j++) uv[j] = Us[r * HSX + 2 * tx + j];
#pragma unroll
                for (int i = 0; i < 4; i++)
#pragma unroll
                    for (int j = 0; j < 2; j++) {
                        p1[i][j] += kv[i] * uv[j];
                        p2[i][j] += kv[i] * uv[j] * wr;
                    }
            }
#pragma unroll
            for (int i = 0; i < 4; i++)
#pragma unroll
                for (int j = 0; j < 2; j++) {
                    int idx2 = (4 * ty + i) * HSX + 2 * tx + j;
                    float wold = Wt[idx2], waold = Wa[idx2];
                    Wa[idx2] = coef1 * waold + coef2 * wold + p2[i][j];
                    Wt[idx2] = wold + p1[i][j];
                }
        }
    }
}

/* -------- RMS norm over head dim + fp16 (hi only) for final 2-pass GEMM ----- */
__global__ __launch_bounds__(256) void rms_split(const float* __restrict__ rms_w)
{
    const int bl = blockIdx.x, tid = threadIdx.x;
    float4 v = ((const float4*)g_o)[(size_t)bl * 256 + tid];
    float ss = v.x * v.x + v.y * v.y + v.z * v.z + v.w * v.w;
#pragma unroll
    for (int o = 8; o > 0; o >>= 1) ss += __shfl_xor_sync(0xffffffffu, ss, o);
    float scale = rsqrtf(ss * (1.f / 64.f) + 1e-6f);
    float4 rw = ((const float4*)rms_w)[tid & 15];
    float a0 = v.x * scale * rw.x, a1 = v.y * scale * rw.y;
    float a2 = v.z * scale * rw.z, a3 = v.w * scale * rw.w;
    __half2 h01 = __floats2half2_rn(a0, a1);
    __half2 h23 = __floats2half2_rn(a2, a3);
    ((uint2*)g_oh)[(size_t)bl * 256 + tid] = make_uint2(*(uint32_t*)&h01, *(uint32_t*)&h23);
}

/* ------------------------------- launcher ----------------------------------*/
extern "C" void kernel_launch(void* const* d_in, const int* in_sizes, int n_in,
                              void* d_out, int out_size)
{
    (void)in_sizes; (void)n_in; (void)out_size;
    const float* x     = (const float*)d_in[0];
    const float* Wk    = (const float*)d_in[1];
    const float* bk    = (const float*)d_in[2];
    const float* Wq    = (const float*)d_in[3];
    const float* bq    = (const float*)d_in[4];
    const float* Wv    = (const float*)d_in[5];
    const float* bv    = (const float*)d_in[6];
    const float* Wbeta = (const float*)d_in[7];
    const float* bbeta = (const float*)d_in[8];
    const float* ck    = (const float*)d_in[9];
    const float* cq    = (const float*)d_in[10];
    const float* cv    = (const float*)d_in[11];
    const float* rms_w = (const float*)d_in[12];
    const float* Wout  = (const float*)d_in[13];
    const float* bout  = (const float*)d_in[14];
    float* out = (float*)d_out;

    float *kpre, *qpre, *vpre;
    __half *xh, *oh, *wsh, *wsl;
    cudaGetSymbolAddress((void**)&kpre, g_kpre);
    cudaGetSymbolAddress((void**)&qpre, g_qpre);
    cudaGetSymbolAddress((void**)&vpre, g_vpre);
    cudaGetSymbolAddress((void**)&xh, g_xh);
    cudaGetSymbolAddress((void**)&oh, g_oh);
    cudaGetSymbolAddress((void**)&wsh, g_wsh);
    cudaGetSymbolAddress((void**)&wsl, g_wsl);

    split_hi<<<(ML * D_MODEL / 4 + 255) / 256, 256>>>(
        (const float4*)x, (uint2*)xh, ML * D_MODEL / 4);
    split_w4<<<(4 * DD / 4) / 256, 256>>>(
        (const float4*)Wk, (const float4*)Wq, (const float4*)Wv,
        (const float4*)Wout, (uint2*)wsh, (uint2*)wsl);

    cudaFuncSetAttribute(gemm_qkv2, cudaFuncAttributeMaxDynamicSharedMemorySize,
                         QSM_BYTES);
    cudaFuncSetAttribute(gemm_h2b, cudaFuncAttributeMaxDynamicSharedMemorySize,
                         QSM_BYTES);

    gemm_qkv2<<<dim3(48, 64), 256, QSM_BYTES>>>(
        xh, wsh, wsl, bk, bq, bv, kpre, qpre, vpre, ML, D_MODEL);

    prep8<<<B_DIM * (L_DIM / 8), 512>>>(x, Wbeta, bbeta, ck, cq, cv);

    size_t smem_bytes = SMEM_FLOATS * sizeof(float);
    cudaFuncSetAttribute(delta_kernel, cudaFuncAttributeMaxDynamicSharedMemorySize,
                         (int)smem_bytes);
    delta_kernel<<<2 * N_PAIR, 256, smem_bytes>>>();

    rms_split<<<ML, 256>>>(rms_w);

    gemm_h2b<<<dim3(16, 64), 256, QSM_BYTES>>>(
        oh, wsh + 3 * DD, wsl + 3 * DD, bout, out, ML, D_MODEL);
}

// round 13
// speedup vs baseline: 1.5183x; 1.1727x over previous
#include <cuda_runtime.h>
#include <cuda_fp16.h>
#include <math.h>
#include <stdint.h>

#define B_DIM   4
#define L_DIM   2048
#define D_MODEL 1024
#define N_HEADS 16
#define D_HEAD  64
#define ML      (B_DIM * L_DIM)
#define N_PAIR  (B_DIM * N_HEADS)
#define N_CHUNK (L_DIM / 64)
#define DD      (D_MODEL * D_MODEL)
#define FS      65                       /* full fp32 smem stride */
#define HSX     33                       /* half-width fp32 smem stride */
#define HX      72                       /* fp16 tile stride (halves) */
#define F16T    (64 * HX)
#define F16H    (32 * HX)

/* ---------------- scratch (device globals; no runtime alloc) ---------------- */
__device__ float  g_kpre[ML * D_MODEL];
__device__ float  g_qpre[ML * D_MODEL];
__device__ float  g_vpre[ML * D_MODEL];
__device__ float  g_kn  [ML * D_MODEL];
__device__ float  g_qn  [ML * D_MODEL];
__device__ float  g_vs  [ML * D_MODEL];
__device__ float  g_bb  [ML * D_MODEL];
__device__ float  g_o   [ML * D_MODEL];
__device__ __half g_xh  [ML * D_MODEL];
__device__ __half g_oh  [ML * D_MODEL];
__device__ __half g_wsh [4 * DD];
__device__ __half g_wsl [4 * DD];

/* ---------------- fp32 -> fp16 splits, vectorized --------------------------- */
__device__ __forceinline__ void split4(float4 v, uint2& hi, uint2& lo) {
    __half2 h01 = __floats2half2_rn(v.x, v.y);
    __half2 h23 = __floats2half2_rn(v.z, v.w);
    __half2 l01 = __floats2half2_rn(v.x - __low2float(h01), v.y - __high2float(h01));
    __half2 l23 = __floats2half2_rn(v.z - __low2float(h23), v.w - __high2float(h23));
    hi = make_uint2(*(uint32_t*)&h01, *(uint32_t*)&h23);
    lo = make_uint2(*(uint32_t*)&l01, *(uint32_t*)&l23);
}

__global__ __launch_bounds__(256) void split_hi(
    const float4* __restrict__ src, uint2* __restrict__ hi, int n4)
{
    int i = blockIdx.x * blockDim.x + threadIdx.x;
    if (i >= n4) return;
    float4 v = src[i];
    __half2 h01 = __floats2half2_rn(v.x, v.y);
    __half2 h23 = __floats2half2_rn(v.z, v.w);
    hi[i] = make_uint2(*(uint32_t*)&h01, *(uint32_t*)&h23);
}

__global__ __launch_bounds__(256) void split_w4(
    const float4* __restrict__ w0, const float4* __restrict__ w1,
    const float4* __restrict__ w2, const float4* __restrict__ w3,
    uint2* __restrict__ hi, uint2* __restrict__ lo)
{
    int i = blockIdx.x * blockDim.x + threadIdx.x;
    int seg = i >> 18;
    int off = i & ((DD / 4) - 1);
    const float4* src = (seg == 0) ? w0 : (seg == 1) ? w1 : (seg == 2) ? w2 : w3;
    uint2 h, l;
    split4(src[off], h, l);
    hi[i] = h; lo[i] = l;
}

/* =================== tensor-core GEMM machinery (FP16) ====================== */
#define HS      40

__device__ __forceinline__ uint32_t smem_u32(const void* p) {
    uint32_t a;
    asm("{ .reg .u64 t; cvta.to.shared.u64 t, %1; cvt.u32.u64 %0, t; }"
        : "=r"(a) : "l"(p));
    return a;
}

#define LDSM_X4(r, a)                                                         \
    asm volatile("ldmatrix.sync.aligned.m8n8.x4.shared.b16 "                  \
                 "{%0,%1,%2,%3}, [%4];"                                       \
                 : "=r"((r)[0]), "=r"((r)[1]), "=r"((r)[2]), "=r"((r)[3])     \
                 : "r"(a))

#define MMA_F16B(d, a, b0, b1)                                                \
    asm volatile(                                                             \
        "mma.sync.aligned.m16n8k16.row.col.f32.f16.f16.f32 "                  \
        "{%0,%1,%2,%3}, {%4,%5,%6,%7}, {%8,%9}, {%0,%1,%2,%3};"               \
        : "+f"(d[0]), "+f"(d[1]), "+f"(d[2]), "+f"(d[3])                      \
        : "r"(a[0]), "r"(a[1]), "r"(a[2]), "r"(a[3]), "r"(b0), "r"(b1))

#define CP_ASYNC16(sa, gp)                                                    \
    asm volatile("cp.async.cg.shared.global [%0], [%1], 16;"                  \
                 :: "r"(sa), "l"(gp))

/* ---------- shared 2-pass mainloop (A hi only; B hi+lo), 3-stage pipeline --- */
#define QS_AH   0
#define QS_BH   10240
#define QS_BL   15360
#define QSTG    20480
#define QSM_BYTES (3 * QSTG)

#define GEMM2_BODY(Yptr, biasptr)                                             \
    extern __shared__ char smg[];                                             \
    const uint32_t sbase = smem_u32(smg);                                     \
    const int tid = threadIdx.x;                                              \
    const int bm = blockIdx.y * 128;                                          \
    const int lane = tid & 31, w = tid >> 5;                                  \
    const int wm = (w >> 1) * 32, wn = (w & 1) * 32;                          \
    const int g = lane >> 2, tg = lane & 3;                                   \
    const int arow = (lane & 7) + ((lane >> 3) & 1) * 8;                      \
    const int acol = (lane >> 4) * 8;                                         \
    const int brow = ((lane >> 4) & 1) * 8 + (lane & 7);                      \
    const int bcol = ((lane >> 3) & 1) * 8;                                   \
    const int r4 = tid >> 2, c4 = tid & 3;                                    \
    const uint32_t so = r4 * 80 + c4 * 16;                                    \
    float acc[2][4][4];                                                       \
    _Pragma("unroll")                                                         \
    for (int mt = 0; mt < 2; mt++)                                            \
        _Pragma("unroll")                                                     \
        for (int nt = 0; nt < 4; nt++)                                        \
            _Pragma("unroll")                                                 \
            for (int e = 0; e < 4; e++) acc[mt][nt][e] = 0.f;                 \
    const int n_tiles = K >> 5;                                               \
    QLOAD(0);                                                                 \
    QLOAD(1);                                                                 \
    for (int t = 0; t < n_tiles; t++) {                                       \
        if (t + 2 < n_tiles) {                                                \
            QLOAD(t + 2);                                                     \
            asm volatile("cp.async.wait_group 2;");                           \
        } else if (t + 1 < n_tiles) {                                         \
            asm volatile("cp.async.wait_group 1;");                           \
        } else {                                                              \
            asm volatile("cp.async.wait_group 0;");                           \
        }                                                                     \
        __syncthreads();                                                      \
        const uint32_t sb = sbase + (t % 3) * QSTG;                           \
        _Pragma("unroll")                                                     \
        for (int kk = 0; kk < 2; kk++) {                                      \
            const int kc = kk * 16;                                           \
            uint32_t ah[2][4], bh[2][4], bl[2][4];                            \
            _Pragma("unroll")                                                 \
            for (int mt = 0; mt < 2; mt++) {                                  \
                uint32_t ad = sb + QS_AH +                                    \
                              ((wm + mt * 16 + arow) * HS + kc + acol) * 2;   \
                LDSM_X4(ah[mt], ad);                                          \
            }                                                                 \
            _Pragma("unroll")                                                 \
            for (int a2 = 0; a2 < 2; a2++) {                                  \
                uint32_t bd = sb + QS_BH +                                    \
                              ((wn + a2 * 16 + brow) * HS + kc + bcol) * 2;   \
                LDSM_X4(bh[a2], bd);                                          \
                LDSM_X4(bl[a2], bd + (QS_BL - QS_BH));                        \
            }                                                                 \
            _Pragma("unroll")                                                 \
            for (int mt = 0; mt < 2; mt++)                                    \
                _Pragma("unroll")                                             \
                for (int nt = 0; nt < 4; nt++) {                              \
                    const int hi2 = nt >> 1, p = (nt & 1) * 2;                \
                    MMA_F16B(acc[mt][nt], ah[mt], bh[hi2][p], bh[hi2][p+1]);  \
                    MMA_F16B(acc[mt][nt], ah[mt], bl[hi2][p], bl[hi2][p+1]);  \
                }                                                             \
        }                                                                     \
        __syncthreads();                                                      \
    }                                                                         \
    _Pragma("unroll")                                                         \
    for (int mt = 0; mt < 2; mt++) {                                          \
        const int row = bm + wm + mt * 16 + g;                                \
        _Pragma("unroll")                                                     \
        for (int nt = 0; nt < 4; nt++) {                                      \
            const int col = bnL + wn + nt * 8 + tg * 2;                       \
            const float b0 = (biasptr)[col], b1 = (biasptr)[col + 1];         \
            float2 v0 = make_float2(acc[mt][nt][0] + b0, acc[mt][nt][1] + b1);\
            float2 v1 = make_float2(acc[mt][nt][2] + b0, acc[mt][nt][3] + b1);\
            *(float2*)((Yptr) + (size_t)row * D_MODEL + col) = v0;            \
            *(float2*)((Yptr) + (size_t)(row + 8) * D_MODEL + col) = v1;      \
        }                                                                     \
    }

#define QLOAD(t) do {                                                         \
        const uint32_t _sb = sbase + ((t) % 3) * QSTG;                        \
        const int _kb = (t) << 5;                                             \
        const size_t _ga0 = (size_t)(bm + r4) * K + _kb + c4 * 8;             \
        const size_t _ga1 = (size_t)(bm + 64 + r4) * K + _kb + c4 * 8;        \
        const size_t _gb0 = (size_t)(bnG + r4) * K + _kb + c4 * 8;            \
        CP_ASYNC16(_sb + QS_AH + so,        Ahg + _ga0);                      \
        CP_ASYNC16(_sb + QS_AH + so + 5120, Ahg + _ga1);                      \
        CP_ASYNC16(_sb + QS_BH + so,        Bhg + _gb0);                      \
        CP_ASYNC16(_sb + QS_BL + so,        Blg + _gb0);                      \
        asm volatile("cp.async.commit_group;");                               \
    } while (0)

__global__ __launch_bounds__(256, 3) void gemm_qkv2(
    const __half* __restrict__ Ahg,
    const __half* __restrict__ Bhg, const __half* __restrict__ Blg,
    const float* __restrict__ bk, const float* __restrict__ bq,
    const float* __restrict__ bv,
    float* __restrict__ Yk, float* __restrict__ Yq, float* __restrict__ Yv,
    int M, int K)
{
    const int bnG = blockIdx.x * 64;
    const int seg = bnG >> 10;
    const int bnL = bnG & 1023;
    const float* bias = (seg == 0) ? bk : (seg == 1) ? bq : bv;
    float* Y = (seg == 0) ? Yk : (seg == 1) ? Yq : Yv;
    GEMM2_BODY(Y, bias)
}

__global__ __launch_bounds__(256, 3) void gemm_h2b(
    const __half* __restrict__ Ahg,
    const __half* __restrict__ Bhg, const __half* __restrict__ Blg,
    const float* __restrict__ bias, float* __restrict__ Y,
    int M, int K)
{
    const int bnG = blockIdx.x * 64;
    const int bnL = bnG;
    GEMM2_BODY(Y, bias)
}
#undef QLOAD

/* -------- prep8: 512 threads, 2 channels/thread, 8 tokens/CTA --------------- */
__global__ __launch_bounds__(512, 2) void prep8(
    const float* __restrict__ x,
    const float* __restrict__ Wbeta, const float* __restrict__ bbeta,
    const float* __restrict__ ck, const float* __restrict__ cq,
    const float* __restrict__ cv)
{
    __shared__ float xs[8 * D_MODEL];
    __shared__ float eta_s[8][N_HEADS];

    const int bid = blockIdx.x;
    const int b = bid >> 8;
    const int l0 = (bid & 255) * 8;
    const int tid = threadIdx.x;
    const int d = tid * 2;
    const int h = tid >> 5;
    const int lane = tid & 31;
    const int w = tid >> 5;

#pragma unroll
    for (int i = 0; i < 4; i++) {
        int idx = i * 512 + tid;
        int t = idx >> 8, c = idx & 255;
        ((float4*)xs)[t * 256 + c] =
            *(const float4*)(x + ((size_t)(b * L_DIM + l0 + t)) * D_MODEL + c * 4);
    }
    __syncthreads();

    {
        const int t = w >> 1;
        const int hb0 = (w & 1) * 8;
        const float* xr = xs + t * D_MODEL;
#pragma unroll
        for (int hh = 0; hh < 8; hh++) {
            int hb = hb0 + hh;
            float s = 0.f;
            const float* wb = Wbeta + hb * D_MODEL;
            for (int k = lane * 4; k < D_MODEL; k += 128) {
                float4 xv = *(const float4*)(xr + k);
                float4 wv = *(const float4*)(wb + k);
                s += xv.x * wv.x + xv.y * wv.y + xv.z * wv.z + xv.w * wv.w;
            }
#pragma unroll
            for (int o = 16; o > 0; o >>= 1) s += __shfl_down_sync(0xffffffffu, s, o);
            if (lane == 0) eta_s[t][hb] = 1.f / (1.f + __expf(-(s + bbeta[hb])));
        }
    }

    float4 cwk[2], cwq[2], cwv[2];
#pragma unroll
    for (int c = 0; c < 2; c++) {
        cwk[c] = ((const float4*)ck)[d + c];
        cwq[c] = ((const float4*)cq)[d + c];
        cwv[c] = ((const float4*)cv)[d + c];
    }

    float2 wk[4], wq[4], wv[4];
#pragma unroll
    for (int j = 0; j < 3; j++) {
        int ls = l0 - 3 + j;
        if (ls >= 0) {
            size_t base = ((size_t)(b * L_DIM + ls)) * D_MODEL + d;
            wk[j] = *(const float2*)&g_kpre[base];
            wq[j] = *(const float2*)&g_qpre[base];
            wv[j] = *(const float2*)&g_vpre[base];
        } else {
            wk[j] = wq[j] = wv[j] = make_float2(0.f, 0.f);
        }
    }
    __syncthreads();

#pragma unroll
    for (int t = 0; t < 8; t++) {
        {
            size_t base = ((size_t)(b * L_DIM + l0 + t)) * D_MODEL + d;
            wk[(t + 3) & 3] = *(const float2*)&g_kpre[base];
            wq[(t + 3) & 3] = *(const float2*)&g_qpre[base];
            wv[(t + 3) & 3] = *(const float2*)&g_vpre[base];
        }
        float ak0 = 0.f, ak1 = 0.f, aq0 = 0.f, aq1 = 0.f, av0 = 0.f, av1 = 0.f;
#pragma unroll
        for (int j = 0; j < 4; j++) {
            const int sl = (t + j) & 3;
            float wk0 = ((const float*)&cwk[0])[j], wk1 = ((const float*)&cwk[1])[j];
            float wq0 = ((const float*)&cwq[0])[j], wq1 = ((const float*)&cwq[1])[j];
            float wv0 = ((const float*)&cwv[0])[j], wv1 = ((const float*)&cwv[1])[j];
            ak0 += wk[sl].x * wk0; ak1 += wk[sl].y * wk1;
            aq0 += wq[sl].x * wq0; aq1 += wq[sl].y * wq1;
            av0 += wv[sl].x * wv0; av1 += wv[sl].y * wv1;
        }
        float sk = ak0 * ak0 + ak1 * ak1;
        float sq = aq0 * aq0 + aq1 * aq1;
#pragma unroll
        for (int o = 16; o > 0; o >>= 1) {
            sk += __shfl_xor_sync(0xffffffffu, sk, o);
            sq += __shfl_xor_sync(0xffffffffu, sq, o);
        }
        const float rkn = 1.f / (sqrtf(sk) + 1e-6f);
        const float rqn = 1.f / (sqrtf(sq) + 1e-6f);
        const float e = eta_s[t][h];

        float kn0 = ak0 * rkn, kn1 = ak1 * rkn;
        float qn0 = aq0 * rqn, qn1 = aq1 * rqn;
        float sv0 = av0 / (1.f + __expf(-av0));
        float sv1 = av1 / (1.f + __expf(-av1));
        size_t obase = (((size_t)(b * N_HEADS + h)) * L_DIM + l0 + t) * D_HEAD + (d & 63);
        *(float2*)&g_kn[obase] = make_float2(kn0, kn1);
        *(float2*)&g_qn[obase] = make_float2(qn0, qn1);
        *(float2*)&g_vs[obase] = make_float2(e * sv0, e * sv1);
        *(float2*)&g_bb[obase] = make_float2(e * kn0, e * kn1);
    }
}

/* ---------------- chunked o2b weighted delta-rule scan ----------------------
   column-split (2 CTAs/pair); ALL matmuls (T/QK, B, D, F, H) on HMMA with
   fp16 3-pass splits; fp32 kept for solve + W state. ------------------------ */
#define SPLIT_ST(ah_, al_, idx_, val_) do {                                   \
        __half _hh = __float2half_rn(val_);                                   \
        (ah_)[idx_] = _hh;                                                    \
        (al_)[idx_] = __float2half_rn((val_) - __half2float(_hh));            \
    } while (0)

#define DSM_BYTES ((2 * 64 * FS + 3 * 64 * HSX + 512 + 256) * 4 +             \
                   (10 * F16T + 8 * F16H) * 2)

__global__ __launch_bounds__(256) void delta_kernel()
{
    extern __shared__ float smd[];
    float* Ts   = smd;                    /* 64 x 65 */
    float* Qk   = Ts + 64 * FS;
    float* Wt   = Qk + 64 * FS;           /* 64 x 33 */
    float* Wa   = Wt + 64 * HSX;
    float* Us   = Wa + 64 * HSX;
    float* invD = Us + 64 * HSX;          /* 512 */
    float* Mb   = invD + 512;             /* 256 */
    __half* Kh   = (__half*)(Mb + 256);
    __half* Kl   = Kh  + F16T;
    __half* Qh   = Kl  + F16T;
    __half* Ql   = Qh  + F16T;
    __half* Bh2  = Ql  + F16T;
    __half* Bl2  = Bh2 + F16T;
    __half* KTh  = Bl2 + F16T;
    __half* KTl  = KTh + F16T;
    __half* Sh   = KTl + F16T;
    __half* Sl   = Sh  + F16T;
    __half* WtTh = Sl  + F16T;            /* 32 x 72 each below */
    __half* WtTl = WtTh + F16H;
    __half* WaTh = WtTl + F16H;
    __half* WaTl = WaTh + F16H;
    __half* UTh  = WaTl + F16H;
    __half* UTl  = UTh + F16H;
    __half* UwTh = UTl + F16H;
    __half* UwTl = UwTh + F16H;

    const int tid = threadIdx.x;
    const int lane = tid & 31, w = tid >> 5;
    const int g = lane >> 2, tg = lane & 3;
    const int arow = (lane & 7) + ((lane >> 3) & 1) * 8;
    const int acol = (lane >> 4) * 8;
    const int brow = ((lane >> 4) & 1) * 8 + (lane & 7);
    const int bcol = ((lane >> 3) & 1) * 8;

    const int pair = blockIdx.x >> 1;
    const int half = blockIdx.x & 1;
    const int col0 = half * 32;
    const int b = pair >> 4, h = pair & 15;

    for (int i = tid; i < 64 * HSX; i += 256) { Wt[i] = 0.f; Wa[i] = 0.f; }

    const size_t pbase = (size_t)pair * L_DIM * D_HEAD;
    const uint32_t khB = smem_u32(Kh), klB = smem_u32(Kl);

    for (int chunk = 0; chunk < N_CHUNK; chunk++) {
        __syncthreads();
        const size_t cb = pbase + (size_t)chunk * 64 * D_HEAD;
        for (int i2 = tid; i2 < 4096; i2 += 256) {
            int r = i2 >> 6, c = i2 & 63;
            float kv = g_kn[cb + i2];
            float qv = g_qn[cb + i2];
            float bv = g_bb[cb + i2];
            SPLIT_ST(Kh, Kl, r * HX + c, kv);
            SPLIT_ST(KTh, KTl, c * HX + r, kv);
            SPLIT_ST(Qh, Ql, r * HX + c, qv);
            SPLIT_ST(Bh2, Bl2, r * HX + c, bv);
        }
        for (int i2 = tid; i2 < 2048; i2 += 256) {
            int r = i2 >> 5, c = i2 & 31;
            Us[r * HSX + c] = g_vs[cb + r * 64 + col0 + c];
        }
        for (int i2 = tid; i2 < 2048; i2 += 256) {
            int m = i2 >> 5, n = i2 & 31;
            SPLIT_ST(WtTh, WtTl, n * HX + m, Wt[m * HSX + n]);
            SPLIT_ST(WaTh, WaTl, n * HX + m, Wa[m * HSX + n]);
        }
        __syncthreads();

        const float ts    = (float)(chunk * 64);
        const float tri0  = 0.5f * (1.f + ts) * ts;
        const float denw  = 0.5f * (65.f + ts) * (64.f + ts);
        const float Ssum  = 64.f * ts + 2080.f;
        const float coef1 = (ts / (ts + 64.f)) * ((1.f + ts) / (ts + 65.f));
        const float coef2 = (64.f / (ts + 64.f)) * ((2.f * ts + 65.f) / (ts + 65.f));

        /* PASS 1a: [B;Q] @ K^T -> T (warps 0-3, tril) / QK (warps 4-7) */
        {
            const uint32_t ahB = smem_u32((w < 4) ? Bh2 : Qh);
            const uint32_t alB = smem_u32((w < 4) ? Bl2 : Ql);
            const int r0 = (w & 3) * 16;
            float acc[8][4];
#pragma unroll
            for (int j = 0; j < 8; j++)
#pragma unroll
                for (int e = 0; e < 4; e++) acc[j][e] = 0.f;

#pragma unroll
            for (int ks = 0; ks < 4; ks++) {
                const int kc = ks * 16;
                uint32_t ah[4], al[4], bh[4][4], bl[4][4];
                const uint32_t aoff = ((r0 + arow) * HX + kc + acol) * 2;
                LDSM_X4(ah, ahB + aoff);
                LDSM_X4(al, alB + aoff);
#pragma unroll
                for (int nt = 0; nt < 4; nt++) {
                    const uint32_t boff = ((nt * 16 + brow) * HX + kc + bcol) * 2;
                    LDSM_X4(bh[nt], khB + boff);
                    LDSM_X4(bl[nt], klB + boff);
                }
#pragma unroll
                for (int j = 0; j < 8; j++) {
                    const int grp = j >> 1, p = (j & 1) * 2;
                    MMA_F16B(acc[j], ah, bh[grp][p], bh[grp][p + 1]);
                    MMA_F16B(acc[j], ah, bl[grp][p], bl[grp][p + 1]);
                    MMA_F16B(acc[j], al, bh[grp][p], bh[grp][p + 1]);
                }
            }
            if (w < 4) {
#pragma unroll
                for (int j = 0; j < 8; j++) {
                    const int C = j * 8 + tg * 2;
                    const int R1 = r0 + g, R2 = r0 + g + 8;
                    Ts[R1 * FS + C]     = (R1 > C)     ? acc[j][0] : 0.f;
                    Ts[R1 * FS + C + 1] = (R1 > C + 1) ? acc[j][1] : 0.f;
                    Ts[R2 * FS + C]     = (R2 > C)     ? acc[j][2] : 0.f;
                    Ts[R2 * FS + C + 1] = (R2 > C + 1) ? acc[j][3] : 0.f;
                }
            } else {
#pragma unroll
                for (int j = 0; j < 8; j++) {
                    const int C = j * 8 + tg * 2;
                    const int R1 = r0 + g, R2 = r0 + g + 8;
                    Qk[R1 * FS + C]     = acc[j][0];
                    Qk[R1 * FS + C + 1] = acc[j][1];
                    Qk[R2 * FS + C]     = acc[j][2];
                    Qk[R2 * FS + C + 1] = acc[j][3];
                }
            }
        }

        /* PASS 1b: RHS = V - B @ Wt  (each warp: 16-row x 16-col patch) */
        {
            const uint32_t b2h = smem_u32(Bh2), b2l = smem_u32(Bl2);
            const uint32_t wth = smem_u32(WtTh), wtl = smem_u32(WtTl);
            const int bm0 = (w & 3) * 16;
            const int bn0 = (w >> 2) * 16;
            float accB[2][4];
#pragma unroll
            for (int nt = 0; nt < 2; nt++)
#pragma unroll
                for (int e = 0; e < 4; e++) accB[nt][e] = 0.f;
#pragma unroll
            for (int ks = 0; ks < 4; ks++) {
                const int kc = ks * 16;
                uint32_t ah[4], al[4], bh[4], bl[4];
                const uint32_t aoff = ((bm0 + arow) * HX + kc + acol) * 2;
                LDSM_X4(ah, b2h + aoff);
                LDSM_X4(al, b2l + aoff);
                const uint32_t boff = ((bn0 + brow) * HX + kc + bcol) * 2;
                LDSM_X4(bh, wth + boff);
                LDSM_X4(bl, wtl + boff);
#pragma unroll
                for (int nt = 0; nt < 2; nt++) {
                    const int p = nt * 2;
                    MMA_F16B(accB[nt], ah, bh[p], bh[p + 1]);
                    MMA_F16B(accB[nt], ah, bl[p], bl[p + 1]);
                    MMA_F16B(accB[nt], al, bh[p], bh[p + 1]);
                }
            }
#pragma unroll
            for (int nt = 0; nt < 2; nt++) {
                const int col = bn0 + nt * 8 + tg * 2;
                const int R1 = bm0 + g, R2 = bm0 + g + 8;
                Us[R1 * HSX + col]     -= accB[nt][0];
                Us[R1 * HSX + col + 1] -= accB[nt][1];
                Us[R2 * HSX + col]     -= accB[nt][2];
                Us[R2 * HSX + col + 1] -= accB[nt][3];
            }
        }
        __syncthreads();

        /* C0: invert the 8 unit-lower 8x8 diagonal blocks */
        if (tid < 64) {
            const int blk = tid >> 3, c = tid & 7;
            const int r0 = blk * 8;
            float xcol[8];
#pragma unroll
            for (int r = 0; r < 8; r++) {
                float s = (r == c) ? 1.f : 0.f;
                for (int k2 = c; k2 < r; k2++)
                    s -= Ts[(r0 + r) * FS + r0 + k2] * xcol[k2];
                xcol[r] = s;
            }
#pragma unroll
            for (int r = 0; r < 8; r++) invD[(r0 + r) * 8 + c] = xcol[r];
        }
        __syncthreads();

        /* C: blocked forward substitution (I+T) U = RHS */
        {
            const int cc = tid & 31, rr = tid >> 5;
            for (int ib = 0; ib < 8; ib++) {
                const int r0 = ib * 8;
                float s = 0.f;
                for (int j = 0; j < r0; j++)
                    s += Ts[(r0 + rr) * FS + j] * Us[j * HSX + cc];
                float rhs = Us[(r0 + rr) * HSX + cc] - s;
                Mb[rr * 32 + cc] = rhs;
                __syncthreads();
                s = rhs;
                for (int k2 = 0; k2 < rr; k2++)
                    s += invD[(r0 + rr) * 8 + k2] * Mb[k2 * 32 + cc];
                Us[(r0 + rr) * HSX + cc] = s;
                __syncthreads();
            }
        }

        /* conversions: S = weights o QK; U^T and (U*w)^T in fp16 hi/lo */
        for (int i2 = tid; i2 < 4096; i2 += 256) {
            int r = i2 >> 6, c = i2 & 63;
            float rr2 = (float)r;
            float cs_r = (rr2 + 1.f) * ts + 0.5f * (rr2 + 1.f) * (rr2 + 2.f);
            float rdiv = 1.f / (tri0 + cs_r);
            float kf = (float)c;
            float csk_m = kf * ts + 0.5f * kf * (kf + 1.f);
            float num = cs_r - csk_m;
            float sfac = (num >= 0.f) ? num * rdiv : 0.f;
            float sv = sfac * Qk[r * FS + c];
            SPLIT_ST(Sh, Sl, r * HX + c, sv);
        }
        for (int i2 = tid; i2 < 2048; i2 += 256) {
            int c = i2 >> 6, r = i2 & 63;       /* c: 0..31 col, r: token */
            float u = Us[r * HSX + c];
            float rr2 = (float)r;
            float idxr = ts + rr2 + 1.f;
            float csrr = (rr2 + 1.f) * ts + 0.5f * (rr2 + 1.f) * (rr2 + 2.f);
            float wr = (idxr + Ssum - csrr) / denw;
            SPLIT_ST(UTh, UTl, c * HX + r, u);
            SPLIT_ST(UwTh, UwTl, c * HX + r, u * wr);
        }
        __syncthreads();

        /* PASS 2: warps 0-3 -> O (D + F); warps 4-7 -> H (W updates) */
        if (w < 4) {
            const int r0 = w * 16;
            const uint32_t qhB = smem_u32(Qh), qlB = smem_u32(Ql);
            const uint32_t shB = smem_u32(Sh), slB = smem_u32(Sl);
            const uint32_t wah = smem_u32(WaTh), wal = smem_u32(WaTl);
            const uint32_t wth = smem_u32(WtTh), wtl = smem_u32(WtTl);
            const uint32_t uth = smem_u32(UTh), utl = smem_u32(UTl);
            float aA[4][4], aT[4][4], aF[4][4];
#pragma unroll
            for (int nt = 0; nt < 4; nt++)
#pragma unroll
                for (int e = 0; e < 4; e++) { aA[nt][e] = 0.f; aT[nt][e] = 0.f; aF[nt][e] = 0.f; }

#pragma unroll
            for (int ks = 0; ks < 4; ks++) {
                const int kc = ks * 16;
                const uint32_t aoff = ((r0 + arow) * HX + kc + acol) * 2;
                uint32_t qh[4], ql[4], sh[4], sl[4];
                LDSM_X4(qh, qhB + aoff);
                LDSM_X4(ql, qlB + aoff);
                LDSM_X4(sh, shB + aoff);
                LDSM_X4(sl, slB + aoff);
                uint32_t bwa[2][4], bwa2[2][4], bwt[2][4], bwt2[2][4], bu[2][4], bu2[2][4];
#pragma unroll
                for (int a2 = 0; a2 < 2; a2++) {
                    const uint32_t boff = ((a2 * 16 + brow) * HX + kc + bcol) * 2;
                    LDSM_X4(bwa[a2], wah + boff);
                    LDSM_X4(bwa2[a2], wal + boff);
                    LDSM_X4(bwt[a2], wth + boff);
                    LDSM_X4(bwt2[a2], wtl + boff);
                    LDSM_X4(bu[a2], uth + boff);
                    LDSM_X4(bu2[a2], utl + boff);
                }
#pragma unroll
                for (int nt = 0; nt < 4; nt++) {
                    const int grp = nt >> 1, p = (nt & 1) * 2;
                    MMA_F16B(aA[nt], qh, bwa[grp][p], bwa[grp][p + 1]);
                    MMA_F16B(aA[nt], qh, bwa2[grp][p], bwa2[grp][p + 1]);
                    MMA_F16B(aA[nt], ql, bwa[grp][p], bwa[grp][p + 1]);
                    MMA_F16B(aT[nt], qh, bwt[grp][p], bwt[grp][p + 1]);
                    MMA_F16B(aT[nt], qh, bwt2[grp][p], bwt2[grp][p + 1]);
                    MMA_F16B(aT[nt], ql, bwt[grp][p], bwt[grp][p + 1]);
                    MMA_F16B(aF[nt], sh, bu[grp][p], bu[grp][p + 1]);
                    MMA_F16B(aF[nt], sh, bu2[grp][p], bu2[grp][p + 1]);
                    MMA_F16B(aF[nt], sl, bu[grp][p], bu[grp][p + 1]);
                }
            }
            const int r1 = r0 + g, r2 = r1 + 8;
            float f1 = (float)r1, f2 = (float)r2;
            float cs1 = (f1 + 1.f) * ts + 0.5f * (f1 + 1.f) * (f1 + 2.f);
            float cs2 = (f2 + 1.f) * ts + 0.5f * (f2 + 1.f) * (f2 + 2.f);
            float ar1 = tri0 / (tri0 + cs1);
            float ar2 = tri0 / (tri0 + cs2);
#pragma unroll
            for (int nt = 0; nt < 4; nt++) {
                const int cg = h * 64 + col0 + nt * 8 + tg * 2;
                int l1 = chunk * 64 + r1, l2 = chunk * 64 + r2;
                float2 v1 = make_float2(
                    ar1 * aA[nt][0] + (1.f - ar1) * aT[nt][0] + aF[nt][0],
                    ar1 * aA[nt][1] + (1.f - ar1) * aT[nt][1] + aF[nt][1]);
                float2 v2 = make_float2(
                    ar2 * aA[nt][2] + (1.f - ar2) * aT[nt][2] + aF[nt][2],
                    ar2 * aA[nt][3] + (1.f - ar2) * aT[nt][3] + aF[nt][3]);
                *(float2*)&g_o[((size_t)(b * L_DIM + l1)) * D_MODEL + cg] = v1;
                *(float2*)&g_o[((size_t)(b * L_DIM + l2)) * D_MODEL + cg] = v2;
            }
        } else {
            const int m0 = (w - 4) * 16;
            const uint32_t kth = smem_u32(KTh), ktl = smem_u32(KTl);
            const uint32_t uth = smem_u32(UTh), utl = smem_u32(UTl);
            const uint32_t uwh = smem_u32(UwTh), uwl = smem_u32(UwTl);
            float p1a[4][4], p2a[4][4];
#pragma unroll
            for (int nt = 0; nt < 4; nt++)
#pragma unroll
                for (int e = 0; e < 4; e++) { p1a[nt][e] = 0.f; p2a[nt][e] = 0.f; }

#pragma unroll
            for (int ks = 0; ks < 4; ks++) {
                const int kc = ks * 16;
                const uint32_t aoff = ((m0 + arow) * HX + kc + acol) * 2;
                uint32_t kh2[4], kl2[4];
                LDSM_X4(kh2, kth + aoff);
                LDSM_X4(kl2, ktl + aoff);
                uint32_t bu[2][4], bu2[2][4], bw[2][4], bw2[2][4];
#pragma unroll
                for (int a2 = 0; a2 < 2; a2++) {
                    const uint32_t boff = ((a2 * 16 + brow) * HX + kc + bcol) * 2;
                    LDSM_X4(bu[a2], uth + boff);
                    LDSM_X4(bu2[a2], utl + boff);
                    LDSM_X4(bw[a2], uwh + boff);
                    LDSM_X4(bw2[a2], uwl + boff);
                }
#pragma unroll
                for (int nt = 0; nt < 4; nt++) {
                    const int grp = nt >> 1, p = (nt & 1) * 2;
                    MMA_F16B(p1a[nt], kh2, bu[grp][p], bu[grp][p + 1]);
                    MMA_F16B(p1a[nt], kh2, bu2[grp][p], bu2[grp][p + 1]);
                    MMA_F16B(p1a[nt], kl2, bu[grp][p], bu[grp][p + 1]);
                    MMA_F16B(p2a[nt], kh2, bw[grp][p], bw[grp][p + 1]);
                    MMA_F16B(p2a[nt], kh2, bw2[grp][p], bw2[grp][p + 1]);
                    MMA_F16B(p2a[nt], kl2, bw[grp][p], bw[grp][p + 1]);
                }
            }
            const int m1 = m0 + g, m2 = m1 + 8;
#pragma unroll
            for (int nt = 0; nt < 4; nt++) {
                const int n = nt * 8 + tg * 2;
#pragma unroll
                for (int cc2 = 0; cc2 < 2; cc2++) {
                    int i1 = m1 * HSX + n + cc2;
                    float wo = Wt[i1];
                    Wa[i1] = coef1 * Wa[i1] + coef2 * wo + p2a[nt][cc2];
                    Wt[i1] = wo + p1a[nt][cc2];
                    int i2x = m2 * HSX + n + cc2;
                    wo = Wt[i2x];
                    Wa[i2x] = coef1 * Wa[i2x] + coef2 * wo + p2a[nt][2 + cc2];
                    Wt[i2x] = wo + p1a[nt][2 + cc2];
                }
            }
        }
        /* loop-top sync orders H's W writes before next chunk's WtT rebuild */
    }
}

/* -------- RMS norm over head dim + fp16 (hi only) for final 2-pass GEMM ----- */
__global__ __launch_bounds__(256) void rms_split(const float* __restrict__ rms_w)
{
    const int bl = blockIdx.x, tid = threadIdx.x;
    float4 v = ((const float4*)g_o)[(size_t)bl * 256 + tid];
    float ss = v.x * v.x + v.y * v.y + v.z * v.z + v.w * v.w;
#pragma unroll
    for (int o = 8; o > 0; o >>= 1) ss += __shfl_xor_sync(0xffffffffu, ss, o);
    float scale = rsqrtf(ss * (1.f / 64.f) + 1e-6f);
    float4 rw = ((const float4*)rms_w)[tid & 15];
    float a0 = v.x * scale * rw.x, a1 = v.y * scale * rw.y;
    float a2 = v.z * scale * rw.z, a3 = v.w * scale * rw.w;
    __half2 h01 = __floats2half2_rn(a0, a1);
    __half2 h23 = __floats2half2_rn(a2, a3);
    ((uint2*)g_oh)[(size_t)bl * 256 + tid] = make_uint2(*(uint32_t*)&h01, *(uint32_t*)&h23);
}

/* ------------------------------- launcher ----------------------------------*/
extern "C" void kernel_launch(void* const* d_in, const int* in_sizes, int n_in,
                              void* d_out, int out_size)
{
    (void)in_sizes; (void)n_in; (void)out_size;
    const float* x     = (const float*)d_in[0];
    const float* Wk    = (const float*)d_in[1];
    const float* bk    = (const float*)d_in[2];
    const float* Wq    = (const float*)d_in[3];
    const float* bq    = (const float*)d_in[4];
    const float* Wv    = (const float*)d_in[5];
    const float* bv    = (const float*)d_in[6];
    const float* Wbeta = (const float*)d_in[7];
    const float* bbeta = (const float*)d_in[8];
    const float* ck    = (const float*)d_in[9];
    const float* cq    = (const float*)d_in[10];
    const float* cv    = (const float*)d_in[11];
    const float* rms_w = (const float*)d_in[12];
    const float* Wout  = (const float*)d_in[13];
    const float* bout  = (const float*)d_in[14];
    float* out = (float*)d_out;

    float *kpre, *qpre, *vpre;
    __half *xh, *oh, *wsh, *wsl;
    cudaGetSymbolAddress((void**)&kpre, g_kpre);
    cudaGetSymbolAddress((void**)&qpre, g_qpre);
    cudaGetSymbolAddress((void**)&vpre, g_vpre);
    cudaGetSymbolAddress((void**)&xh, g_xh);
    cudaGetSymbolAddress((void**)&oh, g_oh);
    cudaGetSymbolAddress((void**)&wsh, g_wsh);
    cudaGetSymbolAddress((void**)&wsl, g_wsl);

    split_hi<<<(ML * D_MODEL / 4 + 255) / 256, 256>>>(
        (const float4*)x, (uint2*)xh, ML * D_MODEL / 4);
    split_w4<<<(4 * DD / 4) / 256, 256>>>(
        (const float4*)Wk, (const float4*)Wq, (const float4*)Wv,
        (const float4*)Wout, (uint2*)wsh, (uint2*)wsl);

    cudaFuncSetAttribute(gemm_qkv2, cudaFuncAttributeMaxDynamicSharedMemorySize,
                         QSM_BYTES);
    cudaFuncSetAttribute(gemm_h2b, cudaFuncAttributeMaxDynamicSharedMemorySize,
                         QSM_BYTES);

    gemm_qkv2<<<dim3(48, 64), 256, QSM_BYTES>>>(
        xh, wsh, wsl, bk, bq, bv, kpre, qpre, vpre, ML, D_MODEL);

    prep8<<<B_DIM * (L_DIM / 8), 512>>>(x, Wbeta, bbeta, ck, cq, cv);

    cudaFuncSetAttribute(delta_kernel, cudaFuncAttributeMaxDynamicSharedMemorySize,
                         DSM_BYTES);
    delta_kernel<<<2 * N_PAIR, 256, DSM_BYTES>>>();

    rms_split<<<ML, 256>>>(rms_w);

    gemm_h2b<<<dim3(16, 64), 256, QSM_BYTES>>>(
        oh, wsh + 3 * DD, wsl + 3 * DD, bout, out, ML, D_MODEL);
}